// round 1
// baseline (speedup 1.0000x reference)
#include <cuda_runtime.h>
#include <math.h>

#define NTOK 16384
#define CDIM 192
#define BATCH 8
#define NHEADS 8
#define HD 24
#define SPLITK 8
#define KSLAB (NTOK / SPLITK)

// -------- scratch (device globals; no allocation allowed) --------
__device__ float g_C[BATCH][6][CDIM][CDIM];    // correlation matrices
__device__ float g_s[BATCH][4][CDIM];          // rowsums: q1, x2, q2, x1
__device__ float g_T[BATCH][6][CDIM][CDIM];    // W @ C products
__device__ float g_vec[BATCH][8][CDIM];        // wqs1,wks2,wqs2,wks1,nq1,nk2,nq2,nk1
__device__ float g_attn[BATCH][2][NHEADS][HD][HD];
__device__ float g_tvec[BATCH][2][CDIM];
__device__ float g_cvec[BATCH][2][CDIM];
__device__ float g_P[BATCH][2][CDIM][CDIM];
__device__ float g_M[BATCH][2][CDIM][CDIM];

// -------- zero the accumulated scratch --------
__global__ void zero_kernel() {
    size_t nC = sizeof(g_C) / 4;
    size_t nS = sizeof(g_s) / 4;
    float* c = &g_C[0][0][0][0];
    float* s = &g_s[0][0][0];
    for (size_t i = (size_t)blockIdx.x * blockDim.x + threadIdx.x; i < nC;
         i += (size_t)gridDim.x * blockDim.x)
        c[i] = 0.f;
    for (size_t i = (size_t)blockIdx.x * blockDim.x + threadIdx.x; i < nS;
         i += (size_t)gridDim.x * blockDim.x)
        s[i] = 0.f;
}

// -------- correlation GEMMs: C[g] = A @ B^T over N tokens (+ rowsums) --------
// grid: x = colTile(3), y = rowTile(3) * SPLITK, z = b*6+g ; 256 threads
__global__ void gram_kernel(const float* __restrict__ q1, const float* __restrict__ q2,
                            const float* __restrict__ x1, const float* __restrict__ x2) {
    int z = blockIdx.z;
    int b = z / 6, g = z % 6;
    int rowTile = blockIdx.y % 3;
    int sk = blockIdx.y / 3;
    int colTile = blockIdx.x;

    const float* Aten; const float* Bten; int slot;
    switch (g) {
        case 0: Aten = q1; Bten = q1; slot = 0; break;
        case 1: Aten = q1; Bten = x2; slot = -1; break;
        case 2: Aten = x2; Bten = x2; slot = 1; break;
        case 3: Aten = q2; Bten = q2; slot = 2; break;
        case 4: Aten = q2; Bten = x1; slot = -1; break;
        default: Aten = x1; Bten = x1; slot = 3; break;
    }
    const float* A = Aten + (size_t)b * CDIM * NTOK;
    const float* Bm = Bten + (size_t)b * CDIM * NTOK;

    int i0 = rowTile * 64, j0 = colTile * 64;
    int k0base = sk * KSLAB;

    __shared__ float As[16][64];
    __shared__ float Bs[16][64];

    int t = threadIdx.x;
    int tx = t % 16, ty = t / 16;
    int lrow = t >> 2, lq = t & 3;

    float acc[4][4];
#pragma unroll
    for (int i = 0; i < 4; i++)
#pragma unroll
        for (int j = 0; j < 4; j++) acc[i][j] = 0.f;
    float asum = 0.f;

    const float* Arow = A + (size_t)(i0 + lrow) * NTOK + k0base + lq * 4;
    const float* Brow = Bm + (size_t)(j0 + lrow) * NTOK + k0base + lq * 4;

    for (int kc = 0; kc < KSLAB; kc += 16) {
        float4 av = *(const float4*)(Arow + kc);
        float4 bv = *(const float4*)(Brow + kc);
        __syncthreads();
        As[lq * 4 + 0][lrow] = av.x; As[lq * 4 + 1][lrow] = av.y;
        As[lq * 4 + 2][lrow] = av.z; As[lq * 4 + 3][lrow] = av.w;
        Bs[lq * 4 + 0][lrow] = bv.x; Bs[lq * 4 + 1][lrow] = bv.y;
        Bs[lq * 4 + 2][lrow] = bv.z; Bs[lq * 4 + 3][lrow] = bv.w;
        asum += av.x + av.y + av.z + av.w;
        __syncthreads();
#pragma unroll
        for (int kk = 0; kk < 16; kk++) {
            float4 a4 = *(float4*)&As[kk][ty * 4];
            float4 b4 = *(float4*)&Bs[kk][tx * 4];
            float ar[4] = {a4.x, a4.y, a4.z, a4.w};
            float br[4] = {b4.x, b4.y, b4.z, b4.w};
#pragma unroll
            for (int i = 0; i < 4; i++)
#pragma unroll
                for (int j = 0; j < 4; j++) acc[i][j] = fmaf(ar[i], br[j], acc[i][j]);
        }
    }

    float* Cout = &g_C[b][g][0][0];
#pragma unroll
    for (int i = 0; i < 4; i++)
#pragma unroll
        for (int j = 0; j < 4; j++)
            atomicAdd(&Cout[(i0 + ty * 4 + i) * CDIM + (j0 + tx * 4 + j)], acc[i][j]);

    if (slot >= 0 && colTile == 0) atomicAdd(&g_s[b][slot][i0 + lrow], asum);
}

// -------- small NN GEMMs (192x192x192): D = W @ C --------
// mode 0: z=b*6+g, T[b][g] = W(g) @ g_C[b][g]   ; mode 1: z=b*2+p, M = Wproj @ P
__global__ void smallgemm_nn(const float* __restrict__ Wq, const float* __restrict__ Wk,
                             const float* __restrict__ Wproj, int mode) {
    int z = blockIdx.z;
    const float* W; const float* C; float* D;
    if (mode == 0) {
        int b = z / 6, g = z % 6;
        W = (g == 2 || g == 5) ? Wk : Wq;
        C = &g_C[b][g][0][0];
        D = &g_T[b][g][0][0];
    } else {
        int b = z / 2, p = z % 2;
        W = Wproj;
        C = &g_P[b][p][0][0];
        D = &g_M[b][p][0][0];
    }
    int m0 = blockIdx.y * 32, j0 = blockIdx.x * 32;
    __shared__ float Ws[32][33];
    __shared__ float Cs[32][33];
    int t = threadIdx.x, tx = t % 16, ty = t / 16;
    float acc[2][2] = {{0.f, 0.f}, {0.f, 0.f}};
    for (int k0 = 0; k0 < CDIM; k0 += 32) {
        __syncthreads();
        for (int e = t; e < 1024; e += 256) {
            int r = e / 32, cc = e % 32;
            Ws[r][cc] = W[(m0 + r) * CDIM + k0 + cc];
            Cs[r][cc] = C[(k0 + r) * CDIM + j0 + cc];
        }
        __syncthreads();
#pragma unroll
        for (int kk = 0; kk < 32; kk++) {
            float w0 = Ws[ty * 2 + 0][kk], w1 = Ws[ty * 2 + 1][kk];
            float c0 = Cs[kk][tx * 2 + 0], c1 = Cs[kk][tx * 2 + 1];
            acc[0][0] = fmaf(w0, c0, acc[0][0]);
            acc[0][1] = fmaf(w0, c1, acc[0][1]);
            acc[1][0] = fmaf(w1, c0, acc[1][0]);
            acc[1][1] = fmaf(w1, c1, acc[1][1]);
        }
    }
#pragma unroll
    for (int i = 0; i < 2; i++)
#pragma unroll
        for (int j = 0; j < 2; j++)
            D[(m0 + ty * 2 + i) * CDIM + (j0 + tx * 2 + j)] = acc[i][j];
}

// -------- per-batch vectors: W@rowsum products and channel norms --------
__global__ void vec_kernel(const float* __restrict__ Wq, const float* __restrict__ Wk,
                           const float* __restrict__ bq, const float* __restrict__ bk) {
    int b = blockIdx.x;
    int c = threadIdx.x;  // 192 threads
    __shared__ float ss[4][CDIM];
    for (int e = c; e < 4 * CDIM; e += CDIM) ss[e / CDIM][e % CDIM] = g_s[b][e / CDIM][e % CDIM];
    __syncthreads();
    float wqs1 = 0, wks2 = 0, wqs2 = 0, wks1 = 0;
    float d0 = 0, d2 = 0, d3 = 0, d5 = 0;
    for (int i = 0; i < CDIM; i++) {
        float wq = Wq[c * CDIM + i], wk = Wk[c * CDIM + i];
        wqs1 = fmaf(wq, ss[0][i], wqs1);
        wqs2 = fmaf(wq, ss[2][i], wqs2);
        wks2 = fmaf(wk, ss[1][i], wks2);
        wks1 = fmaf(wk, ss[3][i], wks1);
        d0 = fmaf(g_T[b][0][c][i], wq, d0);
        d2 = fmaf(g_T[b][2][c][i], wk, d2);
        d3 = fmaf(g_T[b][3][c][i], wq, d3);
        d5 = fmaf(g_T[b][5][c][i], wk, d5);
    }
    float bqc = bq[c], bkc = bk[c];
    const float NN = (float)NTOK;
    g_vec[b][0][c] = wqs1;
    g_vec[b][1][c] = wks2;
    g_vec[b][2][c] = wqs2;
    g_vec[b][3][c] = wks1;
    g_vec[b][4][c] = sqrtf(fmaxf(d0 + 2.f * bqc * wqs1 + NN * bqc * bqc, 0.f));
    g_vec[b][5][c] = sqrtf(fmaxf(d2 + 2.f * bkc * wks2 + NN * bkc * bkc, 0.f));
    g_vec[b][6][c] = sqrtf(fmaxf(d3 + 2.f * bqc * wqs2 + NN * bqc * bqc, 0.f));
    g_vec[b][7][c] = sqrtf(fmaxf(d5 + 2.f * bkc * wks1 + NN * bkc * bkc, 0.f));
}

// -------- logits + softmax per (batch, pair, head); also t = BD(attn)@bv --------
__global__ void attn_kernel(const float* __restrict__ Wk, const float* __restrict__ bq,
                            const float* __restrict__ bk, const float* __restrict__ scale,
                            const float* __restrict__ bv) {
    int h = blockIdx.x, pair = blockIdx.y, b = blockIdx.z;
    __shared__ float sTA[HD][CDIM];
    __shared__ float sWk[HD][CDIM];
    __shared__ float slog[HD][HD];
    const float* TA = pair ? &g_T[b][4][0][0] : &g_T[b][1][0][0];
    const float* wqs = pair ? g_vec[b][2] : g_vec[b][0];
    const float* wks = pair ? g_vec[b][3] : g_vec[b][1];
    const float* nq = pair ? g_vec[b][6] : g_vec[b][4];
    const float* nk = pair ? g_vec[b][7] : g_vec[b][5];
    int t = threadIdx.x;  // 256
    for (int e = t; e < HD * CDIM; e += 256) {
        int r = e / CDIM, cc = e % CDIM;
        sTA[r][cc] = TA[(h * HD + r) * CDIM + cc];
        sWk[r][cc] = Wk[(h * HD + r) * CDIM + cc];
    }
    __syncthreads();
    float sc = scale[h];
    const float NN = (float)NTOK;
    for (int e = t; e < HD * HD; e += 256) {
        int i = e / HD, j = e % HD;
        int c = h * HD + i, d = h * HD + j;
        float dot = 0.f;
        for (int k = 0; k < CDIM; k++) dot = fmaf(sTA[i][k], sWk[j][k], dot);
        float raw = dot + wqs[c] * bk[d] + bq[c] * wks[d] + NN * bq[c] * bk[d];
        slog[i][j] = raw / (fmaxf(nq[c], 1e-12f) * fmaxf(nk[d], 1e-12f)) * sc;
    }
    __syncthreads();
    if (t < HD) {
        int i = t;
        float m = -INFINITY;
        for (int j = 0; j < HD; j++) m = fmaxf(m, slog[i][j]);
        float ex[HD];
        float sum = 0.f;
        for (int j = 0; j < HD; j++) { ex[j] = __expf(slog[i][j] - m) ; sum += ex[j]; }
        // use precise expf to stay close to reference
        sum = 0.f;
        for (int j = 0; j < HD; j++) { ex[j] = expf(slog[i][j] - m); sum += ex[j]; }
        float inv = 1.f / sum;
        float tv = 0.f;
        for (int j = 0; j < HD; j++) {
            float a = ex[j] * inv;
            g_attn[b][pair][h][i][j] = a;
            tv = fmaf(a, bv[h * HD + j], tv);
        }
        g_tvec[b][pair][h * HD + i] = tv;
    }
}

// -------- cvec = Wproj @ tvec --------
__global__ void cvec_kernel(const float* __restrict__ Wproj) {
    int b = blockIdx.x, p = blockIdx.y, c = threadIdx.x;
    __shared__ float tv[CDIM];
    tv[c] = g_tvec[b][p][c];
    __syncthreads();
    float s = 0.f;
    for (int i = 0; i < CDIM; i++) s = fmaf(Wproj[c * CDIM + i], tv[i], s);
    g_cvec[b][p][c] = s;
}

// -------- P = BD(attn) @ Wv --------
__global__ void p_kernel(const float* __restrict__ Wv) {
    int vt = blockIdx.x, p = blockIdx.y, b = blockIdx.z;
    int v0 = vt * 32;
    __shared__ float sA[NHEADS][HD][HD];
    __shared__ float sWv[CDIM][32];
    int t = threadIdx.x;
    const float* attnflat = &g_attn[b][p][0][0][0];
    for (int e = t; e < NHEADS * HD * HD; e += 256) (&sA[0][0][0])[e] = attnflat[e];
    for (int e = t; e < CDIM * 32; e += 256) {
        int r = e / 32, vc = e % 32;
        sWv[r][vc] = Wv[r * CDIM + v0 + vc];
    }
    __syncthreads();
    for (int e = t; e < CDIM * 32; e += 256) {
        int c = e / 32, vc = e % 32;
        int h = c / HD, i = c % HD;
        float acc = 0.f;
#pragma unroll
        for (int j = 0; j < HD; j++) acc = fmaf(sA[h][i][j], sWv[h * HD + j][vc], acc);
        g_P[b][p][c][v0 + vc] = acc;
    }
}

// -------- final: out = M @ X + cvec --------
// grid: x = n-tiles(128), y = c-tiles(3), z = b*2+pair ; 256 threads
__global__ void out_kernel(const float* __restrict__ x1, const float* __restrict__ x2,
                           float* __restrict__ out) {
    int z = blockIdx.z;
    int b = z >> 1, p = z & 1;
    const float* X = (p ? x1 : x2) + (size_t)b * CDIM * NTOK;
    const float* M = &g_M[b][p][0][0];
    const float* cv = g_cvec[b][p];
    float* O = out + (size_t)p * BATCH * CDIM * NTOK + (size_t)b * CDIM * NTOK;
    int c0 = blockIdx.y * 64, n0 = blockIdx.x * 128;

    __shared__ float Ms[8][64];
    __shared__ float Xs[8][128];
    int t = threadIdx.x, tx = t % 16, ty = t / 16;
    float acc[4][8];
#pragma unroll
    for (int i = 0; i < 4; i++)
#pragma unroll
        for (int j = 0; j < 8; j++) acc[i][j] = 0.f;

    int lkk = t >> 5, lnc = (t & 31) * 4;
    for (int k0 = 0; k0 < CDIM; k0 += 8) {
        __syncthreads();
        for (int e = t; e < 512; e += 256) {
            int r = e >> 3, kk = e & 7;
            Ms[kk][r] = M[(c0 + r) * CDIM + k0 + kk];
        }
        float4 xv = *(const float4*)(X + (size_t)(k0 + lkk) * NTOK + n0 + lnc);
        *(float4*)&Xs[lkk][lnc] = xv;
        __syncthreads();
#pragma unroll
        for (int kk = 0; kk < 8; kk++) {
            float4 a4 = *(float4*)&Ms[kk][ty * 4];
            float ar[4] = {a4.x, a4.y, a4.z, a4.w};
            float4 b0 = *(float4*)&Xs[kk][tx * 8];
            float4 b1 = *(float4*)&Xs[kk][tx * 8 + 4];
            float br[8] = {b0.x, b0.y, b0.z, b0.w, b1.x, b1.y, b1.z, b1.w};
#pragma unroll
            for (int i = 0; i < 4; i++)
#pragma unroll
                for (int j = 0; j < 8; j++) acc[i][j] = fmaf(ar[i], br[j], acc[i][j]);
        }
    }
#pragma unroll
    for (int i = 0; i < 4; i++) {
        int c = c0 + ty * 4 + i;
        float bias = cv[c];
        float4 o0, o1;
        o0.x = acc[i][0] + bias; o0.y = acc[i][1] + bias;
        o0.z = acc[i][2] + bias; o0.w = acc[i][3] + bias;
        o1.x = acc[i][4] + bias; o1.y = acc[i][5] + bias;
        o1.z = acc[i][6] + bias; o1.w = acc[i][7] + bias;
        float* dst = O + (size_t)c * NTOK + n0 + tx * 8;
        *(float4*)dst = o0;
        *(float4*)(dst + 4) = o1;
    }
}

extern "C" void kernel_launch(void* const* d_in, const int* in_sizes, int n_in,
                              void* d_out, int out_size) {
    const float* x1 = (const float*)d_in[0];
    const float* x2 = (const float*)d_in[1];
    const float* q1 = (const float*)d_in[2];
    const float* q2 = (const float*)d_in[3];
    const float* Wq = (const float*)d_in[4];
    const float* bq = (const float*)d_in[5];
    const float* Wk = (const float*)d_in[6];
    const float* bk = (const float*)d_in[7];
    const float* Wv = (const float*)d_in[8];
    const float* bv = (const float*)d_in[9];
    const float* scale = (const float*)d_in[10];
    const float* Wproj = (const float*)d_in[11];
    float* out = (float*)d_out;

    zero_kernel<<<512, 256>>>();
    gram_kernel<<<dim3(3, 3 * SPLITK, BATCH * 6), 256>>>(q1, q2, x1, x2);
    smallgemm_nn<<<dim3(6, 6, BATCH * 6), 256>>>(Wq, Wk, Wproj, 0);
    vec_kernel<<<dim3(BATCH), CDIM>>>(Wq, Wk, bq, bk);
    attn_kernel<<<dim3(NHEADS, 2, BATCH), 256>>>(Wk, bq, bk, scale, bv);
    cvec_kernel<<<dim3(BATCH, 2), CDIM>>>(Wproj);
    p_kernel<<<dim3(6, 2, BATCH), 256>>>(Wv);
    smallgemm_nn<<<dim3(6, 6, BATCH * 2), 256>>>(Wq, Wk, Wproj, 1);
    out_kernel<<<dim3(NTOK / 128, 3, BATCH * 2), 256>>>(x1, x2, out);
}

// round 3
// speedup vs baseline: 1.7586x; 1.7586x over previous
#include <cuda_runtime.h>
#include <cuda_bf16.h>
#include <math.h>
#include <stdint.h>

#define NTOK 16384
#define CDIM 192
#define BATCH 8
#define NHEADS 8
#define HD 24

// gram config
#define GSPLITK 8
#define GSLAB (NTOK / GSPLITK)   // 2048
#define GCH 32                   // k elems per chunk
#define GNCH (GSLAB / GCH)       // 64
#define SROW 40                  // padded smem row stride (bf16 elems)
#define GRAM_SMEM (4 * CDIM * SROW * 2)

// out config
#define OXROW 136
#define OUT_SMEM (2 * CDIM * SROW * 2 + 2 * 32 * OXROW * 2 + CDIM * 4)

// -------- scratch --------
__device__ float g_C[BATCH][6][CDIM][CDIM];
__device__ float g_s[BATCH][4][CDIM];  // rowsums: q1, x2, q2, x1
__device__ float g_T[BATCH][6][CDIM][CDIM];
__device__ float g_vec[BATCH][8][CDIM];
__device__ float g_attn[BATCH][2][NHEADS][HD][HD];
__device__ float g_tvec[BATCH][2][CDIM];
__device__ float g_cvec[BATCH][2][CDIM];
__device__ float g_P[BATCH][2][CDIM][CDIM];
__device__ float g_M[BATCH][2][CDIM][CDIM];
__device__ __nv_bfloat16 g_Mh[BATCH * 2][CDIM * CDIM];
__device__ __nv_bfloat16 g_Ml[BATCH * 2][CDIM * CDIM];

// ================= mma helpers (sm_80-portable) =================
__device__ __forceinline__ uint32_t smem_u32(const void* p) {
    uint32_t a;
    asm("{ .reg .u64 t; cvta.to.shared.u64 t, %1; cvt.u32.u64 %0, t; }" : "=r"(a) : "l"(p));
    return a;
}
__device__ __forceinline__ void ldsm_x4(uint32_t* r, uint32_t addr) {
    asm volatile("ldmatrix.sync.aligned.m8n8.x4.shared.b16 {%0,%1,%2,%3}, [%4];"
                 : "=r"(r[0]), "=r"(r[1]), "=r"(r[2]), "=r"(r[3]) : "r"(addr));
}
__device__ __forceinline__ void ldsm_x4_t(uint32_t* r, uint32_t addr) {
    asm volatile("ldmatrix.sync.aligned.m8n8.x4.trans.shared.b16 {%0,%1,%2,%3}, [%4];"
                 : "=r"(r[0]), "=r"(r[1]), "=r"(r[2]), "=r"(r[3]) : "r"(addr));
}
__device__ __forceinline__ void mma16816(float* d, const uint32_t* a, const uint32_t* b) {
    asm volatile(
        "mma.sync.aligned.m16n8k16.row.col.f32.bf16.bf16.f32 "
        "{%0,%1,%2,%3}, {%4,%5,%6,%7}, {%8,%9}, {%0,%1,%2,%3};"
        : "+f"(d[0]), "+f"(d[1]), "+f"(d[2]), "+f"(d[3])
        : "r"(a[0]), "r"(a[1]), "r"(a[2]), "r"(a[3]), "r"(b[0]), "r"(b[1]));
}
__device__ __forceinline__ void cvt_hl(float v, __nv_bfloat16& h, __nv_bfloat16& l) {
    h = __float2bfloat16(v);
    l = __float2bfloat16(v - __bfloat162float(h));
}

// ================= kernels =================
__global__ void zero_kernel() {
    size_t n = sizeof(g_C) / 4;
    float* c = &g_C[0][0][0][0];
    for (size_t i = (size_t)blockIdx.x * blockDim.x + threadIdx.x; i < n;
         i += (size_t)gridDim.x * blockDim.x)
        c[i] = 0.f;
}

// per-channel rowsums; grid (CDIM, BATCH, 4)
__global__ void rowsum_kernel(const float* __restrict__ q1, const float* __restrict__ q2,
                              const float* __restrict__ x1, const float* __restrict__ x2) {
    int c = blockIdx.x, b = blockIdx.y, t = blockIdx.z;
    const float* src;
    switch (t) {
        case 0: src = q1; break;
        case 1: src = q2; break;
        case 2: src = x1; break;
        default: src = x2; break;
    }
    src += ((size_t)b * CDIM + c) * NTOK;
    float sum = 0.f;
    for (int i = threadIdx.x * 4; i < NTOK; i += blockDim.x * 4) {
        float4 v = *(const float4*)(src + i);
        sum += v.x + v.y + v.z + v.w;
    }
    __shared__ float red[256];
    red[threadIdx.x] = sum;
    __syncthreads();
    for (int s = 128; s > 0; s >>= 1) {
        if (threadIdx.x < s) red[threadIdx.x] += red[threadIdx.x + s];
        __syncthreads();
    }
    if (threadIdx.x == 0) {
        const int map[4] = {0, 2, 3, 1};
        g_s[b][map[t]][c] = red[0];
    }
}

// tensor-core gram: C[b][g] += A @ B^T over a split-K slab, bf16 hi/lo 3-term.
// grid (GSPLITK, BATCH*6), 384 threads (12 warps, 3x4; warp tile 64x48)
__global__ __launch_bounds__(384, 1) void gram_mma(const float* __restrict__ q1,
                                                   const float* __restrict__ q2,
                                                   const float* __restrict__ x1,
                                                   const float* __restrict__ x2) {
    extern __shared__ __align__(128) __nv_bfloat16 sm[];
    __nv_bfloat16* sAh = sm;
    __nv_bfloat16* sAl = sm + CDIM * SROW;
    __nv_bfloat16* sBh = sm + 2 * CDIM * SROW;
    __nv_bfloat16* sBl = sm + 3 * CDIM * SROW;

    int sk = blockIdx.x, bg = blockIdx.y;
    int b = bg / 6, g = bg % 6;
    const int AI[6] = {0, 0, 3, 1, 1, 2};
    const int BI[6] = {0, 3, 3, 1, 2, 2};
    const float* ten[4] = {q1, q2, x1, x2};
    int ai = AI[g], bi = BI[g];
    const float* A = ten[ai] + (size_t)b * CDIM * NTOK;
    const float* Bm = ten[bi] + (size_t)b * CDIM * NTOK;
    bool diag = (ai == bi);

    int tid = threadIdx.x, lane = tid & 31, wid = tid >> 5;
    int wm = wid >> 2, wn = wid & 3;  // 3 x 4

    uint32_t sAh_a = smem_u32(sAh);
    uint32_t sBh_a = diag ? sAh_a : smem_u32(sBh);
    const uint32_t LOFF = CDIM * SROW * 2;  // hi -> lo byte offset (same for A and B)

    float acc[4][6][4];
#pragma unroll
    for (int i = 0; i < 4; i++)
#pragma unroll
        for (int j = 0; j < 6; j++)
#pragma unroll
            for (int k = 0; k < 4; k++) acc[i][j][k] = 0.f;

    int kslab0 = sk * GSLAB;
    for (int ch = 0; ch < GNCH; ch++) {
        int kb = kslab0 + ch * GCH;
        __syncthreads();
#pragma unroll
        for (int it = 0; it < 4; it++) {
            int u = tid + it * 384;  // 1536 total
            int row = u >> 3, c4 = (u & 7) * 4;
            float4 v = *(const float4*)(A + (size_t)row * NTOK + kb + c4);
            __nv_bfloat16 h0, l0, h1, l1, h2, l2, h3, l3;
            cvt_hl(v.x, h0, l0); cvt_hl(v.y, h1, l1);
            cvt_hl(v.z, h2, l2); cvt_hl(v.w, h3, l3);
            __nv_bfloat16* dh = sAh + row * SROW + c4;
            __nv_bfloat16* dl = sAl + row * SROW + c4;
            dh[0] = h0; dh[1] = h1; dh[2] = h2; dh[3] = h3;
            dl[0] = l0; dl[1] = l1; dl[2] = l2; dl[3] = l3;
        }
        if (!diag) {
#pragma unroll
            for (int it = 0; it < 4; it++) {
                int u = tid + it * 384;
                int row = u >> 3, c4 = (u & 7) * 4;
                float4 v = *(const float4*)(Bm + (size_t)row * NTOK + kb + c4);
                __nv_bfloat16 h0, l0, h1, l1, h2, l2, h3, l3;
                cvt_hl(v.x, h0, l0); cvt_hl(v.y, h1, l1);
                cvt_hl(v.z, h2, l2); cvt_hl(v.w, h3, l3);
                __nv_bfloat16* dh = sBh + row * SROW + c4;
                __nv_bfloat16* dl = sBl + row * SROW + c4;
                dh[0] = h0; dh[1] = h1; dh[2] = h2; dh[3] = h3;
                dl[0] = l0; dl[1] = l1; dl[2] = l2; dl[3] = l3;
            }
        }
        __syncthreads();

#pragma unroll
        for (int s = 0; s < 2; s++) {
            int ks = s * 16;
            uint32_t ah[16], al[16], bb[12];
            int arow0 = wm * 64 + (lane & 15);
            int acol = ks + ((lane >> 4) << 3);
#pragma unroll
            for (int i = 0; i < 4; i++) {
                uint32_t ad = sAh_a + (uint32_t)(((arow0 + i * 16) * SROW + acol) * 2);
                ldsm_x4(ah + 4 * i, ad);
                ldsm_x4(al + 4 * i, ad + LOFF);
            }
            int brow0 = wn * 48 + (lane & 7) + (((lane >> 4) & 1) << 3);
            int bcol = ks + (((lane >> 3) & 1) << 3);
#pragma unroll
            for (int j = 0; j < 3; j++)
                ldsm_x4(bb + 4 * j, sBh_a + (uint32_t)(((brow0 + j * 16) * SROW + bcol) * 2));
#pragma unroll
            for (int i = 0; i < 4; i++)
#pragma unroll
                for (int jj = 0; jj < 6; jj++) {
                    const uint32_t* bp = bb + (jj >> 1) * 4 + (jj & 1) * 2;
                    mma16816(acc[i][jj], ah + 4 * i, bp);
                    mma16816(acc[i][jj], al + 4 * i, bp);
                }
#pragma unroll
            for (int j = 0; j < 3; j++)
                ldsm_x4(bb + 4 * j,
                        sBh_a + LOFF + (uint32_t)(((brow0 + j * 16) * SROW + bcol) * 2));
#pragma unroll
            for (int i = 0; i < 4; i++)
#pragma unroll
                for (int jj = 0; jj < 6; jj++)
                    mma16816(acc[i][jj], ah + 4 * i, bb + (jj >> 1) * 4 + (jj & 1) * 2);
        }
    }

    float* C = &g_C[b][g][0][0];
    int r0 = wm * 64 + (lane >> 2);
    int cb = wn * 48 + (lane & 3) * 2;
#pragma unroll
    for (int i = 0; i < 4; i++)
#pragma unroll
        for (int jj = 0; jj < 6; jj++) {
            int rr = r0 + i * 16, cc = cb + jj * 8;
            atomicAdd(C + rr * CDIM + cc, acc[i][jj][0]);
            atomicAdd(C + rr * CDIM + cc + 1, acc[i][jj][1]);
            atomicAdd(C + (rr + 8) * CDIM + cc, acc[i][jj][2]);
            atomicAdd(C + (rr + 8) * CDIM + cc + 1, acc[i][jj][3]);
        }
}

// -------- small NN GEMMs (192x192x192): D = W @ C --------
__global__ void smallgemm_nn(const float* __restrict__ Wq, const float* __restrict__ Wk,
                             const float* __restrict__ Wproj, int mode) {
    int z = blockIdx.z;
    const float* W; const float* C; float* D;
    if (mode == 0) {
        int b = z / 6, g = z % 6;
        W = (g == 2 || g == 5) ? Wk : Wq;
        C = &g_C[b][g][0][0];
        D = &g_T[b][g][0][0];
    } else {
        int b = z / 2, p = z % 2;
        W = Wproj;
        C = &g_P[b][p][0][0];
        D = &g_M[b][p][0][0];
    }
    int m0 = blockIdx.y * 32, j0 = blockIdx.x * 32;
    __shared__ float Ws[32][33];
    __shared__ float Cs[32][33];
    int t = threadIdx.x, tx = t % 16, ty = t / 16;
    float acc[2][2] = {{0.f, 0.f}, {0.f, 0.f}};
    for (int k0 = 0; k0 < CDIM; k0 += 32) {
        __syncthreads();
        for (int e = t; e < 1024; e += 256) {
            int r = e / 32, cc = e % 32;
            Ws[r][cc] = W[(m0 + r) * CDIM + k0 + cc];
            Cs[r][cc] = C[(k0 + r) * CDIM + j0 + cc];
        }
        __syncthreads();
#pragma unroll
        for (int kk = 0; kk < 32; kk++) {
            float w0 = Ws[ty * 2 + 0][kk], w1 = Ws[ty * 2 + 1][kk];
            float c0 = Cs[kk][tx * 2 + 0], c1 = Cs[kk][tx * 2 + 1];
            acc[0][0] = fmaf(w0, c0, acc[0][0]);
            acc[0][1] = fmaf(w0, c1, acc[0][1]);
            acc[1][0] = fmaf(w1, c0, acc[1][0]);
            acc[1][1] = fmaf(w1, c1, acc[1][1]);
        }
    }
#pragma unroll
    for (int i = 0; i < 2; i++)
#pragma unroll
        for (int j = 0; j < 2; j++)
            D[(m0 + ty * 2 + i) * CDIM + (j0 + tx * 2 + j)] = acc[i][j];
}

// -------- per-batch vectors (warp per (b,c)) --------
__global__ void vec_kernel(const float* __restrict__ Wq, const float* __restrict__ Wk,
                           const float* __restrict__ bq, const float* __restrict__ bk) {
    int c = blockIdx.x, b = blockIdx.y, l = threadIdx.x;
    float a0 = 0, a1 = 0, a2 = 0, a3 = 0, d0 = 0, d2 = 0, d3 = 0, d5 = 0;
    for (int i = l; i < CDIM; i += 32) {
        float wq = Wq[c * CDIM + i], wk = Wk[c * CDIM + i];
        a0 = fmaf(wq, g_s[b][0][i], a0);
        a1 = fmaf(wk, g_s[b][1][i], a1);
        a2 = fmaf(wq, g_s[b][2][i], a2);
        a3 = fmaf(wk, g_s[b][3][i], a3);
        d0 = fmaf(g_T[b][0][c][i], wq, d0);
        d2 = fmaf(g_T[b][2][c][i], wk, d2);
        d3 = fmaf(g_T[b][3][c][i], wq, d3);
        d5 = fmaf(g_T[b][5][c][i], wk, d5);
    }
#pragma unroll
    for (int s = 16; s > 0; s >>= 1) {
        a0 += __shfl_xor_sync(0xffffffff, a0, s);
        a1 += __shfl_xor_sync(0xffffffff, a1, s);
        a2 += __shfl_xor_sync(0xffffffff, a2, s);
        a3 += __shfl_xor_sync(0xffffffff, a3, s);
        d0 += __shfl_xor_sync(0xffffffff, d0, s);
        d2 += __shfl_xor_sync(0xffffffff, d2, s);
        d3 += __shfl_xor_sync(0xffffffff, d3, s);
        d5 += __shfl_xor_sync(0xffffffff, d5, s);
    }
    if (l == 0) {
        float bqc = bq[c], bkc = bk[c];
        const float NN = (float)NTOK;
        g_vec[b][0][c] = a0;
        g_vec[b][1][c] = a1;
        g_vec[b][2][c] = a2;
        g_vec[b][3][c] = a3;
        g_vec[b][4][c] = sqrtf(fmaxf(d0 + 2.f * bqc * a0 + NN * bqc * bqc, 0.f));
        g_vec[b][5][c] = sqrtf(fmaxf(d2 + 2.f * bkc * a1 + NN * bkc * bkc, 0.f));
        g_vec[b][6][c] = sqrtf(fmaxf(d3 + 2.f * bqc * a2 + NN * bqc * bqc, 0.f));
        g_vec[b][7][c] = sqrtf(fmaxf(d5 + 2.f * bkc * a3 + NN * bkc * bkc, 0.f));
    }
}

// -------- logits + softmax --------
__global__ void attn_kernel(const float* __restrict__ Wk, const float* __restrict__ bq,
                            const float* __restrict__ bk, const float* __restrict__ scale,
                            const float* __restrict__ bv) {
    int h = blockIdx.x, pair = blockIdx.y, b = blockIdx.z;
    __shared__ float sTA[HD][CDIM];
    __shared__ float sWk[HD][CDIM];
    __shared__ float slog[HD][HD];
    const float* TA = pair ? &g_T[b][4][0][0] : &g_T[b][1][0][0];
    const float* wqs = pair ? g_vec[b][2] : g_vec[b][0];
    const float* wks = pair ? g_vec[b][3] : g_vec[b][1];
    const float* nq = pair ? g_vec[b][6] : g_vec[b][4];
    const float* nk = pair ? g_vec[b][7] : g_vec[b][5];
    int t = threadIdx.x;
    for (int e = t; e < HD * CDIM; e += 256) {
        int r = e / CDIM, cc = e % CDIM;
        sTA[r][cc] = TA[(h * HD + r) * CDIM + cc];
        sWk[r][cc] = Wk[(h * HD + r) * CDIM + cc];
    }
    __syncthreads();
    float sc = scale[h];
    const float NN = (float)NTOK;
    for (int e = t; e < HD * HD; e += 256) {
        int i = e / HD, j = e % HD;
        int c = h * HD + i, d = h * HD + j;
        float dot = 0.f;
        for (int k = 0; k < CDIM; k++) dot = fmaf(sTA[i][k], sWk[j][k], dot);
        float raw = dot + wqs[c] * bk[d] + bq[c] * wks[d] + NN * bq[c] * bk[d];
        slog[i][j] = raw / (fmaxf(nq[c], 1e-12f) * fmaxf(nk[d], 1e-12f)) * sc;
    }
    __syncthreads();
    if (t < HD) {
        int i = t;
        float m = -INFINITY;
        for (int j = 0; j < HD; j++) m = fmaxf(m, slog[i][j]);
        float ex[HD];
        float sum = 0.f;
        for (int j = 0; j < HD; j++) { ex[j] = expf(slog[i][j] - m); sum += ex[j]; }
        float inv = 1.f / sum;
        float tv = 0.f;
        for (int j = 0; j < HD; j++) {
            float a = ex[j] * inv;
            g_attn[b][pair][h][i][j] = a;
            tv = fmaf(a, bv[h * HD + j], tv);
        }
        g_tvec[b][pair][h * HD + i] = tv;
    }
}

__global__ void cvec_kernel(const float* __restrict__ Wproj) {
    int b = blockIdx.x, p = blockIdx.y, c = threadIdx.x;
    __shared__ float tv[CDIM];
    tv[c] = g_tvec[b][p][c];
    __syncthreads();
    float s = 0.f;
    for (int i = 0; i < CDIM; i++) s = fmaf(Wproj[c * CDIM + i], tv[i], s);
    g_cvec[b][p][c] = s;
}

__global__ void p_kernel(const float* __restrict__ Wv) {
    int vt = blockIdx.x, p = blockIdx.y, b = blockIdx.z;
    int v0 = vt * 32;
    __shared__ float sA[NHEADS][HD][HD];
    __shared__ float sWv[CDIM][32];
    int t = threadIdx.x;
    const float* attnflat = &g_attn[b][p][0][0][0];
    for (int e = t; e < NHEADS * HD * HD; e += 256) (&sA[0][0][0])[e] = attnflat[e];
    for (int e = t; e < CDIM * 32; e += 256) {
        int r = e / 32, vc = e % 32;
        sWv[r][vc] = Wv[r * CDIM + v0 + vc];
    }
    __syncthreads();
    for (int e = t; e < CDIM * 32; e += 256) {
        int c = e / 32, vc = e % 32;
        int h = c / HD, i = c % HD;
        float acc = 0.f;
#pragma unroll
        for (int j = 0; j < HD; j++) acc = fmaf(sA[h][i][j], sWv[h * HD + j][vc], acc);
        g_P[b][p][c][v0 + vc] = acc;
    }
}

// M -> bf16 hi/lo ; grid (16), 256 threads
__global__ void mconv_kernel() {
    int z = blockIdx.x;
    const float* M = &g_M[z >> 1][z & 1][0][0];
    for (int u = threadIdx.x; u < CDIM * CDIM; u += 256) {
        __nv_bfloat16 h, l;
        cvt_hl(M[u], h, l);
        g_Mh[z][u] = h;
        g_Ml[z][u] = l;
    }
}

// out = M @ X + cvec ; grid (NTOK/128, 16), 384 threads (12 warps 3x4, warp 64x32)
__global__ __launch_bounds__(384, 1) void out_mma(const float* __restrict__ x1,
                                                  const float* __restrict__ x2,
                                                  float* __restrict__ out) {
    extern __shared__ __align__(128) char smo[];
    __nv_bfloat16* sMh = (__nv_bfloat16*)smo;
    __nv_bfloat16* sMl = sMh + CDIM * SROW;
    __nv_bfloat16* sXh = sMl + CDIM * SROW;
    __nv_bfloat16* sXl = sXh + 32 * OXROW;
    float* scv = (float*)(sXl + 32 * OXROW);

    int z = blockIdx.y;
    int b = z >> 1, p = z & 1;
    const float* X = (p ? x1 : x2) + (size_t)b * CDIM * NTOK;
    const __nv_bfloat16* Mh = g_Mh[z];
    const __nv_bfloat16* Ml = g_Ml[z];
    float* O = out + (size_t)p * BATCH * CDIM * NTOK + (size_t)b * CDIM * NTOK;
    int n0 = blockIdx.x * 128;

    int tid = threadIdx.x, lane = tid & 31, wid = tid >> 5;
    int wm = wid >> 2, wn = wid & 3;

    if (tid < CDIM) scv[tid] = g_cvec[b][p][tid];

    uint32_t sMh_a = smem_u32(sMh);
    uint32_t sXh_a = smem_u32(sXh);
    const uint32_t MLOFF = CDIM * SROW * 2;
    const uint32_t XLOFF = 32 * OXROW * 2;

    float acc[4][4][4];
#pragma unroll
    for (int i = 0; i < 4; i++)
#pragma unroll
        for (int j = 0; j < 4; j++)
#pragma unroll
            for (int k = 0; k < 4; k++) acc[i][j][k] = 0.f;

    for (int ch = 0; ch < 6; ch++) {
        int kb = ch * 32;
        __syncthreads();
#pragma unroll
        for (int it = 0; it < 2; it++) {
            int u = tid + it * 384;  // 768
            int row = u >> 2, c8 = (u & 3) * 8;
            *(uint4*)(sMh + row * SROW + c8) = *(const uint4*)(Mh + row * CDIM + kb + c8);
            *(uint4*)(sMl + row * SROW + c8) = *(const uint4*)(Ml + row * CDIM + kb + c8);
        }
        for (int u = tid; u < 1024; u += 384) {
            int r = u >> 5, c4 = (u & 31) * 4;
            float4 v = *(const float4*)(X + (size_t)(kb + r) * NTOK + n0 + c4);
            __nv_bfloat16 h0, l0, h1, l1, h2, l2, h3, l3;
            cvt_hl(v.x, h0, l0); cvt_hl(v.y, h1, l1);
            cvt_hl(v.z, h2, l2); cvt_hl(v.w, h3, l3);
            __nv_bfloat16* dh = sXh + r * OXROW + c4;
            __nv_bfloat16* dl = sXl + r * OXROW + c4;
            dh[0] = h0; dh[1] = h1; dh[2] = h2; dh[3] = h3;
            dl[0] = l0; dl[1] = l1; dl[2] = l2; dl[3] = l3;
        }
        __syncthreads();

#pragma unroll
        for (int s = 0; s < 2; s++) {
            int ks = s * 16;
            uint32_t ah[16], al[16], bx[8];
            int arow0 = wm * 64 + (lane & 15);
            int acol = ks + ((lane >> 4) << 3);
#pragma unroll
            for (int i = 0; i < 4; i++) {
                uint32_t ad = sMh_a + (uint32_t)(((arow0 + i * 16) * SROW + acol) * 2);
                ldsm_x4(ah + 4 * i, ad);
                ldsm_x4(al + 4 * i, ad + MLOFF);
            }
            int krow = ks + (lane & 7) + (((lane >> 3) & 1) << 3);
            int ncol0 = wn * 32 + ((lane >> 4) << 3);
#pragma unroll
            for (int jb = 0; jb < 2; jb++)
                ldsm_x4_t(bx + 4 * jb, sXh_a + (uint32_t)((krow * OXROW + ncol0 + jb * 16) * 2));
#pragma unroll
            for (int i = 0; i < 4; i++)
#pragma unroll
                for (int jj = 0; jj < 4; jj++) {
                    const uint32_t* bp = bx + (jj >> 1) * 4 + (jj & 1) * 2;
                    mma16816(acc[i][jj], ah + 4 * i, bp);
                    mma16816(acc[i][jj], al + 4 * i, bp);
                }
#pragma unroll
            for (int jb = 0; jb < 2; jb++)
                ldsm_x4_t(bx + 4 * jb,
                          sXh_a + XLOFF + (uint32_t)((krow * OXROW + ncol0 + jb * 16) * 2));
#pragma unroll
            for (int i = 0; i < 4; i++)
#pragma unroll
                for (int jj = 0; jj < 4; jj++)
                    mma16816(acc[i][jj], ah + 4 * i, bx + (jj >> 1) * 4 + (jj & 1) * 2);
        }
    }

    int r0 = wm * 64 + (lane >> 2);
    int nb = n0 + wn * 32 + (lane & 3) * 2;
#pragma unroll
    for (int i = 0; i < 4; i++) {
        int c = r0 + i * 16;
        float b0 = scv[c], b1 = scv[c + 8];
#pragma unroll
        for (int jj = 0; jj < 4; jj++) {
            float2 v0 = {acc[i][jj][0] + b0, acc[i][jj][1] + b0};
            float2 v1 = {acc[i][jj][2] + b1, acc[i][jj][3] + b1};
            *(float2*)(O + (size_t)c * NTOK + nb + jj * 8) = v0;
            *(float2*)(O + (size_t)(c + 8) * NTOK + nb + jj * 8) = v1;
        }
    }
}

extern "C" void kernel_launch(void* const* d_in, const int* in_sizes, int n_in,
                              void* d_out, int out_size) {
    const float* x1 = (const float*)d_in[0];
    const float* x2 = (const float*)d_in[1];
    const float* q1 = (const float*)d_in[2];
    const float* q2 = (const float*)d_in[3];
    const float* Wq = (const float*)d_in[4];
    const float* bq = (const float*)d_in[5];
    const float* Wk = (const float*)d_in[6];
    const float* bk = (const float*)d_in[7];
    const float* Wv = (const float*)d_in[8];
    const float* bv = (const float*)d_in[9];
    const float* scale = (const float*)d_in[10];
    const float* Wproj = (const float*)d_in[11];
    float* out = (float*)d_out;

    static int configured = 0;
    if (!configured) {
        cudaFuncSetAttribute(gram_mma, cudaFuncAttributeMaxDynamicSharedMemorySize, GRAM_SMEM);
        cudaFuncSetAttribute(out_mma, cudaFuncAttributeMaxDynamicSharedMemorySize, OUT_SMEM);
        configured = 1;
    }

    zero_kernel<<<256, 256>>>();
    rowsum_kernel<<<dim3(CDIM, BATCH, 4), 256>>>(q1, q2, x1, x2);
    gram_mma<<<dim3(GSPLITK, BATCH * 6), 384, GRAM_SMEM>>>(q1, q2, x1, x2);
    smallgemm_nn<<<dim3(6, 6, BATCH * 6), 256>>>(Wq, Wk, Wproj, 0);
    vec_kernel<<<dim3(CDIM, BATCH), 32>>>(Wq, Wk, bq, bk);
    attn_kernel<<<dim3(NHEADS, 2, BATCH), 256>>>(Wk, bq, bk, scale, bv);
    cvec_kernel<<<dim3(BATCH, 2), CDIM>>>(Wproj);
    p_kernel<<<dim3(6, 2, BATCH), 256>>>(Wv);
    smallgemm_nn<<<dim3(6, 6, BATCH * 2), 256>>>(Wq, Wk, Wproj, 1);
    mconv_kernel<<<16, 256>>>();
    out_mma<<<dim3(NTOK / 128, BATCH * 2), 384, OUT_SMEM>>>(x1, x2, out);
}

// round 4
// speedup vs baseline: 2.5763x; 1.4650x over previous
#include <cuda_runtime.h>
#include <cuda_bf16.h>
#include <math.h>
#include <stdint.h>

#define NTOK 16384
#define CDIM 192
#define BATCH 8
#define NHEADS 8
#define HD 24

// gram config
#define GSPLITK 8
#define GSLAB (NTOK / GSPLITK)   // 2048
#define GCH 32                   // k elems per chunk
#define GNCH (GSLAB / GCH)       // 64
#define SROW 40                  // padded smem row stride (bf16 elems)
#define STAGE (CDIM * SROW)      // elems per array
#define GRAM_SMEM (2 * 4 * STAGE * 2)

// out config
#define MROW 200
#define OXROW 136
#define XSTAGE (32 * OXROW)
#define OUT_SMEM (2 * CDIM * MROW * 2 + 2 * 2 * XSTAGE * 2 + CDIM * 4)

// -------- scratch --------
__device__ float g_C[BATCH][6][CDIM][CDIM];
__device__ float g_s[BATCH][4][CDIM];  // rowsums: q1, x2, q2, x1
__device__ float g_T[BATCH][6][CDIM][CDIM];
__device__ float g_vec[BATCH][8][CDIM];
__device__ float g_attn[BATCH][2][NHEADS][HD][HD];
__device__ float g_tvec[BATCH][2][CDIM];
__device__ float g_cvec[BATCH][2][CDIM];
__device__ float g_P[BATCH][2][CDIM][CDIM];
__device__ float g_M[BATCH][2][CDIM][CDIM];
__device__ __nv_bfloat16 g_Mh[BATCH * 2][CDIM * CDIM];
__device__ __nv_bfloat16 g_Ml[BATCH * 2][CDIM * CDIM];

// ================= mma helpers (sm_80-portable) =================
__device__ __forceinline__ uint32_t smem_u32(const void* p) {
    uint32_t a;
    asm("{ .reg .u64 t; cvta.to.shared.u64 t, %1; cvt.u32.u64 %0, t; }" : "=r"(a) : "l"(p));
    return a;
}
__device__ __forceinline__ void ldsm_x4(uint32_t* r, uint32_t addr) {
    asm volatile("ldmatrix.sync.aligned.m8n8.x4.shared.b16 {%0,%1,%2,%3}, [%4];"
                 : "=r"(r[0]), "=r"(r[1]), "=r"(r[2]), "=r"(r[3]) : "r"(addr));
}
__device__ __forceinline__ void ldsm_x4_t(uint32_t* r, uint32_t addr) {
    asm volatile("ldmatrix.sync.aligned.m8n8.x4.trans.shared.b16 {%0,%1,%2,%3}, [%4];"
                 : "=r"(r[0]), "=r"(r[1]), "=r"(r[2]), "=r"(r[3]) : "r"(addr));
}
__device__ __forceinline__ void mma16816(float* d, const uint32_t* a, const uint32_t* b) {
    asm volatile(
        "mma.sync.aligned.m16n8k16.row.col.f32.bf16.bf16.f32 "
        "{%0,%1,%2,%3}, {%4,%5,%6,%7}, {%8,%9}, {%0,%1,%2,%3};"
        : "+f"(d[0]), "+f"(d[1]), "+f"(d[2]), "+f"(d[3])
        : "r"(a[0]), "r"(a[1]), "r"(a[2]), "r"(a[3]), "r"(b[0]), "r"(b[1]));
}
__device__ __forceinline__ void cvt_hl(float v, __nv_bfloat16& h, __nv_bfloat16& l) {
    h = __float2bfloat16(v);
    l = __float2bfloat16(v - __bfloat162float(h));
}
// packed: float4 -> 4 bf16 hi (8B STS) + 4 bf16 lo (8B STS)
__device__ __forceinline__ void cvt_store(float4 v, __nv_bfloat16* dh, __nv_bfloat16* dl) {
    __nv_bfloat162 h01 = __floats2bfloat162_rn(v.x, v.y);
    __nv_bfloat162 h23 = __floats2bfloat162_rn(v.z, v.w);
    float2 f01 = __bfloat1622float2(h01);
    float2 f23 = __bfloat1622float2(h23);
    __nv_bfloat162 l01 = __floats2bfloat162_rn(v.x - f01.x, v.y - f01.y);
    __nv_bfloat162 l23 = __floats2bfloat162_rn(v.z - f23.x, v.w - f23.y);
    uint2 uh, ul;
    uh.x = *(uint32_t*)&h01;
    uh.y = *(uint32_t*)&h23;
    ul.x = *(uint32_t*)&l01;
    ul.y = *(uint32_t*)&l23;
    *(uint2*)dh = uh;
    *(uint2*)dl = ul;
}

// ================= kernels =================
__global__ void zero_kernel() {
    size_t n = sizeof(g_C) / 4;
    float* c = &g_C[0][0][0][0];
    for (size_t i = (size_t)blockIdx.x * blockDim.x + threadIdx.x; i < n;
         i += (size_t)gridDim.x * blockDim.x)
        c[i] = 0.f;
}

// per-channel rowsums; grid (CDIM, BATCH, 4)
__global__ void rowsum_kernel(const float* __restrict__ q1, const float* __restrict__ q2,
                              const float* __restrict__ x1, const float* __restrict__ x2) {
    int c = blockIdx.x, b = blockIdx.y, t = blockIdx.z;
    const float* src;
    switch (t) {
        case 0: src = q1; break;
        case 1: src = q2; break;
        case 2: src = x1; break;
        default: src = x2; break;
    }
    src += ((size_t)b * CDIM + c) * NTOK;
    float sum = 0.f;
    for (int i = threadIdx.x * 4; i < NTOK; i += blockDim.x * 4) {
        float4 v = *(const float4*)(src + i);
        sum += v.x + v.y + v.z + v.w;
    }
    __shared__ float red[256];
    red[threadIdx.x] = sum;
    __syncthreads();
    for (int s = 128; s > 0; s >>= 1) {
        if (threadIdx.x < s) red[threadIdx.x] += red[threadIdx.x + s];
        __syncthreads();
    }
    if (threadIdx.x == 0) {
        const int map[4] = {0, 2, 3, 1};
        g_s[b][map[t]][c] = red[0];
    }
}

// tensor-core gram: C[b][g] += A @ B^T over a split-K slab, bf16 hi/lo 3-term.
// double-buffered; grid (GSPLITK, BATCH*6), 384 threads (12 warps 3x4, warp 64x48)
__global__ __launch_bounds__(384, 1) void gram_mma(const float* __restrict__ q1,
                                                   const float* __restrict__ q2,
                                                   const float* __restrict__ x1,
                                                   const float* __restrict__ x2) {
    extern __shared__ __align__(16) __nv_bfloat16 sm[];

    int sk = blockIdx.x, bg = blockIdx.y;
    int b = bg / 6, g = bg % 6;
    const int AI[6] = {0, 0, 3, 1, 1, 2};
    const int BI[6] = {0, 3, 3, 1, 2, 2};
    const float* ten[4] = {q1, q2, x1, x2};
    int ai = AI[g], bi = BI[g];
    const float* A = ten[ai] + (size_t)b * CDIM * NTOK;
    const float* Bm = ten[bi] + (size_t)b * CDIM * NTOK;
    bool diag = (ai == bi);

    int tid = threadIdx.x, lane = tid & 31, wid = tid >> 5;
    int wm = wid >> 2, wn = wid & 3;  // 3 x 4

    uint32_t smb = smem_u32(sm);
    const uint32_t LOFF = STAGE * 2;  // hi->lo byte offset

    float acc[4][6][4];
#pragma unroll
    for (int i = 0; i < 4; i++)
#pragma unroll
        for (int j = 0; j < 6; j++)
#pragma unroll
            for (int k = 0; k < 4; k++) acc[i][j][k] = 0.f;

    int kslab0 = sk * GSLAB;

    // prologue: chunk 0 -> stage 0
    {
        int kb = kslab0;
#pragma unroll
        for (int it = 0; it < 4; it++) {
            int u = tid + it * 384;
            int row = u >> 3, c4 = (u & 7) * 4;
            float4 v = *(const float4*)(A + (size_t)row * NTOK + kb + c4);
            cvt_store(v, sm + row * SROW + c4, sm + STAGE + row * SROW + c4);
            if (!diag) {
                float4 w = *(const float4*)(Bm + (size_t)row * NTOK + kb + c4);
                cvt_store(w, sm + 2 * STAGE + row * SROW + c4,
                          sm + 3 * STAGE + row * SROW + c4);
            }
        }
    }
    __syncthreads();

    float4 va[4], vb[4];
    for (int ch = 0; ch < GNCH; ch++) {
        int cur = ch & 1, nxt = cur ^ 1;
        bool pf = (ch + 1 < GNCH);
        if (pf) {
            int kb = kslab0 + (ch + 1) * GCH;
#pragma unroll
            for (int it = 0; it < 4; it++) {
                int u = tid + it * 384;
                va[it] = *(const float4*)(A + (size_t)(u >> 3) * NTOK + kb + (u & 7) * 4);
            }
            if (!diag) {
#pragma unroll
                for (int it = 0; it < 4; it++) {
                    int u = tid + it * 384;
                    vb[it] = *(const float4*)(Bm + (size_t)(u >> 3) * NTOK + kb + (u & 7) * 4);
                }
            }
        }

        // mma on stage cur
        uint32_t base = smb + cur * (4 * STAGE * 2);
        uint32_t aH = base;
        uint32_t bH = diag ? base : base + 2 * STAGE * 2;
#pragma unroll
        for (int s = 0; s < 2; s++) {
            int ks = s * 16;
            uint32_t ah[16], al[16], bb[12];
            int arow0 = wm * 64 + (lane & 15);
            int acol = ks + ((lane >> 4) << 3);
#pragma unroll
            for (int i = 0; i < 4; i++) {
                uint32_t ad = aH + (uint32_t)(((arow0 + i * 16) * SROW + acol) * 2);
                ldsm_x4(ah + 4 * i, ad);
                ldsm_x4(al + 4 * i, ad + LOFF);
            }
            int brow0 = wn * 48 + (lane & 7) + (((lane >> 4) & 1) << 3);
            int bcol = ks + (((lane >> 3) & 1) << 3);
#pragma unroll
            for (int j = 0; j < 3; j++)
                ldsm_x4(bb + 4 * j, bH + (uint32_t)(((brow0 + j * 16) * SROW + bcol) * 2));
#pragma unroll
            for (int i = 0; i < 4; i++)
#pragma unroll
                for (int jj = 0; jj < 6; jj++) {
                    const uint32_t* bp = bb + (jj >> 1) * 4 + (jj & 1) * 2;
                    mma16816(acc[i][jj], ah + 4 * i, bp);
                    mma16816(acc[i][jj], al + 4 * i, bp);
                }
#pragma unroll
            for (int j = 0; j < 3; j++)
                ldsm_x4(bb + 4 * j,
                        bH + LOFF + (uint32_t)(((brow0 + j * 16) * SROW + bcol) * 2));
#pragma unroll
            for (int i = 0; i < 4; i++)
#pragma unroll
                for (int jj = 0; jj < 6; jj++)
                    mma16816(acc[i][jj], ah + 4 * i, bb + (jj >> 1) * 4 + (jj & 1) * 2);
        }

        if (pf) {
            __nv_bfloat16* nb = sm + nxt * 4 * STAGE;
#pragma unroll
            for (int it = 0; it < 4; it++) {
                int u = tid + it * 384;
                int row = u >> 3, c4 = (u & 7) * 4;
                cvt_store(va[it], nb + row * SROW + c4, nb + STAGE + row * SROW + c4);
            }
            if (!diag) {
#pragma unroll
                for (int it = 0; it < 4; it++) {
                    int u = tid + it * 384;
                    int row = u >> 3, c4 = (u & 7) * 4;
                    cvt_store(vb[it], nb + 2 * STAGE + row * SROW + c4,
                              nb + 3 * STAGE + row * SROW + c4);
                }
            }
        }
        __syncthreads();
    }

    float* C = &g_C[b][g][0][0];
    int r0 = wm * 64 + (lane >> 2);
    int cb = wn * 48 + (lane & 3) * 2;
#pragma unroll
    for (int i = 0; i < 4; i++)
#pragma unroll
        for (int jj = 0; jj < 6; jj++) {
            int rr = r0 + i * 16, cc = cb + jj * 8;
            atomicAdd(C + rr * CDIM + cc, acc[i][jj][0]);
            atomicAdd(C + rr * CDIM + cc + 1, acc[i][jj][1]);
            atomicAdd(C + (rr + 8) * CDIM + cc, acc[i][jj][2]);
            atomicAdd(C + (rr + 8) * CDIM + cc + 1, acc[i][jj][3]);
        }
}

// -------- small NN GEMMs (192x192x192): D = W @ C --------
__global__ void smallgemm_nn(const float* __restrict__ Wq, const float* __restrict__ Wk,
                             const float* __restrict__ Wproj, int mode) {
    int z = blockIdx.z;
    const float* W; const float* C; float* D;
    if (mode == 0) {
        int b = z / 6, g = z % 6;
        W = (g == 2 || g == 5) ? Wk : Wq;
        C = &g_C[b][g][0][0];
        D = &g_T[b][g][0][0];
    } else {
        int b = z / 2, p = z % 2;
        W = Wproj;
        C = &g_P[b][p][0][0];
        D = &g_M[b][p][0][0];
    }
    int m0 = blockIdx.y * 32, j0 = blockIdx.x * 32;
    __shared__ float Ws[32][33];
    __shared__ float Cs[32][33];
    int t = threadIdx.x, tx = t % 16, ty = t / 16;
    float acc[2][2] = {{0.f, 0.f}, {0.f, 0.f}};
    for (int k0 = 0; k0 < CDIM; k0 += 32) {
        __syncthreads();
        for (int e = t; e < 1024; e += 256) {
            int r = e / 32, cc = e % 32;
            Ws[r][cc] = W[(m0 + r) * CDIM + k0 + cc];
            Cs[r][cc] = C[(k0 + r) * CDIM + j0 + cc];
        }
        __syncthreads();
#pragma unroll
        for (int kk = 0; kk < 32; kk++) {
            float w0 = Ws[ty * 2 + 0][kk], w1 = Ws[ty * 2 + 1][kk];
            float c0 = Cs[kk][tx * 2 + 0], c1 = Cs[kk][tx * 2 + 1];
            acc[0][0] = fmaf(w0, c0, acc[0][0]);
            acc[0][1] = fmaf(w0, c1, acc[0][1]);
            acc[1][0] = fmaf(w1, c0, acc[1][0]);
            acc[1][1] = fmaf(w1, c1, acc[1][1]);
        }
    }
#pragma unroll
    for (int i = 0; i < 2; i++)
#pragma unroll
        for (int j = 0; j < 2; j++)
            D[(m0 + ty * 2 + i) * CDIM + (j0 + tx * 2 + j)] = acc[i][j];
}

// -------- per-batch vectors (warp per (b,c)) --------
__global__ void vec_kernel(const float* __restrict__ Wq, const float* __restrict__ Wk,
                           const float* __restrict__ bq, const float* __restrict__ bk) {
    int c = blockIdx.x, b = blockIdx.y, l = threadIdx.x;
    float a0 = 0, a1 = 0, a2 = 0, a3 = 0, d0 = 0, d2 = 0, d3 = 0, d5 = 0;
    for (int i = l; i < CDIM; i += 32) {
        float wq = Wq[c * CDIM + i], wk = Wk[c * CDIM + i];
        a0 = fmaf(wq, g_s[b][0][i], a0);
        a1 = fmaf(wk, g_s[b][1][i], a1);
        a2 = fmaf(wq, g_s[b][2][i], a2);
        a3 = fmaf(wk, g_s[b][3][i], a3);
        d0 = fmaf(g_T[b][0][c][i], wq, d0);
        d2 = fmaf(g_T[b][2][c][i], wk, d2);
        d3 = fmaf(g_T[b][3][c][i], wq, d3);
        d5 = fmaf(g_T[b][5][c][i], wk, d5);
    }
#pragma unroll
    for (int s = 16; s > 0; s >>= 1) {
        a0 += __shfl_xor_sync(0xffffffff, a0, s);
        a1 += __shfl_xor_sync(0xffffffff, a1, s);
        a2 += __shfl_xor_sync(0xffffffff, a2, s);
        a3 += __shfl_xor_sync(0xffffffff, a3, s);
        d0 += __shfl_xor_sync(0xffffffff, d0, s);
        d2 += __shfl_xor_sync(0xffffffff, d2, s);
        d3 += __shfl_xor_sync(0xffffffff, d3, s);
        d5 += __shfl_xor_sync(0xffffffff, d5, s);
    }
    if (l == 0) {
        float bqc = bq[c], bkc = bk[c];
        const float NN = (float)NTOK;
        g_vec[b][0][c] = a0;
        g_vec[b][1][c] = a1;
        g_vec[b][2][c] = a2;
        g_vec[b][3][c] = a3;
        g_vec[b][4][c] = sqrtf(fmaxf(d0 + 2.f * bqc * a0 + NN * bqc * bqc, 0.f));
        g_vec[b][5][c] = sqrtf(fmaxf(d2 + 2.f * bkc * a1 + NN * bkc * bkc, 0.f));
        g_vec[b][6][c] = sqrtf(fmaxf(d3 + 2.f * bqc * a2 + NN * bqc * bqc, 0.f));
        g_vec[b][7][c] = sqrtf(fmaxf(d5 + 2.f * bkc * a3 + NN * bkc * bkc, 0.f));
    }
}

// -------- logits + softmax --------
__global__ void attn_kernel(const float* __restrict__ Wk, const float* __restrict__ bq,
                            const float* __restrict__ bk, const float* __restrict__ scale,
                            const float* __restrict__ bv) {
    int h = blockIdx.x, pair = blockIdx.y, b = blockIdx.z;
    __shared__ float sTA[HD][CDIM];
    __shared__ float sWk[HD][CDIM];
    __shared__ float slog[HD][HD];
    const float* TA = pair ? &g_T[b][4][0][0] : &g_T[b][1][0][0];
    const float* wqs = pair ? g_vec[b][2] : g_vec[b][0];
    const float* wks = pair ? g_vec[b][3] : g_vec[b][1];
    const float* nq = pair ? g_vec[b][6] : g_vec[b][4];
    const float* nk = pair ? g_vec[b][7] : g_vec[b][5];
    int t = threadIdx.x;
    for (int e = t; e < HD * CDIM; e += 256) {
        int r = e / CDIM, cc = e % CDIM;
        sTA[r][cc] = TA[(h * HD + r) * CDIM + cc];
        sWk[r][cc] = Wk[(h * HD + r) * CDIM + cc];
    }
    __syncthreads();
    float sc = scale[h];
    const float NN = (float)NTOK;
    for (int e = t; e < HD * HD; e += 256) {
        int i = e / HD, j = e % HD;
        int c = h * HD + i, d = h * HD + j;
        float dot = 0.f;
        for (int k = 0; k < CDIM; k++) dot = fmaf(sTA[i][k], sWk[j][k], dot);
        float raw = dot + wqs[c] * bk[d] + bq[c] * wks[d] + NN * bq[c] * bk[d];
        slog[i][j] = raw / (fmaxf(nq[c], 1e-12f) * fmaxf(nk[d], 1e-12f)) * sc;
    }
    __syncthreads();
    if (t < HD) {
        int i = t;
        float m = -INFINITY;
        for (int j = 0; j < HD; j++) m = fmaxf(m, slog[i][j]);
        float ex[HD];
        float sum = 0.f;
        for (int j = 0; j < HD; j++) { ex[j] = expf(slog[i][j] - m); sum += ex[j]; }
        float inv = 1.f / sum;
        float tv = 0.f;
        for (int j = 0; j < HD; j++) {
            float a = ex[j] * inv;
            g_attn[b][pair][h][i][j] = a;
            tv = fmaf(a, bv[h * HD + j], tv);
        }
        g_tvec[b][pair][h * HD + i] = tv;
    }
}

__global__ void cvec_kernel(const float* __restrict__ Wproj) {
    int b = blockIdx.x, p = blockIdx.y, c = threadIdx.x;
    __shared__ float tv[CDIM];
    tv[c] = g_tvec[b][p][c];
    __syncthreads();
    float s = 0.f;
    for (int i = 0; i < CDIM; i++) s = fmaf(Wproj[c * CDIM + i], tv[i], s);
    g_cvec[b][p][c] = s;
}

__global__ void p_kernel(const float* __restrict__ Wv) {
    int vt = blockIdx.x, p = blockIdx.y, b = blockIdx.z;
    int v0 = vt * 32;
    __shared__ float sA[NHEADS][HD][HD];
    __shared__ float sWv[CDIM][32];
    int t = threadIdx.x;
    const float* attnflat = &g_attn[b][p][0][0][0];
    for (int e = t; e < NHEADS * HD * HD; e += 256) (&sA[0][0][0])[e] = attnflat[e];
    for (int e = t; e < CDIM * 32; e += 256) {
        int r = e / 32, vc = e % 32;
        sWv[r][vc] = Wv[r * CDIM + v0 + vc];
    }
    __syncthreads();
    for (int e = t; e < CDIM * 32; e += 256) {
        int c = e / 32, vc = e % 32;
        int h = c / HD, i = c % HD;
        float acc = 0.f;
#pragma unroll
        for (int j = 0; j < HD; j++) acc = fmaf(sA[h][i][j], sWv[h * HD + j][vc], acc);
        g_P[b][p][c][v0 + vc] = acc;
    }
}

// M -> bf16 hi/lo ; grid (16), 256 threads
__global__ void mconv_kernel() {
    int z = blockIdx.x;
    const float* M = &g_M[z >> 1][z & 1][0][0];
    for (int u = threadIdx.x; u < CDIM * CDIM; u += 256) {
        __nv_bfloat16 h, l;
        cvt_hl(M[u], h, l);
        g_Mh[z][u] = h;
        g_Ml[z][u] = l;
    }
}

// out = M @ X + cvec ; M resident in smem, X double-buffered.
// grid (NTOK/128, 16), 384 threads (12 warps 3x4, warp 64x32)
__global__ __launch_bounds__(384, 1) void out_mma(const float* __restrict__ x1,
                                                  const float* __restrict__ x2,
                                                  float* __restrict__ out) {
    extern __shared__ __align__(16) __nv_bfloat16 smo[];
    __nv_bfloat16* sM = smo;                       // hi [CDIM*MROW], lo at +CDIM*MROW
    __nv_bfloat16* sX = smo + 2 * CDIM * MROW;     // stage s: hi at s*2*XSTAGE, lo +XSTAGE
    float* scv = (float*)(smo + 2 * CDIM * MROW + 4 * XSTAGE);

    int z = blockIdx.y;
    int b = z >> 1, p = z & 1;
    const float* X = (p ? x1 : x2) + (size_t)b * CDIM * NTOK;
    const __nv_bfloat16* Mh = g_Mh[z];
    const __nv_bfloat16* Ml = g_Ml[z];
    float* O = out + (size_t)p * BATCH * CDIM * NTOK + (size_t)b * CDIM * NTOK;
    int n0 = blockIdx.x * 128;

    int tid = threadIdx.x, lane = tid & 31, wid = tid >> 5;
    int wm = wid >> 2, wn = wid & 3;

    if (tid < CDIM) scv[tid] = g_cvec[b][p][tid];

    // resident M load (hi+lo), padded stride MROW
    for (int u = tid; u < CDIM * CDIM / 8; u += 384) {
        int row = u / 24, col = (u % 24) * 8;
        *(uint4*)(sM + row * MROW + col) = *(const uint4*)(Mh + row * CDIM + col);
        *(uint4*)(sM + CDIM * MROW + row * MROW + col) = *(const uint4*)(Ml + row * CDIM + col);
    }
    // X chunk 0 -> stage 0
    for (int u = tid; u < 1024; u += 384) {
        int r = u >> 5, c4 = (u & 31) * 4;
        float4 v = *(const float4*)(X + (size_t)r * NTOK + n0 + c4);
        cvt_store(v, sX + r * OXROW + c4, sX + XSTAGE + r * OXROW + c4);
    }
    __syncthreads();

    uint32_t sM_a = smem_u32(sM);
    uint32_t sX_a = smem_u32(sX);
    const uint32_t MLOFF = CDIM * MROW * 2;
    const uint32_t XLOFF = XSTAGE * 2;

    float acc[4][4][4];
#pragma unroll
    for (int i = 0; i < 4; i++)
#pragma unroll
        for (int j = 0; j < 4; j++)
#pragma unroll
            for (int k = 0; k < 4; k++) acc[i][j][k] = 0.f;

    float4 vx[3];
    for (int ch = 0; ch < 6; ch++) {
        int cur = ch & 1, nxt = cur ^ 1;
        bool pf = (ch < 5);
        if (pf) {
            int kb = (ch + 1) * 32;
#pragma unroll
            for (int it = 0; it < 3; it++) {
                int u = tid + it * 384;
                if (u < 1024) {
                    int r = u >> 5, c4 = (u & 31) * 4;
                    vx[it] = *(const float4*)(X + (size_t)(kb + r) * NTOK + n0 + c4);
                }
            }
        }

        uint32_t xb = sX_a + cur * (2 * XSTAGE * 2);
#pragma unroll
        for (int s = 0; s < 2; s++) {
            int kg = ch * 32 + s * 16;
            uint32_t ah[16], al[16], bx[8];
            int arow0 = wm * 64 + (lane & 15);
            int acol = kg + ((lane >> 4) << 3);
#pragma unroll
            for (int i = 0; i < 4; i++) {
                uint32_t ad = sM_a + (uint32_t)(((arow0 + i * 16) * MROW + acol) * 2);
                ldsm_x4(ah + 4 * i, ad);
                ldsm_x4(al + 4 * i, ad + MLOFF);
            }
            int krow = s * 16 + (lane & 7) + (((lane >> 3) & 1) << 3);
            int ncol0 = wn * 32 + ((lane >> 4) << 3);
#pragma unroll
            for (int jb = 0; jb < 2; jb++)
                ldsm_x4_t(bx + 4 * jb, xb + (uint32_t)((krow * OXROW + ncol0 + jb * 16) * 2));
#pragma unroll
            for (int i = 0; i < 4; i++)
#pragma unroll
                for (int jj = 0; jj < 4; jj++) {
                    const uint32_t* bp = bx + (jj >> 1) * 4 + (jj & 1) * 2;
                    mma16816(acc[i][jj], ah + 4 * i, bp);
                    mma16816(acc[i][jj], al + 4 * i, bp);
                }
#pragma unroll
            for (int jb = 0; jb < 2; jb++)
                ldsm_x4_t(bx + 4 * jb,
                          xb + XLOFF + (uint32_t)((krow * OXROW + ncol0 + jb * 16) * 2));
#pragma unroll
            for (int i = 0; i < 4; i++)
#pragma unroll
                for (int jj = 0; jj < 4; jj++)
                    mma16816(acc[i][jj], ah + 4 * i, bx + (jj >> 1) * 4 + (jj & 1) * 2);
        }

        if (pf) {
            __nv_bfloat16* nb = sX + nxt * 2 * XSTAGE;
#pragma unroll
            for (int it = 0; it < 3; it++) {
                int u = tid + it * 384;
                if (u < 1024) {
                    int r = u >> 5, c4 = (u & 31) * 4;
                    cvt_store(vx[it], nb + r * OXROW + c4, nb + XSTAGE + r * OXROW + c4);
                }
            }
        }
        __syncthreads();
    }

    int r0 = wm * 64 + (lane >> 2);
    int nb = n0 + wn * 32 + (lane & 3) * 2;
#pragma unroll
    for (int i = 0; i < 4; i++) {
        int c = r0 + i * 16;
        float b0 = scv[c], b1 = scv[c + 8];
#pragma unroll
        for (int jj = 0; jj < 4; jj++) {
            float2 v0 = {acc[i][jj][0] + b0, acc[i][jj][1] + b0};
            float2 v1 = {acc[i][jj][2] + b1, acc[i][jj][3] + b1};
            *(float2*)(O + (size_t)c * NTOK + nb + jj * 8) = v0;
            *(float2*)(O + (size_t)(c + 8) * NTOK + nb + jj * 8) = v1;
        }
    }
}

extern "C" void kernel_launch(void* const* d_in, const int* in_sizes, int n_in,
                              void* d_out, int out_size) {
    const float* x1 = (const float*)d_in[0];
    const float* x2 = (const float*)d_in[1];
    const float* q1 = (const float*)d_in[2];
    const float* q2 = (const float*)d_in[3];
    const float* Wq = (const float*)d_in[4];
    const float* bq = (const float*)d_in[5];
    const float* Wk = (const float*)d_in[6];
    const float* bk = (const float*)d_in[7];
    const float* Wv = (const float*)d_in[8];
    const float* bv = (const float*)d_in[9];
    const float* scale = (const float*)d_in[10];
    const float* Wproj = (const float*)d_in[11];
    float* out = (float*)d_out;

    static int configured = 0;
    if (!configured) {
        cudaFuncSetAttribute(gram_mma, cudaFuncAttributeMaxDynamicSharedMemorySize, GRAM_SMEM);
        cudaFuncSetAttribute(out_mma, cudaFuncAttributeMaxDynamicSharedMemorySize, OUT_SMEM);
        configured = 1;
    }

    zero_kernel<<<256, 256>>>();
    rowsum_kernel<<<dim3(CDIM, BATCH, 4), 256>>>(q1, q2, x1, x2);
    gram_mma<<<dim3(GSPLITK, BATCH * 6), 384, GRAM_SMEM>>>(q1, q2, x1, x2);
    smallgemm_nn<<<dim3(6, 6, BATCH * 6), 256>>>(Wq, Wk, Wproj, 0);
    vec_kernel<<<dim3(CDIM, BATCH), 32>>>(Wq, Wk, bq, bk);
    attn_kernel<<<dim3(NHEADS, 2, BATCH), 256>>>(Wk, bq, bk, scale, bv);
    cvec_kernel<<<dim3(BATCH, 2), CDIM>>>(Wproj);
    p_kernel<<<dim3(6, 2, BATCH), 256>>>(Wv);
    smallgemm_nn<<<dim3(6, 6, BATCH * 2), 256>>>(Wq, Wk, Wproj, 1);
    mconv_kernel<<<16, 256>>>();
    out_mma<<<dim3(NTOK / 128, BATCH * 2), 384, OUT_SMEM>>>(x1, x2, out);
}

// round 5
// speedup vs baseline: 2.7511x; 1.0678x over previous
#include <cuda_runtime.h>
#include <cuda_bf16.h>
#include <math.h>
#include <stdint.h>

#define NTOK 16384
#define CDIM 192
#define BATCH 8
#define NHEADS 8
#define HD 24

// gram config
#define GSPLITK 8
#define GSLAB (NTOK / GSPLITK)   // 2048
#define GCH 32                   // k elems per chunk
#define GNCH (GSLAB / GCH)       // 64
#define SROW 40                  // padded smem row stride (bf16 elems)
#define STAGE (CDIM * SROW)      // elems per array
#define GRAM_SMEM (2 * 4 * STAGE * 2)

// out config
#define MROW 200
#define OXROW 136
#define XSTAGE (32 * OXROW)
#define OUT_SMEM (2 * CDIM * MROW * 2 + 2 * 2 * XSTAGE * 2 + CDIM * 4)

// -------- scratch --------
__device__ float g_C[BATCH][6][CDIM][CDIM];
__device__ float g_s[BATCH][4][CDIM];  // rowsums: q1, x2, q2, x1
__device__ float g_T[BATCH][6][CDIM][CDIM];
__device__ float g_vec[BATCH][8][CDIM];
__device__ float g_attn[BATCH][2][NHEADS][HD][HD];
__device__ float g_tvec[BATCH][2][CDIM];
__device__ float g_cvec[BATCH][2][CDIM];
__device__ float g_P[BATCH][2][CDIM][CDIM];
__device__ __nv_bfloat16 g_Mh[BATCH * 2][CDIM * CDIM];
__device__ __nv_bfloat16 g_Ml[BATCH * 2][CDIM * CDIM];

// ================= mma helpers (sm_80-portable) =================
__device__ __forceinline__ uint32_t smem_u32(const void* p) {
    uint32_t a;
    asm("{ .reg .u64 t; cvta.to.shared.u64 t, %1; cvt.u32.u64 %0, t; }" : "=r"(a) : "l"(p));
    return a;
}
__device__ __forceinline__ void ldsm_x4(uint32_t* r, uint32_t addr) {
    asm volatile("ldmatrix.sync.aligned.m8n8.x4.shared.b16 {%0,%1,%2,%3}, [%4];"
                 : "=r"(r[0]), "=r"(r[1]), "=r"(r[2]), "=r"(r[3]) : "r"(addr));
}
__device__ __forceinline__ void ldsm_x4_t(uint32_t* r, uint32_t addr) {
    asm volatile("ldmatrix.sync.aligned.m8n8.x4.trans.shared.b16 {%0,%1,%2,%3}, [%4];"
                 : "=r"(r[0]), "=r"(r[1]), "=r"(r[2]), "=r"(r[3]) : "r"(addr));
}
__device__ __forceinline__ void mma16816(float* d, const uint32_t* a, const uint32_t* b) {
    asm volatile(
        "mma.sync.aligned.m16n8k16.row.col.f32.bf16.bf16.f32 "
        "{%0,%1,%2,%3}, {%4,%5,%6,%7}, {%8,%9}, {%0,%1,%2,%3};"
        : "+f"(d[0]), "+f"(d[1]), "+f"(d[2]), "+f"(d[3])
        : "r"(a[0]), "r"(a[1]), "r"(a[2]), "r"(a[3]), "r"(b[0]), "r"(b[1]));
}
__device__ __forceinline__ void cvt_hl(float v, __nv_bfloat16& h, __nv_bfloat16& l) {
    h = __float2bfloat16(v);
    l = __float2bfloat16(v - __bfloat162float(h));
}
// packed: float4 -> 4 bf16 hi (8B STS) + 4 bf16 lo (8B STS)
__device__ __forceinline__ void cvt_store(float4 v, __nv_bfloat16* dh, __nv_bfloat16* dl) {
    __nv_bfloat162 h01 = __floats2bfloat162_rn(v.x, v.y);
    __nv_bfloat162 h23 = __floats2bfloat162_rn(v.z, v.w);
    float2 f01 = __bfloat1622float2(h01);
    float2 f23 = __bfloat1622float2(h23);
    __nv_bfloat162 l01 = __floats2bfloat162_rn(v.x - f01.x, v.y - f01.y);
    __nv_bfloat162 l23 = __floats2bfloat162_rn(v.z - f23.x, v.w - f23.y);
    uint2 uh, ul;
    uh.x = *(uint32_t*)&h01;
    uh.y = *(uint32_t*)&h23;
    ul.x = *(uint32_t*)&l01;
    ul.y = *(uint32_t*)&l23;
    *(uint2*)dh = uh;
    *(uint2*)dl = ul;
}

// ================= kernels =================
__global__ void zero_kernel() {
    size_t n = sizeof(g_C) / 4;
    float* c = &g_C[0][0][0][0];
    for (size_t i = (size_t)blockIdx.x * blockDim.x + threadIdx.x; i < n;
         i += (size_t)gridDim.x * blockDim.x)
        c[i] = 0.f;
    size_t ns = sizeof(g_s) / 4;
    float* s = &g_s[0][0][0];
    for (size_t i = (size_t)blockIdx.x * blockDim.x + threadIdx.x; i < ns;
         i += (size_t)gridDim.x * blockDim.x)
        s[i] = 0.f;
}

// tensor-core gram: C[b][g] += A @ B^T over a split-K slab, bf16 hi/lo 3-term.
// Diagonal grams also accumulate per-row sums into g_s (fused rowsum).
// double-buffered; grid (GSPLITK, BATCH*6), 384 threads (12 warps 3x4, warp 64x48)
__global__ __launch_bounds__(384, 1) void gram_mma(const float* __restrict__ q1,
                                                   const float* __restrict__ q2,
                                                   const float* __restrict__ x1,
                                                   const float* __restrict__ x2) {
    extern __shared__ __align__(16) __nv_bfloat16 sm[];

    int sk = blockIdx.x, bg = blockIdx.y;
    int b = bg / 6, g = bg % 6;
    const int AI[6] = {0, 0, 3, 1, 1, 2};
    const int BI[6] = {0, 3, 3, 1, 2, 2};
    const int SLOT[6] = {0, -1, 1, 2, -1, 3};  // rowsum slot for diagonal grams
    const float* ten[4] = {q1, q2, x1, x2};
    int ai = AI[g], bi = BI[g];
    const float* A = ten[ai] + (size_t)b * CDIM * NTOK;
    const float* Bm = ten[bi] + (size_t)b * CDIM * NTOK;
    bool diag = (ai == bi);
    int slot = SLOT[g];

    int tid = threadIdx.x, lane = tid & 31, wid = tid >> 5;
    int wm = wid >> 2, wn = wid & 3;  // 3 x 4

    uint32_t smb = smem_u32(sm);
    const uint32_t LOFF = STAGE * 2;  // hi->lo byte offset

    float acc[4][6][4];
#pragma unroll
    for (int i = 0; i < 4; i++)
#pragma unroll
        for (int j = 0; j < 6; j++)
#pragma unroll
            for (int k = 0; k < 4; k++) acc[i][j][k] = 0.f;
    float rs[4] = {0.f, 0.f, 0.f, 0.f};  // fused rowsums (diag only)

    int kslab0 = sk * GSLAB;

    // prologue: chunk 0 -> stage 0
    {
        int kb = kslab0;
#pragma unroll
        for (int it = 0; it < 4; it++) {
            int u = tid + it * 384;
            int row = u >> 3, c4 = (u & 7) * 4;
            float4 v = *(const float4*)(A + (size_t)row * NTOK + kb + c4);
            if (diag) rs[it] += v.x + v.y + v.z + v.w;
            cvt_store(v, sm + row * SROW + c4, sm + STAGE + row * SROW + c4);
            if (!diag) {
                float4 w = *(const float4*)(Bm + (size_t)row * NTOK + kb + c4);
                cvt_store(w, sm + 2 * STAGE + row * SROW + c4,
                          sm + 3 * STAGE + row * SROW + c4);
            }
        }
    }
    __syncthreads();

    float4 va[4], vb[4];
    for (int ch = 0; ch < GNCH; ch++) {
        int cur = ch & 1, nxt = cur ^ 1;
        bool pf = (ch + 1 < GNCH);
        if (pf) {
            int kb = kslab0 + (ch + 1) * GCH;
#pragma unroll
            for (int it = 0; it < 4; it++) {
                int u = tid + it * 384;
                va[it] = *(const float4*)(A + (size_t)(u >> 3) * NTOK + kb + (u & 7) * 4);
            }
            if (!diag) {
#pragma unroll
                for (int it = 0; it < 4; it++) {
                    int u = tid + it * 384;
                    vb[it] = *(const float4*)(Bm + (size_t)(u >> 3) * NTOK + kb + (u & 7) * 4);
                }
            }
        }

        // mma on stage cur
        uint32_t base = smb + cur * (4 * STAGE * 2);
        uint32_t aH = base;
        uint32_t bH = diag ? base : base + 2 * STAGE * 2;
#pragma unroll
        for (int s = 0; s < 2; s++) {
            int ks = s * 16;
            uint32_t ah[16], al[16], bb[12];
            int arow0 = wm * 64 + (lane & 15);
            int acol = ks + ((lane >> 4) << 3);
#pragma unroll
            for (int i = 0; i < 4; i++) {
                uint32_t ad = aH + (uint32_t)(((arow0 + i * 16) * SROW + acol) * 2);
                ldsm_x4(ah + 4 * i, ad);
                ldsm_x4(al + 4 * i, ad + LOFF);
            }
            int brow0 = wn * 48 + (lane & 7) + (((lane >> 4) & 1) << 3);
            int bcol = ks + (((lane >> 3) & 1) << 3);
#pragma unroll
            for (int j = 0; j < 3; j++)
                ldsm_x4(bb + 4 * j, bH + (uint32_t)(((brow0 + j * 16) * SROW + bcol) * 2));
#pragma unroll
            for (int i = 0; i < 4; i++)
#pragma unroll
                for (int jj = 0; jj < 6; jj++) {
                    const uint32_t* bp = bb + (jj >> 1) * 4 + (jj & 1) * 2;
                    mma16816(acc[i][jj], ah + 4 * i, bp);
                    mma16816(acc[i][jj], al + 4 * i, bp);
                }
#pragma unroll
            for (int j = 0; j < 3; j++)
                ldsm_x4(bb + 4 * j,
                        bH + LOFF + (uint32_t)(((brow0 + j * 16) * SROW + bcol) * 2));
#pragma unroll
            for (int i = 0; i < 4; i++)
#pragma unroll
                for (int jj = 0; jj < 6; jj++)
                    mma16816(acc[i][jj], ah + 4 * i, bb + (jj >> 1) * 4 + (jj & 1) * 2);
        }

        if (pf) {
            __nv_bfloat16* nb = sm + nxt * 4 * STAGE;
#pragma unroll
            for (int it = 0; it < 4; it++) {
                int u = tid + it * 384;
                int row = u >> 3, c4 = (u & 7) * 4;
                if (diag) rs[it] += va[it].x + va[it].y + va[it].z + va[it].w;
                cvt_store(va[it], nb + row * SROW + c4, nb + STAGE + row * SROW + c4);
            }
            if (!diag) {
#pragma unroll
                for (int it = 0; it < 4; it++) {
                    int u = tid + it * 384;
                    int row = u >> 3, c4 = (u & 7) * 4;
                    cvt_store(vb[it], nb + 2 * STAGE + row * SROW + c4,
                              nb + 3 * STAGE + row * SROW + c4);
                }
            }
        }
        __syncthreads();
    }

    float* C = &g_C[b][g][0][0];
    int r0 = wm * 64 + (lane >> 2);
    int cb = wn * 48 + (lane & 3) * 2;
#pragma unroll
    for (int i = 0; i < 4; i++)
#pragma unroll
        for (int jj = 0; jj < 6; jj++) {
            int rr = r0 + i * 16, cc = cb + jj * 8;
            atomicAdd(C + rr * CDIM + cc, acc[i][jj][0]);
            atomicAdd(C + rr * CDIM + cc + 1, acc[i][jj][1]);
            atomicAdd(C + (rr + 8) * CDIM + cc, acc[i][jj][2]);
            atomicAdd(C + (rr + 8) * CDIM + cc + 1, acc[i][jj][3]);
        }
    if (diag) {
#pragma unroll
        for (int it = 0; it < 4; it++) {
            int row = (tid + it * 384) >> 3;
            atomicAdd(&g_s[b][slot][row], rs[it]);
        }
    }
}

// -------- small NN GEMMs (192x192x192): D = W @ C --------
// mode 0: T[b][g] = W(g) @ C[b][g] (fp32 out). mode 1: M = Wproj @ P, emit bf16 hi/lo.
__global__ void smallgemm_nn(const float* __restrict__ Wq, const float* __restrict__ Wk,
                             const float* __restrict__ Wproj, int mode) {
    int z = blockIdx.z;
    const float* W; const float* C; float* D = nullptr;
    __nv_bfloat16* Dh = nullptr; __nv_bfloat16* Dl = nullptr;
    if (mode == 0) {
        int b = z / 6, g = z % 6;
        W = (g == 2 || g == 5) ? Wk : Wq;
        C = &g_C[b][g][0][0];
        D = &g_T[b][g][0][0];
    } else {
        int b = z / 2, p = z % 2;
        W = Wproj;
        C = &g_P[b][p][0][0];
        Dh = g_Mh[z];
        Dl = g_Ml[z];
    }
    int m0 = blockIdx.y * 32, j0 = blockIdx.x * 32;
    __shared__ float Ws[32][33];
    __shared__ float Cs[32][33];
    int t = threadIdx.x, tx = t % 16, ty = t / 16;
    float acc[2][2] = {{0.f, 0.f}, {0.f, 0.f}};
    for (int k0 = 0; k0 < CDIM; k0 += 32) {
        __syncthreads();
        for (int e = t; e < 1024; e += 256) {
            int r = e / 32, cc = e % 32;
            Ws[r][cc] = W[(m0 + r) * CDIM + k0 + cc];
            Cs[r][cc] = C[(k0 + r) * CDIM + j0 + cc];
        }
        __syncthreads();
#pragma unroll
        for (int kk = 0; kk < 32; kk++) {
            float w0 = Ws[ty * 2 + 0][kk], w1 = Ws[ty * 2 + 1][kk];
            float c0 = Cs[kk][tx * 2 + 0], c1 = Cs[kk][tx * 2 + 1];
            acc[0][0] = fmaf(w0, c0, acc[0][0]);
            acc[0][1] = fmaf(w0, c1, acc[0][1]);
            acc[1][0] = fmaf(w1, c0, acc[1][0]);
            acc[1][1] = fmaf(w1, c1, acc[1][1]);
        }
    }
    if (mode == 0) {
#pragma unroll
        for (int i = 0; i < 2; i++)
#pragma unroll
            for (int j = 0; j < 2; j++)
                D[(m0 + ty * 2 + i) * CDIM + (j0 + tx * 2 + j)] = acc[i][j];
    } else {
#pragma unroll
        for (int i = 0; i < 2; i++)
#pragma unroll
            for (int j = 0; j < 2; j++) {
                __nv_bfloat16 h, l;
                cvt_hl(acc[i][j], h, l);
                int idx = (m0 + ty * 2 + i) * CDIM + (j0 + tx * 2 + j);
                Dh[idx] = h;
                Dl[idx] = l;
            }
    }
}

// -------- per-batch vectors (warp per (b,c)) --------
__global__ void vec_kernel(const float* __restrict__ Wq, const float* __restrict__ Wk,
                           const float* __restrict__ bq, const float* __restrict__ bk) {
    int c = blockIdx.x, b = blockIdx.y, l = threadIdx.x;
    float a0 = 0, a1 = 0, a2 = 0, a3 = 0, d0 = 0, d2 = 0, d3 = 0, d5 = 0;
    for (int i = l; i < CDIM; i += 32) {
        float wq = Wq[c * CDIM + i], wk = Wk[c * CDIM + i];
        a0 = fmaf(wq, g_s[b][0][i], a0);
        a1 = fmaf(wk, g_s[b][1][i], a1);
        a2 = fmaf(wq, g_s[b][2][i], a2);
        a3 = fmaf(wk, g_s[b][3][i], a3);
        d0 = fmaf(g_T[b][0][c][i], wq, d0);
        d2 = fmaf(g_T[b][2][c][i], wk, d2);
        d3 = fmaf(g_T[b][3][c][i], wq, d3);
        d5 = fmaf(g_T[b][5][c][i], wk, d5);
    }
#pragma unroll
    for (int s = 16; s > 0; s >>= 1) {
        a0 += __shfl_xor_sync(0xffffffff, a0, s);
        a1 += __shfl_xor_sync(0xffffffff, a1, s);
        a2 += __shfl_xor_sync(0xffffffff, a2, s);
        a3 += __shfl_xor_sync(0xffffffff, a3, s);
        d0 += __shfl_xor_sync(0xffffffff, d0, s);
        d2 += __shfl_xor_sync(0xffffffff, d2, s);
        d3 += __shfl_xor_sync(0xffffffff, d3, s);
        d5 += __shfl_xor_sync(0xffffffff, d5, s);
    }
    if (l == 0) {
        float bqc = bq[c], bkc = bk[c];
        const float NN = (float)NTOK;
        g_vec[b][0][c] = a0;
        g_vec[b][1][c] = a1;
        g_vec[b][2][c] = a2;
        g_vec[b][3][c] = a3;
        g_vec[b][4][c] = sqrtf(fmaxf(d0 + 2.f * bqc * a0 + NN * bqc * bqc, 0.f));
        g_vec[b][5][c] = sqrtf(fmaxf(d2 + 2.f * bkc * a1 + NN * bkc * bkc, 0.f));
        g_vec[b][6][c] = sqrtf(fmaxf(d3 + 2.f * bqc * a2 + NN * bqc * bqc, 0.f));
        g_vec[b][7][c] = sqrtf(fmaxf(d5 + 2.f * bkc * a3 + NN * bkc * bkc, 0.f));
    }
}

// -------- logits + softmax --------
__global__ void attn_kernel(const float* __restrict__ Wk, const float* __restrict__ bq,
                            const float* __restrict__ bk, const float* __restrict__ scale,
                            const float* __restrict__ bv) {
    int h = blockIdx.x, pair = blockIdx.y, b = blockIdx.z;
    __shared__ float sTA[HD][CDIM];
    __shared__ float sWk[HD][CDIM];
    __shared__ float slog[HD][HD];
    const float* TA = pair ? &g_T[b][4][0][0] : &g_T[b][1][0][0];
    const float* wqs = pair ? g_vec[b][2] : g_vec[b][0];
    const float* wks = pair ? g_vec[b][3] : g_vec[b][1];
    const float* nq = pair ? g_vec[b][6] : g_vec[b][4];
    const float* nk = pair ? g_vec[b][7] : g_vec[b][5];
    int t = threadIdx.x;
    for (int e = t; e < HD * CDIM; e += 256) {
        int r = e / CDIM, cc = e % CDIM;
        sTA[r][cc] = TA[(h * HD + r) * CDIM + cc];
        sWk[r][cc] = Wk[(h * HD + r) * CDIM + cc];
    }
    __syncthreads();
    float sc = scale[h];
    const float NN = (float)NTOK;
    for (int e = t; e < HD * HD; e += 256) {
        int i = e / HD, j = e % HD;
        int c = h * HD + i, d = h * HD + j;
        float dot = 0.f;
        for (int k = 0; k < CDIM; k++) dot = fmaf(sTA[i][k], sWk[j][k], dot);
        float raw = dot + wqs[c] * bk[d] + bq[c] * wks[d] + NN * bq[c] * bk[d];
        slog[i][j] = raw / (fmaxf(nq[c], 1e-12f) * fmaxf(nk[d], 1e-12f)) * sc;
    }
    __syncthreads();
    if (t < HD) {
        int i = t;
        float m = -INFINITY;
        for (int j = 0; j < HD; j++) m = fmaxf(m, slog[i][j]);
        float ex[HD];
        float sum = 0.f;
        for (int j = 0; j < HD; j++) { ex[j] = expf(slog[i][j] - m); sum += ex[j]; }
        float inv = 1.f / sum;
        float tv = 0.f;
        for (int j = 0; j < HD; j++) {
            float a = ex[j] * inv;
            g_attn[b][pair][h][i][j] = a;
            tv = fmaf(a, bv[h * HD + j], tv);
        }
        g_tvec[b][pair][h * HD + i] = tv;
    }
}

__global__ void cvec_kernel(const float* __restrict__ Wproj) {
    int b = blockIdx.x, p = blockIdx.y, c = threadIdx.x;
    __shared__ float tv[CDIM];
    tv[c] = g_tvec[b][p][c];
    __syncthreads();
    float s = 0.f;
    for (int i = 0; i < CDIM; i++) s = fmaf(Wproj[c * CDIM + i], tv[i], s);
    g_cvec[b][p][c] = s;
}

__global__ void p_kernel(const float* __restrict__ Wv) {
    int vt = blockIdx.x, p = blockIdx.y, b = blockIdx.z;
    int v0 = vt * 32;
    __shared__ float sA[NHEADS][HD][HD];
    __shared__ float sWv[CDIM][32];
    int t = threadIdx.x;
    const float* attnflat = &g_attn[b][p][0][0][0];
    for (int e = t; e < NHEADS * HD * HD; e += 256) (&sA[0][0][0])[e] = attnflat[e];
    for (int e = t; e < CDIM * 32; e += 256) {
        int r = e / 32, vc = e % 32;
        sWv[r][vc] = Wv[r * CDIM + v0 + vc];
    }
    __syncthreads();
    for (int e = t; e < CDIM * 32; e += 256) {
        int c = e / 32, vc = e % 32;
        int h = c / HD, i = c % HD;
        float acc = 0.f;
#pragma unroll
        for (int j = 0; j < HD; j++) acc = fmaf(sA[h][i][j], sWv[h * HD + j][vc], acc);
        g_P[b][p][c][v0 + vc] = acc;
    }
}

// out = M @ X + cvec ; M resident in smem, X double-buffered.
// grid (NTOK/128, 16), 384 threads (12 warps 3x4, warp 64x32)
__global__ __launch_bounds__(384, 1) void out_mma(const float* __restrict__ x1,
                                                  const float* __restrict__ x2,
                                                  float* __restrict__ out) {
    extern __shared__ __align__(16) __nv_bfloat16 smo[];
    __nv_bfloat16* sM = smo;                       // hi [CDIM*MROW], lo at +CDIM*MROW
    __nv_bfloat16* sX = smo + 2 * CDIM * MROW;     // stage s: hi at s*2*XSTAGE, lo +XSTAGE
    float* scv = (float*)(smo + 2 * CDIM * MROW + 4 * XSTAGE);

    int z = blockIdx.y;
    int b = z >> 1, p = z & 1;
    const float* X = (p ? x1 : x2) + (size_t)b * CDIM * NTOK;
    const __nv_bfloat16* Mh = g_Mh[z];
    const __nv_bfloat16* Ml = g_Ml[z];
    float* O = out + (size_t)p * BATCH * CDIM * NTOK + (size_t)b * CDIM * NTOK;
    int n0 = blockIdx.x * 128;

    int tid = threadIdx.x, lane = tid & 31, wid = tid >> 5;
    int wm = wid >> 2, wn = wid & 3;

    if (tid < CDIM) scv[tid] = g_cvec[b][p][tid];

    // resident M load (hi+lo), padded stride MROW
    for (int u = tid; u < CDIM * CDIM / 8; u += 384) {
        int row = u / 24, col = (u % 24) * 8;
        *(uint4*)(sM + row * MROW + col) = *(const uint4*)(Mh + row * CDIM + col);
        *(uint4*)(sM + CDIM * MROW + row * MROW + col) = *(const uint4*)(Ml + row * CDIM + col);
    }
    // X chunk 0 -> stage 0
    for (int u = tid; u < 1024; u += 384) {
        int r = u >> 5, c4 = (u & 31) * 4;
        float4 v = *(const float4*)(X + (size_t)r * NTOK + n0 + c4);
        cvt_store(v, sX + r * OXROW + c4, sX + XSTAGE + r * OXROW + c4);
    }
    __syncthreads();

    uint32_t sM_a = smem_u32(sM);
    uint32_t sX_a = smem_u32(sX);
    const uint32_t MLOFF = CDIM * MROW * 2;
    const uint32_t XLOFF = XSTAGE * 2;

    float acc[4][4][4];
#pragma unroll
    for (int i = 0; i < 4; i++)
#pragma unroll
        for (int j = 0; j < 4; j++)
#pragma unroll
            for (int k = 0; k < 4; k++) acc[i][j][k] = 0.f;

    float4 vx[3];
    for (int ch = 0; ch < 6; ch++) {
        int cur = ch & 1, nxt = cur ^ 1;
        bool pf = (ch < 5);
        if (pf) {
            int kb = (ch + 1) * 32;
#pragma unroll
            for (int it = 0; it < 3; it++) {
                int u = tid + it * 384;
                if (u < 1024) {
                    int r = u >> 5, c4 = (u & 31) * 4;
                    vx[it] = *(const float4*)(X + (size_t)(kb + r) * NTOK + n0 + c4);
                }
            }
        }

        uint32_t xb = sX_a + cur * (2 * XSTAGE * 2);
#pragma unroll
        for (int s = 0; s < 2; s++) {
            int kg = ch * 32 + s * 16;
            uint32_t ah[16], al[16], bx[8];
            int arow0 = wm * 64 + (lane & 15);
            int acol = kg + ((lane >> 4) << 3);
#pragma unroll
            for (int i = 0; i < 4; i++) {
                uint32_t ad = sM_a + (uint32_t)(((arow0 + i * 16) * MROW + acol) * 2);
                ldsm_x4(ah + 4 * i, ad);
                ldsm_x4(al + 4 * i, ad + MLOFF);
            }
            int krow = s * 16 + (lane & 7) + (((lane >> 3) & 1) << 3);
            int ncol0 = wn * 32 + ((lane >> 4) << 3);
#pragma unroll
            for (int jb = 0; jb < 2; jb++)
                ldsm_x4_t(bx + 4 * jb, xb + (uint32_t)((krow * OXROW + ncol0 + jb * 16) * 2));
#pragma unroll
            for (int i = 0; i < 4; i++)
#pragma unroll
                for (int jj = 0; jj < 4; jj++) {
                    const uint32_t* bp = bx + (jj >> 1) * 4 + (jj & 1) * 2;
                    mma16816(acc[i][jj], ah + 4 * i, bp);
                    mma16816(acc[i][jj], al + 4 * i, bp);
                }
#pragma unroll
            for (int jb = 0; jb < 2; jb++)
                ldsm_x4_t(bx + 4 * jb,
                          xb + XLOFF + (uint32_t)((krow * OXROW + ncol0 + jb * 16) * 2));
#pragma unroll
            for (int i = 0; i < 4; i++)
#pragma unroll
                for (int jj = 0; jj < 4; jj++)
                    mma16816(acc[i][jj], ah + 4 * i, bx + (jj >> 1) * 4 + (jj & 1) * 2);
        }

        if (pf) {
            __nv_bfloat16* nb = sX + nxt * 2 * XSTAGE;
#pragma unroll
            for (int it = 0; it < 3; it++) {
                int u = tid + it * 384;
                if (u < 1024) {
                    int r = u >> 5, c4 = (u & 31) * 4;
                    cvt_store(vx[it], nb + r * OXROW + c4, nb + XSTAGE + r * OXROW + c4);
                }
            }
        }
        __syncthreads();
    }

    int r0 = wm * 64 + (lane >> 2);
    int nb = n0 + wn * 32 + (lane & 3) * 2;
#pragma unroll
    for (int i = 0; i < 4; i++) {
        int c = r0 + i * 16;
        float b0 = scv[c], b1 = scv[c + 8];
#pragma unroll
        for (int jj = 0; jj < 4; jj++) {
            float2 v0 = {acc[i][jj][0] + b0, acc[i][jj][1] + b0};
            float2 v1 = {acc[i][jj][2] + b1, acc[i][jj][3] + b1};
            *(float2*)(O + (size_t)c * NTOK + nb + jj * 8) = v0;
            *(float2*)(O + (size_t)(c + 8) * NTOK + nb + jj * 8) = v1;
        }
    }
}

extern "C" void kernel_launch(void* const* d_in, const int* in_sizes, int n_in,
                              void* d_out, int out_size) {
    const float* x1 = (const float*)d_in[0];
    const float* x2 = (const float*)d_in[1];
    const float* q1 = (const float*)d_in[2];
    const float* q2 = (const float*)d_in[3];
    const float* Wq = (const float*)d_in[4];
    const float* bq = (const float*)d_in[5];
    const float* Wk = (const float*)d_in[6];
    const float* bk = (const float*)d_in[7];
    const float* Wv = (const float*)d_in[8];
    const float* bv = (const float*)d_in[9];
    const float* scale = (const float*)d_in[10];
    const float* Wproj = (const float*)d_in[11];
    float* out = (float*)d_out;

    static int configured = 0;
    if (!configured) {
        cudaFuncSetAttribute(gram_mma, cudaFuncAttributeMaxDynamicSharedMemorySize, GRAM_SMEM);
        cudaFuncSetAttribute(out_mma, cudaFuncAttributeMaxDynamicSharedMemorySize, OUT_SMEM);
        configured = 1;
    }

    zero_kernel<<<256, 256>>>();
    gram_mma<<<dim3(GSPLITK, BATCH * 6), 384, GRAM_SMEM>>>(q1, q2, x1, x2);
    smallgemm_nn<<<dim3(6, 6, BATCH * 6), 256>>>(Wq, Wk, Wproj, 0);
    vec_kernel<<<dim3(CDIM, BATCH), 32>>>(Wq, Wk, bq, bk);
    attn_kernel<<<dim3(NHEADS, 2, BATCH), 256>>>(Wk, bq, bk, scale, bv);
    cvec_kernel<<<dim3(BATCH, 2), CDIM>>>(Wproj);
    p_kernel<<<dim3(6, 2, BATCH), 256>>>(Wv);
    smallgemm_nn<<<dim3(6, 6, BATCH * 2), 256>>>(Wq, Wk, Wproj, 1);
    out_mma<<<dim3(NTOK / 128, BATCH * 2), 384, OUT_SMEM>>>(x1, x2, out);
}

// round 6
// speedup vs baseline: 2.8433x; 1.0335x over previous
#include <cuda_runtime.h>
#include <cuda_bf16.h>
#include <math.h>
#include <stdint.h>

#define NTOK 16384
#define CDIM 192
#define BATCH 8
#define NHEADS 8
#define HD 24

// gram config (triple-fused)
#define GSPLITK 8
#define GSLAB (NTOK / GSPLITK)  // 2048
#define GCH 16                  // k elems per chunk
#define GNCH (GSLAB / GCH)      // 128
#define SROW 24                 // padded smem row stride (bf16 elems)
#define RNG (96 * SROW)         // elems per (arr,hl) plane
#define ARR (2 * RNG)           // per array (hi+lo)
#define STG (4 * ARR)           // per stage (4 arrays)
#define GRAM_SMEM (2 * STG * 2) // bytes (2 stages)

// out config
#define MROW 200
#define OXROW 136
#define XSTAGE (32 * OXROW)
#define OUT_SMEM (2 * CDIM * MROW * 2 + 2 * 2 * XSTAGE * 2 + CDIM * 4)

// -------- scratch --------
__device__ float g_C[BATCH][6][CDIM][CDIM];
__device__ float g_s[BATCH][4][CDIM];  // rowsums: q1, x2, q2, x1
__device__ float g_T[BATCH][6][CDIM][CDIM];
__device__ float g_vec[BATCH][8][CDIM];
__device__ float g_attn[BATCH][2][NHEADS][HD][HD];
__device__ float g_tvec[BATCH][2][CDIM];
__device__ float g_cvec[BATCH][2][CDIM];
__device__ float g_P[BATCH][2][CDIM][CDIM];
__device__ __nv_bfloat16 g_Mh[BATCH * 2][CDIM * CDIM];
__device__ __nv_bfloat16 g_Ml[BATCH * 2][CDIM * CDIM];

// ================= mma helpers (sm_80-portable) =================
__device__ __forceinline__ uint32_t smem_u32(const void* p) {
    uint32_t a;
    asm("{ .reg .u64 t; cvta.to.shared.u64 t, %1; cvt.u32.u64 %0, t; }" : "=r"(a) : "l"(p));
    return a;
}
__device__ __forceinline__ void ldsm_x4(uint32_t* r, uint32_t addr) {
    asm volatile("ldmatrix.sync.aligned.m8n8.x4.shared.b16 {%0,%1,%2,%3}, [%4];"
                 : "=r"(r[0]), "=r"(r[1]), "=r"(r[2]), "=r"(r[3]) : "r"(addr));
}
__device__ __forceinline__ void ldsm_x4_t(uint32_t* r, uint32_t addr) {
    asm volatile("ldmatrix.sync.aligned.m8n8.x4.trans.shared.b16 {%0,%1,%2,%3}, [%4];"
                 : "=r"(r[0]), "=r"(r[1]), "=r"(r[2]), "=r"(r[3]) : "r"(addr));
}
__device__ __forceinline__ void mma16816(float* d, const uint32_t* a, const uint32_t* b) {
    asm volatile(
        "mma.sync.aligned.m16n8k16.row.col.f32.bf16.bf16.f32 "
        "{%0,%1,%2,%3}, {%4,%5,%6,%7}, {%8,%9}, {%0,%1,%2,%3};"
        : "+f"(d[0]), "+f"(d[1]), "+f"(d[2]), "+f"(d[3])
        : "r"(a[0]), "r"(a[1]), "r"(a[2]), "r"(a[3]), "r"(b[0]), "r"(b[1]));
}
__device__ __forceinline__ void cvt_hl(float v, __nv_bfloat16& h, __nv_bfloat16& l) {
    h = __float2bfloat16(v);
    l = __float2bfloat16(v - __bfloat162float(h));
}
// packed: float4 -> 4 bf16 hi (8B STS) + 4 bf16 lo (8B STS)
__device__ __forceinline__ void cvt_store(float4 v, __nv_bfloat16* dh, __nv_bfloat16* dl) {
    __nv_bfloat162 h01 = __floats2bfloat162_rn(v.x, v.y);
    __nv_bfloat162 h23 = __floats2bfloat162_rn(v.z, v.w);
    float2 f01 = __bfloat1622float2(h01);
    float2 f23 = __bfloat1622float2(h23);
    __nv_bfloat162 l01 = __floats2bfloat162_rn(v.x - f01.x, v.y - f01.y);
    __nv_bfloat162 l23 = __floats2bfloat162_rn(v.z - f23.x, v.w - f23.y);
    uint2 uh, ul;
    uh.x = *(uint32_t*)&h01;
    uh.y = *(uint32_t*)&h23;
    ul.x = *(uint32_t*)&l01;
    ul.y = *(uint32_t*)&l23;
    *(uint2*)dh = uh;
    *(uint2*)dl = ul;
}

// ================= kernels =================
__global__ void zero_kernel() {
    size_t n = sizeof(g_C) / 4;
    float* c = &g_C[0][0][0][0];
    for (size_t i = (size_t)blockIdx.x * blockDim.x + threadIdx.x; i < n;
         i += (size_t)gridDim.x * blockDim.x)
        c[i] = 0.f;
    size_t ns = sizeof(g_s) / 4;
    float* s = &g_s[0][0][0];
    for (size_t i = (size_t)blockIdx.x * blockDim.x + threadIdx.x; i < ns;
         i += (size_t)gridDim.x * blockDim.x)
        s[i] = 0.f;
}

// Triple-fused tensor-core gram:
//   triple tr: A = (q1|q2), B = (x2|x1); computes C1 = A@A^T, C2 = A@B^T, C3 = B@B^T
// CTA owns a 96x96 output tile (ti, tj) of each gram for one split-K slab.
// C1/C3 tiles with ti>tj are reconstructed by transposed writes from (tj,ti).
// Fused rowsums. grid (GSPLITK, 4, BATCH*2), 384 threads (12 warps 2x6, warp 48x16/gram).
__global__ __launch_bounds__(384, 1) void gram_mma(const float* __restrict__ q1,
                                                   const float* __restrict__ q2,
                                                   const float* __restrict__ x1,
                                                   const float* __restrict__ x2) {
    extern __shared__ __align__(16) __nv_bfloat16 sm[];

    int sk = blockIdx.x;
    int ti = blockIdx.y >> 1, tj = blockIdx.y & 1;
    int b = blockIdx.z >> 1, tr = blockIdx.z & 1;
    const float* A = (tr ? q2 : q1) + (size_t)b * CDIM * NTOK;
    const float* B = (tr ? x1 : x2) + (size_t)b * CDIM * NTOK;
    int slotA = tr ? 2 : 0, slotB = tr ? 3 : 1;
    float* C1 = &g_C[b][tr * 3 + 0][0][0];
    float* C2 = &g_C[b][tr * 3 + 1][0][0];
    float* C3 = &g_C[b][tr * 3 + 2][0][0];
    bool doC1 = (ti <= tj);   // compute symmetric grams only in upper tiles
    bool trw = (ti < tj);     // also emit transposed copy
    bool aliasJ = (ti == tj);
    int arrAj = aliasJ ? 0 : 1;
    int arrBj = aliasJ ? 2 : 3;

    // build load list: ranges actually needed by this CTA's grams
    const float* lsrc[4];
    int larr[4], lslot[4], lrb[4], nld = 0;
    lsrc[nld] = A + (size_t)ti * 96 * NTOK; larr[nld] = 0;
    lslot[nld] = (tj == 0) ? slotA : -1; lrb[nld] = ti * 96; nld++;
    if (doC1 && !aliasJ) {
        lsrc[nld] = A + (size_t)tj * 96 * NTOK; larr[nld] = 1;
        lslot[nld] = -1; lrb[nld] = tj * 96; nld++;
    }
    if (doC1) {
        lsrc[nld] = B + (size_t)ti * 96 * NTOK; larr[nld] = 2;
        lslot[nld] = (aliasJ && ti == 0) ? slotB : -1; lrb[nld] = ti * 96; nld++;
    }
    if (!aliasJ) {
        lsrc[nld] = B + (size_t)tj * 96 * NTOK; larr[nld] = 3;
        lslot[nld] = (ti == 0) ? slotB : -1; lrb[nld] = tj * 96; nld++;
    }

    int tid = threadIdx.x, lane = tid & 31, wid = tid >> 5;
    int wm = wid / 6, wn = wid % 6;  // 2 x 6 warps; warp tile 48 x 16 per gram
    uint32_t smb = smem_u32(sm);

    float accC1[3][2][4] = {}, accC2[3][2][4] = {}, accC3[3][2][4] = {};
    float rs[4] = {0.f, 0.f, 0.f, 0.f};

    int row = tid >> 2, c4 = (tid & 3) * 4;
    int kb0 = sk * GSLAB;

    // prologue: chunk 0 -> stage 0
#pragma unroll
    for (int l = 0; l < 4; l++)
        if (l < nld) {
            float4 v = *(const float4*)(lsrc[l] + (size_t)row * NTOK + kb0 + c4);
            if (lslot[l] >= 0) rs[l] += v.x + v.y + v.z + v.w;
            __nv_bfloat16* dp = sm + larr[l] * ARR + row * SROW + c4;
            cvt_store(v, dp, dp + RNG);
        }
    __syncthreads();

    float4 va[4];
    for (int ch = 0; ch < GNCH; ch++) {
        int cur = ch & 1, nxt = cur ^ 1;
        bool pf = (ch + 1 < GNCH);
        if (pf) {
            int kb = kb0 + (ch + 1) * GCH;
#pragma unroll
            for (int l = 0; l < 4; l++)
                if (l < nld)
                    va[l] = *(const float4*)(lsrc[l] + (size_t)row * NTOK + kb + c4);
        }

        uint32_t base = smb + cur * (STG * 2);
        int arow = wm * 48 + (lane & 15);
        int acol = (lane >> 4) * 8;
        int brow = wn * 16 + (lane & 7) + (((lane >> 4) & 1) << 3);
        int bcol = ((lane >> 3) & 1) * 8;

        uint32_t aih[12], ail[12];
#pragma unroll
        for (int f = 0; f < 3; f++) {
            uint32_t ad = base + (uint32_t)(((arow + f * 16) * SROW + acol) * 2);
            ldsm_x4(aih + 4 * f, ad);
            ldsm_x4(ail + 4 * f, ad + RNG * 2);
        }
        if (doC1) {
            uint32_t ajh[4], ajl[4];
            uint32_t jd = base + (uint32_t)((arrAj * ARR + brow * SROW + bcol) * 2);
            ldsm_x4(ajh, jd);
            ldsm_x4(ajl, jd + RNG * 2);
#pragma unroll
            for (int f = 0; f < 3; f++)
#pragma unroll
                for (int n = 0; n < 2; n++) {
                    mma16816(accC1[f][n], aih + 4 * f, ajh + 2 * n);
                    mma16816(accC1[f][n], aih + 4 * f, ajl + 2 * n);
                    mma16816(accC1[f][n], ail + 4 * f, ajh + 2 * n);
                }
        }
        uint32_t bjh[4], bjl[4];
        {
            uint32_t bd = base + (uint32_t)((arrBj * ARR + brow * SROW + bcol) * 2);
            ldsm_x4(bjh, bd);
            ldsm_x4(bjl, bd + RNG * 2);
        }
#pragma unroll
        for (int f = 0; f < 3; f++)
#pragma unroll
            for (int n = 0; n < 2; n++) {
                mma16816(accC2[f][n], aih + 4 * f, bjh + 2 * n);
                mma16816(accC2[f][n], aih + 4 * f, bjl + 2 * n);
                mma16816(accC2[f][n], ail + 4 * f, bjh + 2 * n);
            }
        if (doC1) {
            uint32_t bih[12], bil[12];
#pragma unroll
            for (int f = 0; f < 3; f++) {
                uint32_t bd2 = base + (uint32_t)((2 * ARR + (arow + f * 16) * SROW + acol) * 2);
                ldsm_x4(bih + 4 * f, bd2);
                ldsm_x4(bil + 4 * f, bd2 + RNG * 2);
            }
#pragma unroll
            for (int f = 0; f < 3; f++)
#pragma unroll
                for (int n = 0; n < 2; n++) {
                    mma16816(accC3[f][n], bih + 4 * f, bjh + 2 * n);
                    mma16816(accC3[f][n], bih + 4 * f, bjl + 2 * n);
                    mma16816(accC3[f][n], bil + 4 * f, bjh + 2 * n);
                }
        }

        if (pf) {
            uint32_t nb = nxt * STG;
#pragma unroll
            for (int l = 0; l < 4; l++)
                if (l < nld) {
                    if (lslot[l] >= 0) rs[l] += va[l].x + va[l].y + va[l].z + va[l].w;
                    __nv_bfloat16* dp = sm + nb + larr[l] * ARR + row * SROW + c4;
                    cvt_store(va[l], dp, dp + RNG);
                }
        }
        __syncthreads();
    }

    // epilogue: atomic accumulation into g_C (+ transposed copies for symmetric tiles)
    int r0g = ti * 96 + wm * 48 + (lane >> 2);
    int c0g = tj * 96 + wn * 16 + (lane & 3) * 2;
#pragma unroll
    for (int f = 0; f < 3; f++)
#pragma unroll
        for (int n = 0; n < 2; n++) {
            int r = r0g + f * 16, c = c0g + n * 8;
            const float* a2 = accC2[f][n];
            atomicAdd(C2 + r * CDIM + c, a2[0]);
            atomicAdd(C2 + r * CDIM + c + 1, a2[1]);
            atomicAdd(C2 + (r + 8) * CDIM + c, a2[2]);
            atomicAdd(C2 + (r + 8) * CDIM + c + 1, a2[3]);
            if (doC1) {
                const float* a1 = accC1[f][n];
                const float* a3 = accC3[f][n];
                atomicAdd(C1 + r * CDIM + c, a1[0]);
                atomicAdd(C1 + r * CDIM + c + 1, a1[1]);
                atomicAdd(C1 + (r + 8) * CDIM + c, a1[2]);
                atomicAdd(C1 + (r + 8) * CDIM + c + 1, a1[3]);
                atomicAdd(C3 + r * CDIM + c, a3[0]);
                atomicAdd(C3 + r * CDIM + c + 1, a3[1]);
                atomicAdd(C3 + (r + 8) * CDIM + c, a3[2]);
                atomicAdd(C3 + (r + 8) * CDIM + c + 1, a3[3]);
                if (trw) {
                    atomicAdd(C1 + c * CDIM + r, a1[0]);
                    atomicAdd(C1 + (c + 1) * CDIM + r, a1[1]);
                    atomicAdd(C1 + c * CDIM + r + 8, a1[2]);
                    atomicAdd(C1 + (c + 1) * CDIM + r + 8, a1[3]);
                    atomicAdd(C3 + c * CDIM + r, a3[0]);
                    atomicAdd(C3 + (c + 1) * CDIM + r, a3[1]);
                    atomicAdd(C3 + c * CDIM + r + 8, a3[2]);
                    atomicAdd(C3 + (c + 1) * CDIM + r + 8, a3[3]);
                }
            }
        }
#pragma unroll
    for (int l = 0; l < 4; l++)
        if (l < nld && lslot[l] >= 0) atomicAdd(&g_s[b][lslot[l]][lrb[l] + row], rs[l]);
}

// -------- small NN GEMMs (192x192x192): D = W @ C --------
// mode 0: T[b][g] = W(g) @ C[b][g] (fp32 out). mode 1: M = Wproj @ P, emit bf16 hi/lo.
__global__ void smallgemm_nn(const float* __restrict__ Wq, const float* __restrict__ Wk,
                             const float* __restrict__ Wproj, int mode) {
    int z = blockIdx.z;
    const float* W; const float* C; float* D = nullptr;
    __nv_bfloat16* Dh = nullptr; __nv_bfloat16* Dl = nullptr;
    if (mode == 0) {
        int b = z / 6, g = z % 6;
        W = (g == 2 || g == 5) ? Wk : Wq;
        C = &g_C[b][g][0][0];
        D = &g_T[b][g][0][0];
    } else {
        int b = z / 2, p = z % 2;
        W = Wproj;
        C = &g_P[b][p][0][0];
        Dh = g_Mh[z];
        Dl = g_Ml[z];
    }
    int m0 = blockIdx.y * 32, j0 = blockIdx.x * 32;
    __shared__ float Ws[32][33];
    __shared__ float Cs[32][33];
    int t = threadIdx.x, tx = t % 16, ty = t / 16;
    float acc[2][2] = {{0.f, 0.f}, {0.f, 0.f}};
    for (int k0 = 0; k0 < CDIM; k0 += 32) {
        __syncthreads();
        for (int e = t; e < 1024; e += 256) {
            int r = e / 32, cc = e % 32;
            Ws[r][cc] = W[(m0 + r) * CDIM + k0 + cc];
            Cs[r][cc] = C[(k0 + r) * CDIM + j0 + cc];
        }
        __syncthreads();
#pragma unroll
        for (int kk = 0; kk < 32; kk++) {
            float w0 = Ws[ty * 2 + 0][kk], w1 = Ws[ty * 2 + 1][kk];
            float c0 = Cs[kk][tx * 2 + 0], c1 = Cs[kk][tx * 2 + 1];
            acc[0][0] = fmaf(w0, c0, acc[0][0]);
            acc[0][1] = fmaf(w0, c1, acc[0][1]);
            acc[1][0] = fmaf(w1, c0, acc[1][0]);
            acc[1][1] = fmaf(w1, c1, acc[1][1]);
        }
    }
    if (mode == 0) {
#pragma unroll
        for (int i = 0; i < 2; i++)
#pragma unroll
            for (int j = 0; j < 2; j++)
                D[(m0 + ty * 2 + i) * CDIM + (j0 + tx * 2 + j)] = acc[i][j];
    } else {
#pragma unroll
        for (int i = 0; i < 2; i++)
#pragma unroll
            for (int j = 0; j < 2; j++) {
                __nv_bfloat16 h, l;
                cvt_hl(acc[i][j], h, l);
                int idx = (m0 + ty * 2 + i) * CDIM + (j0 + tx * 2 + j);
                Dh[idx] = h;
                Dl[idx] = l;
            }
    }
}

// -------- per-batch vectors (warp per (b,c)) --------
__global__ void vec_kernel(const float* __restrict__ Wq, const float* __restrict__ Wk,
                           const float* __restrict__ bq, const float* __restrict__ bk) {
    int c = blockIdx.x, b = blockIdx.y, l = threadIdx.x;
    float a0 = 0, a1 = 0, a2 = 0, a3 = 0, d0 = 0, d2 = 0, d3 = 0, d5 = 0;
    for (int i = l; i < CDIM; i += 32) {
        float wq = Wq[c * CDIM + i], wk = Wk[c * CDIM + i];
        a0 = fmaf(wq, g_s[b][0][i], a0);
        a1 = fmaf(wk, g_s[b][1][i], a1);
        a2 = fmaf(wq, g_s[b][2][i], a2);
        a3 = fmaf(wk, g_s[b][3][i], a3);
        d0 = fmaf(g_T[b][0][c][i], wq, d0);
        d2 = fmaf(g_T[b][2][c][i], wk, d2);
        d3 = fmaf(g_T[b][3][c][i], wq, d3);
        d5 = fmaf(g_T[b][5][c][i], wk, d5);
    }
#pragma unroll
    for (int s = 16; s > 0; s >>= 1) {
        a0 += __shfl_xor_sync(0xffffffff, a0, s);
        a1 += __shfl_xor_sync(0xffffffff, a1, s);
        a2 += __shfl_xor_sync(0xffffffff, a2, s);
        a3 += __shfl_xor_sync(0xffffffff, a3, s);
        d0 += __shfl_xor_sync(0xffffffff, d0, s);
        d2 += __shfl_xor_sync(0xffffffff, d2, s);
        d3 += __shfl_xor_sync(0xffffffff, d3, s);
        d5 += __shfl_xor_sync(0xffffffff, d5, s);
    }
    if (l == 0) {
        float bqc = bq[c], bkc = bk[c];
        const float NN = (float)NTOK;
        g_vec[b][0][c] = a0;
        g_vec[b][1][c] = a1;
        g_vec[b][2][c] = a2;
        g_vec[b][3][c] = a3;
        g_vec[b][4][c] = sqrtf(fmaxf(d0 + 2.f * bqc * a0 + NN * bqc * bqc, 0.f));
        g_vec[b][5][c] = sqrtf(fmaxf(d2 + 2.f * bkc * a1 + NN * bkc * bkc, 0.f));
        g_vec[b][6][c] = sqrtf(fmaxf(d3 + 2.f * bqc * a2 + NN * bqc * bqc, 0.f));
        g_vec[b][7][c] = sqrtf(fmaxf(d5 + 2.f * bkc * a3 + NN * bkc * bkc, 0.f));
    }
}

// -------- logits + softmax --------
__global__ void attn_kernel(const float* __restrict__ Wk, const float* __restrict__ bq,
                            const float* __restrict__ bk, const float* __restrict__ scale,
                            const float* __restrict__ bv) {
    int h = blockIdx.x, pair = blockIdx.y, b = blockIdx.z;
    __shared__ float sTA[HD][CDIM];
    __shared__ float sWk[HD][CDIM];
    __shared__ float slog[HD][HD];
    const float* TA = pair ? &g_T[b][4][0][0] : &g_T[b][1][0][0];
    const float* wqs = pair ? g_vec[b][2] : g_vec[b][0];
    const float* wks = pair ? g_vec[b][3] : g_vec[b][1];
    const float* nq = pair ? g_vec[b][6] : g_vec[b][4];
    const float* nk = pair ? g_vec[b][7] : g_vec[b][5];
    int t = threadIdx.x;
    for (int e = t; e < HD * CDIM; e += 256) {
        int r = e / CDIM, cc = e % CDIM;
        sTA[r][cc] = TA[(h * HD + r) * CDIM + cc];
        sWk[r][cc] = Wk[(h * HD + r) * CDIM + cc];
    }
    __syncthreads();
    float sc = scale[h];
    const float NN = (float)NTOK;
    for (int e = t; e < HD * HD; e += 256) {
        int i = e / HD, j = e % HD;
        int c = h * HD + i, d = h * HD + j;
        float dot = 0.f;
        for (int k = 0; k < CDIM; k++) dot = fmaf(sTA[i][k], sWk[j][k], dot);
        float raw = dot + wqs[c] * bk[d] + bq[c] * wks[d] + NN * bq[c] * bk[d];
        slog[i][j] = raw / (fmaxf(nq[c], 1e-12f) * fmaxf(nk[d], 1e-12f)) * sc;
    }
    __syncthreads();
    if (t < HD) {
        int i = t;
        float m = -INFINITY;
        for (int j = 0; j < HD; j++) m = fmaxf(m, slog[i][j]);
        float ex[HD];
        float sum = 0.f;
        for (int j = 0; j < HD; j++) { ex[j] = expf(slog[i][j] - m); sum += ex[j]; }
        float inv = 1.f / sum;
        float tv = 0.f;
        for (int j = 0; j < HD; j++) {
            float a = ex[j] * inv;
            g_attn[b][pair][h][i][j] = a;
            tv = fmaf(a, bv[h * HD + j], tv);
        }
        g_tvec[b][pair][h * HD + i] = tv;
    }
}

__global__ void cvec_kernel(const float* __restrict__ Wproj) {
    int b = blockIdx.x, p = blockIdx.y, c = threadIdx.x;
    __shared__ float tv[CDIM];
    tv[c] = g_tvec[b][p][c];
    __syncthreads();
    float s = 0.f;
    for (int i = 0; i < CDIM; i++) s = fmaf(Wproj[c * CDIM + i], tv[i], s);
    g_cvec[b][p][c] = s;
}

__global__ void p_kernel(const float* __restrict__ Wv) {
    int vt = blockIdx.x, p = blockIdx.y, b = blockIdx.z;
    int v0 = vt * 32;
    __shared__ float sA[NHEADS][HD][HD];
    __shared__ float sWv[CDIM][32];
    int t = threadIdx.x;
    const float* attnflat = &g_attn[b][p][0][0][0];
    for (int e = t; e < NHEADS * HD * HD; e += 256) (&sA[0][0][0])[e] = attnflat[e];
    for (int e = t; e < CDIM * 32; e += 256) {
        int r = e / 32, vc = e % 32;
        sWv[r][vc] = Wv[r * CDIM + v0 + vc];
    }
    __syncthreads();
    for (int e = t; e < CDIM * 32; e += 256) {
        int c = e / 32, vc = e % 32;
        int h = c / HD, i = c % HD;
        float acc = 0.f;
#pragma unroll
        for (int j = 0; j < HD; j++) acc = fmaf(sA[h][i][j], sWv[h * HD + j][vc], acc);
        g_P[b][p][c][v0 + vc] = acc;
    }
}

// out = M @ X + cvec ; M resident in smem, X double-buffered.
// grid (NTOK/128, 16), 384 threads (12 warps 3x4, warp 64x32)
__global__ __launch_bounds__(384, 1) void out_mma(const float* __restrict__ x1,
                                                  const float* __restrict__ x2,
                                                  float* __restrict__ out) {
    extern __shared__ __align__(16) __nv_bfloat16 smo[];
    __nv_bfloat16* sM = smo;
    __nv_bfloat16* sX = smo + 2 * CDIM * MROW;
    float* scv = (float*)(smo + 2 * CDIM * MROW + 4 * XSTAGE);

    int z = blockIdx.y;
    int b = z >> 1, p = z & 1;
    const float* X = (p ? x1 : x2) + (size_t)b * CDIM * NTOK;
    const __nv_bfloat16* Mh = g_Mh[z];
    const __nv_bfloat16* Ml = g_Ml[z];
    float* O = out + (size_t)p * BATCH * CDIM * NTOK + (size_t)b * CDIM * NTOK;
    int n0 = blockIdx.x * 128;

    int tid = threadIdx.x, lane = tid & 31, wid = tid >> 5;
    int wm = wid >> 2, wn = wid & 3;

    if (tid < CDIM) scv[tid] = g_cvec[b][p][tid];

    for (int u = tid; u < CDIM * CDIM / 8; u += 384) {
        int row = u / 24, col = (u % 24) * 8;
        *(uint4*)(sM + row * MROW + col) = *(const uint4*)(Mh + row * CDIM + col);
        *(uint4*)(sM + CDIM * MROW + row * MROW + col) = *(const uint4*)(Ml + row * CDIM + col);
    }
    for (int u = tid; u < 1024; u += 384) {
        int r = u >> 5, c4 = (u & 31) * 4;
        float4 v = *(const float4*)(X + (size_t)r * NTOK + n0 + c4);
        cvt_store(v, sX + r * OXROW + c4, sX + XSTAGE + r * OXROW + c4);
    }
    __syncthreads();

    uint32_t sM_a = smem_u32(sM);
    uint32_t sX_a = smem_u32(sX);
    const uint32_t MLOFF = CDIM * MROW * 2;
    const uint32_t XLOFF = XSTAGE * 2;

    float acc[4][4][4];
#pragma unroll
    for (int i = 0; i < 4; i++)
#pragma unroll
        for (int j = 0; j < 4; j++)
#pragma unroll
            for (int k = 0; k < 4; k++) acc[i][j][k] = 0.f;

    float4 vx[3];
    for (int ch = 0; ch < 6; ch++) {
        int cur = ch & 1, nxt = cur ^ 1;
        bool pf = (ch < 5);
        if (pf) {
            int kb = (ch + 1) * 32;
#pragma unroll
            for (int it = 0; it < 3; it++) {
                int u = tid + it * 384;
                if (u < 1024) {
                    int r = u >> 5, c4 = (u & 31) * 4;
                    vx[it] = *(const float4*)(X + (size_t)(kb + r) * NTOK + n0 + c4);
                }
            }
        }

        uint32_t xb = sX_a + cur * (2 * XSTAGE * 2);
#pragma unroll
        for (int s = 0; s < 2; s++) {
            int kg = ch * 32 + s * 16;
            uint32_t ah[16], al[16], bx[8];
            int arow0 = wm * 64 + (lane & 15);
            int acol = kg + ((lane >> 4) << 3);
#pragma unroll
            for (int i = 0; i < 4; i++) {
                uint32_t ad = sM_a + (uint32_t)(((arow0 + i * 16) * MROW + acol) * 2);
                ldsm_x4(ah + 4 * i, ad);
                ldsm_x4(al + 4 * i, ad + MLOFF);
            }
            int krow = s * 16 + (lane & 7) + (((lane >> 3) & 1) << 3);
            int ncol0 = wn * 32 + ((lane >> 4) << 3);
#pragma unroll
            for (int jb = 0; jb < 2; jb++)
                ldsm_x4_t(bx + 4 * jb, xb + (uint32_t)((krow * OXROW + ncol0 + jb * 16) * 2));
#pragma unroll
            for (int i = 0; i < 4; i++)
#pragma unroll
                for (int jj = 0; jj < 4; jj++) {
                    const uint32_t* bp = bx + (jj >> 1) * 4 + (jj & 1) * 2;
                    mma16816(acc[i][jj], ah + 4 * i, bp);
                    mma16816(acc[i][jj], al + 4 * i, bp);
                }
#pragma unroll
            for (int jb = 0; jb < 2; jb++)
                ldsm_x4_t(bx + 4 * jb,
                          xb + XLOFF + (uint32_t)((krow * OXROW + ncol0 + jb * 16) * 2));
#pragma unroll
            for (int i = 0; i < 4; i++)
#pragma unroll
                for (int jj = 0; jj < 4; jj++)
                    mma16816(acc[i][jj], ah + 4 * i, bx + (jj >> 1) * 4 + (jj & 1) * 2);
        }

        if (pf) {
            __nv_bfloat16* nb = sX + nxt * 2 * XSTAGE;
#pragma unroll
            for (int it = 0; it < 3; it++) {
                int u = tid + it * 384;
                if (u < 1024) {
                    int r = u >> 5, c4 = (u & 31) * 4;
                    cvt_store(vx[it], nb + r * OXROW + c4, nb + XSTAGE + r * OXROW + c4);
                }
            }
        }
        __syncthreads();
    }

    int r0 = wm * 64 + (lane >> 2);
    int nb = n0 + wn * 32 + (lane & 3) * 2;
#pragma unroll
    for (int i = 0; i < 4; i++) {
        int c = r0 + i * 16;
        float b0 = scv[c], b1 = scv[c + 8];
#pragma unroll
        for (int jj = 0; jj < 4; jj++) {
            float2 v0 = {acc[i][jj][0] + b0, acc[i][jj][1] + b0};
            float2 v1 = {acc[i][jj][2] + b1, acc[i][jj][3] + b1};
            *(float2*)(O + (size_t)c * NTOK + nb + jj * 8) = v0;
            *(float2*)(O + (size_t)(c + 8) * NTOK + nb + jj * 8) = v1;
        }
    }
}

extern "C" void kernel_launch(void* const* d_in, const int* in_sizes, int n_in,
                              void* d_out, int out_size) {
    const float* x1 = (const float*)d_in[0];
    const float* x2 = (const float*)d_in[1];
    const float* q1 = (const float*)d_in[2];
    const float* q2 = (const float*)d_in[3];
    const float* Wq = (const float*)d_in[4];
    const float* bq = (const float*)d_in[5];
    const float* Wk = (const float*)d_in[6];
    const float* bk = (const float*)d_in[7];
    const float* Wv = (const float*)d_in[8];
    const float* bv = (const float*)d_in[9];
    const float* scale = (const float*)d_in[10];
    const float* Wproj = (const float*)d_in[11];
    float* out = (float*)d_out;

    static int configured = 0;
    if (!configured) {
        cudaFuncSetAttribute(gram_mma, cudaFuncAttributeMaxDynamicSharedMemorySize, GRAM_SMEM);
        cudaFuncSetAttribute(out_mma, cudaFuncAttributeMaxDynamicSharedMemorySize, OUT_SMEM);
        configured = 1;
    }

    zero_kernel<<<256, 256>>>();
    gram_mma<<<dim3(GSPLITK, 4, BATCH * 2), 384, GRAM_SMEM>>>(q1, q2, x1, x2);
    smallgemm_nn<<<dim3(6, 6, BATCH * 6), 256>>>(Wq, Wk, Wproj, 0);
    vec_kernel<<<dim3(CDIM, BATCH), 32>>>(Wq, Wk, bq, bk);
    attn_kernel<<<dim3(NHEADS, 2, BATCH), 256>>>(Wk, bq, bk, scale, bv);
    cvec_kernel<<<dim3(BATCH, 2), CDIM>>>(Wproj);
    p_kernel<<<dim3(6, 2, BATCH), 256>>>(Wv);
    smallgemm_nn<<<dim3(6, 6, BATCH * 2), 256>>>(Wq, Wk, Wproj, 1);
    out_mma<<<dim3(NTOK / 128, BATCH * 2), 384, OUT_SMEM>>>(x1, x2, out);
}

// round 7
// speedup vs baseline: 3.3054x; 1.1625x over previous
#include <cuda_runtime.h>
#include <cuda_bf16.h>
#include <cuda_fp16.h>
#include <math.h>
#include <stdint.h>

#define NTOK 16384
#define CDIM 192
#define BATCH 8
#define NHEADS 8
#define HD 24

// gram config (triple-fused, fp16 2-term)
#define GSPLITK 8
#define GSLAB (NTOK / GSPLITK)  // 2048
#define GCH 16                  // k elems per chunk
#define GNCH (GSLAB / GCH)      // 128
#define SROW 24                 // padded smem row stride (fp16 elems)
#define RNG (96 * SROW)         // elems per (arr,hl) plane
#define ARR (2 * RNG)           // per array (hi+lo)
#define STG (4 * ARR)           // per stage (4 arrays)
#define GRAM_SMEM (2 * STG * 2) // bytes (2 stages)

// out config
#define MROW 200
#define OXROW 136
#define XSTAGE (32 * OXROW)
#define OUT_SMEM (2 * CDIM * MROW * 2 + 2 * 2 * XSTAGE * 2 + CDIM * 4)

// -------- scratch --------
__device__ float g_C[BATCH][6][CDIM][CDIM];
__device__ float g_s[BATCH][4][CDIM];  // rowsums: q1, x2, q2, x1
__device__ float g_T[BATCH][6][CDIM][CDIM];
__device__ float g_vec[BATCH][8][CDIM];
__device__ float g_attn[BATCH][2][NHEADS][HD][HD];
__device__ float g_tvec[BATCH][2][CDIM];
__device__ float g_cvec[BATCH][2][CDIM];
__device__ float g_P[BATCH][2][CDIM][CDIM];
__device__ __nv_bfloat16 g_Mh[BATCH * 2][CDIM * CDIM];
__device__ __nv_bfloat16 g_Ml[BATCH * 2][CDIM * CDIM];

// ================= mma helpers (sm_80-portable) =================
__device__ __forceinline__ uint32_t smem_u32(const void* p) {
    uint32_t a;
    asm("{ .reg .u64 t; cvta.to.shared.u64 t, %1; cvt.u32.u64 %0, t; }" : "=r"(a) : "l"(p));
    return a;
}
__device__ __forceinline__ void ldsm_x4(uint32_t* r, uint32_t addr) {
    asm volatile("ldmatrix.sync.aligned.m8n8.x4.shared.b16 {%0,%1,%2,%3}, [%4];"
                 : "=r"(r[0]), "=r"(r[1]), "=r"(r[2]), "=r"(r[3]) : "r"(addr));
}
__device__ __forceinline__ void ldsm_x4_t(uint32_t* r, uint32_t addr) {
    asm volatile("ldmatrix.sync.aligned.m8n8.x4.trans.shared.b16 {%0,%1,%2,%3}, [%4];"
                 : "=r"(r[0]), "=r"(r[1]), "=r"(r[2]), "=r"(r[3]) : "r"(addr));
}
// bf16 mma (used by out_mma)
__device__ __forceinline__ void mma16816(float* d, const uint32_t* a, const uint32_t* b) {
    asm volatile(
        "mma.sync.aligned.m16n8k16.row.col.f32.bf16.bf16.f32 "
        "{%0,%1,%2,%3}, {%4,%5,%6,%7}, {%8,%9}, {%0,%1,%2,%3};"
        : "+f"(d[0]), "+f"(d[1]), "+f"(d[2]), "+f"(d[3])
        : "r"(a[0]), "r"(a[1]), "r"(a[2]), "r"(a[3]), "r"(b[0]), "r"(b[1]));
}
// fp16 mma (used by gram)
__device__ __forceinline__ void mma16816h(float* d, const uint32_t* a, const uint32_t* b) {
    asm volatile(
        "mma.sync.aligned.m16n8k16.row.col.f32.f16.f16.f32 "
        "{%0,%1,%2,%3}, {%4,%5,%6,%7}, {%8,%9}, {%0,%1,%2,%3};"
        : "+f"(d[0]), "+f"(d[1]), "+f"(d[2]), "+f"(d[3])
        : "r"(a[0]), "r"(a[1]), "r"(a[2]), "r"(a[3]), "r"(b[0]), "r"(b[1]));
}
__device__ __forceinline__ void cvt_hl(float v, __nv_bfloat16& h, __nv_bfloat16& l) {
    h = __float2bfloat16(v);
    l = __float2bfloat16(v - __bfloat162float(h));
}
// bf16 packed store (out_mma path)
__device__ __forceinline__ void cvt_store(float4 v, __nv_bfloat16* dh, __nv_bfloat16* dl) {
    __nv_bfloat162 h01 = __floats2bfloat162_rn(v.x, v.y);
    __nv_bfloat162 h23 = __floats2bfloat162_rn(v.z, v.w);
    float2 f01 = __bfloat1622float2(h01);
    float2 f23 = __bfloat1622float2(h23);
    __nv_bfloat162 l01 = __floats2bfloat162_rn(v.x - f01.x, v.y - f01.y);
    __nv_bfloat162 l23 = __floats2bfloat162_rn(v.z - f23.x, v.w - f23.y);
    uint2 uh, ul;
    uh.x = *(uint32_t*)&h01;
    uh.y = *(uint32_t*)&h23;
    ul.x = *(uint32_t*)&l01;
    ul.y = *(uint32_t*)&l23;
    *(uint2*)dh = uh;
    *(uint2*)dl = ul;
}
// fp16 packed store, hi+lo (gram j-side arrays)
__device__ __forceinline__ void cvt_store_h2(float4 v, __half* dh, __half* dl) {
    __half2 h01 = __floats2half2_rn(v.x, v.y);
    __half2 h23 = __floats2half2_rn(v.z, v.w);
    float2 f01 = __half22float2(h01);
    float2 f23 = __half22float2(h23);
    __half2 l01 = __floats2half2_rn(v.x - f01.x, v.y - f01.y);
    __half2 l23 = __floats2half2_rn(v.z - f23.x, v.w - f23.y);
    uint2 uh, ul;
    uh.x = *(uint32_t*)&h01;
    uh.y = *(uint32_t*)&h23;
    ul.x = *(uint32_t*)&l01;
    ul.y = *(uint32_t*)&l23;
    *(uint2*)dh = uh;
    *(uint2*)dl = ul;
}
// fp16 packed store, hi only (gram i-side-only arrays)
__device__ __forceinline__ void cvt_store_h1(float4 v, __half* dh) {
    __half2 h01 = __floats2half2_rn(v.x, v.y);
    __half2 h23 = __floats2half2_rn(v.z, v.w);
    uint2 uh;
    uh.x = *(uint32_t*)&h01;
    uh.y = *(uint32_t*)&h23;
    *(uint2*)dh = uh;
}

// ================= kernels =================
__global__ void zero_kernel() {
    size_t n = sizeof(g_C) / 4;
    float* c = &g_C[0][0][0][0];
    for (size_t i = (size_t)blockIdx.x * blockDim.x + threadIdx.x; i < n;
         i += (size_t)gridDim.x * blockDim.x)
        c[i] = 0.f;
    size_t ns = sizeof(g_s) / 4;
    float* s = &g_s[0][0][0];
    for (size_t i = (size_t)blockIdx.x * blockDim.x + threadIdx.x; i < ns;
         i += (size_t)gridDim.x * blockDim.x)
        s[i] = 0.f;
}

// Triple-fused tensor-core gram, fp16 2-term: C ~= Ah*Bh^T + Ah*Bl^T.
// triple tr: A = (q1|q2), B = (x2|x1); C1 = A@A^T, C2 = A@B^T, C3 = B@B^T
// CTA owns a 96x96 output tile (ti, tj) of each gram for one split-K slab;
// ti>tj tiles of C1/C3 reconstructed by transposed atomics from (tj,ti).
// grid (GSPLITK, 4, BATCH*2), 384 threads (12 warps 2x6, warp 48x16/gram).
__global__ __launch_bounds__(384, 1) void gram_mma(const float* __restrict__ q1,
                                                   const float* __restrict__ q2,
                                                   const float* __restrict__ x1,
                                                   const float* __restrict__ x2) {
    extern __shared__ __align__(16) __half sm[];

    int sk = blockIdx.x;
    int ti = blockIdx.y >> 1, tj = blockIdx.y & 1;
    int b = blockIdx.z >> 1, tr = blockIdx.z & 1;
    const float* A = (tr ? q2 : q1) + (size_t)b * CDIM * NTOK;
    const float* B = (tr ? x1 : x2) + (size_t)b * CDIM * NTOK;
    int slotA = tr ? 2 : 0, slotB = tr ? 3 : 1;
    float* C1 = &g_C[b][tr * 3 + 0][0][0];
    float* C2 = &g_C[b][tr * 3 + 1][0][0];
    float* C3 = &g_C[b][tr * 3 + 2][0][0];
    bool doC1 = (ti <= tj);
    bool trw = (ti < tj);
    bool aliasJ = (ti == tj);
    int arrAj = aliasJ ? 0 : 1;
    int arrBj = aliasJ ? 2 : 3;

    // load list
    const float* lsrc[4];
    int larr[4], lslot[4], lrb[4], nld = 0;
    bool lneed[4];  // need lo plane (array used as j-side operand)
    lsrc[nld] = A + (size_t)ti * 96 * NTOK; larr[nld] = 0;
    lslot[nld] = (tj == 0) ? slotA : -1; lrb[nld] = ti * 96; lneed[nld] = aliasJ; nld++;
    if (doC1 && !aliasJ) {
        lsrc[nld] = A + (size_t)tj * 96 * NTOK; larr[nld] = 1;
        lslot[nld] = -1; lrb[nld] = tj * 96; lneed[nld] = true; nld++;
    }
    if (doC1) {
        lsrc[nld] = B + (size_t)ti * 96 * NTOK; larr[nld] = 2;
        lslot[nld] = (aliasJ && ti == 0) ? slotB : -1; lrb[nld] = ti * 96;
        lneed[nld] = aliasJ; nld++;
    }
    if (!aliasJ) {
        lsrc[nld] = B + (size_t)tj * 96 * NTOK; larr[nld] = 3;
        lslot[nld] = (ti == 0) ? slotB : -1; lrb[nld] = tj * 96; lneed[nld] = true; nld++;
    }

    int tid = threadIdx.x, lane = tid & 31, wid = tid >> 5;
    int wm = wid / 6, wn = wid % 6;  // 2 x 6 warps; warp tile 48 x 16 per gram
    uint32_t smb = smem_u32(sm);

    float accC1[3][2][4] = {}, accC2[3][2][4] = {}, accC3[3][2][4] = {};
    float rs[4] = {0.f, 0.f, 0.f, 0.f};

    int row = tid >> 2, c4 = (tid & 3) * 4;
    int kb0 = sk * GSLAB;

    // prologue: chunk 0 -> stage 0
#pragma unroll
    for (int l = 0; l < 4; l++)
        if (l < nld) {
            float4 v = *(const float4*)(lsrc[l] + (size_t)row * NTOK + kb0 + c4);
            if (lslot[l] >= 0) rs[l] += v.x + v.y + v.z + v.w;
            __half* dp = sm + larr[l] * ARR + row * SROW + c4;
            if (lneed[l]) cvt_store_h2(v, dp, dp + RNG);
            else cvt_store_h1(v, dp);
        }
    __syncthreads();

    float4 va[4];
    for (int ch = 0; ch < GNCH; ch++) {
        int cur = ch & 1, nxt = cur ^ 1;
        bool pf = (ch + 1 < GNCH);
        if (pf) {
            int kb = kb0 + (ch + 1) * GCH;
#pragma unroll
            for (int l = 0; l < 4; l++)
                if (l < nld)
                    va[l] = *(const float4*)(lsrc[l] + (size_t)row * NTOK + kb + c4);
        }

        uint32_t base = smb + cur * (STG * 2);
        int arow = wm * 48 + (lane & 15);
        int acol = (lane >> 4) * 8;
        int brow = wn * 16 + (lane & 7) + (((lane >> 4) & 1) << 3);
        int bcol = ((lane >> 3) & 1) * 8;

        uint32_t aih[12];  // A_i hi only
#pragma unroll
        for (int f = 0; f < 3; f++)
            ldsm_x4(aih + 4 * f, base + (uint32_t)(((arow + f * 16) * SROW + acol) * 2));
        if (doC1) {
            uint32_t ajh[4], ajl[4];
            uint32_t jd = base + (uint32_t)((arrAj * ARR + brow * SROW + bcol) * 2);
            ldsm_x4(ajh, jd);
            ldsm_x4(ajl, jd + RNG * 2);
#pragma unroll
            for (int f = 0; f < 3; f++)
#pragma unroll
                for (int n = 0; n < 2; n++) {
                    mma16816h(accC1[f][n], aih + 4 * f, ajh + 2 * n);
                    mma16816h(accC1[f][n], aih + 4 * f, ajl + 2 * n);
                }
        }
        uint32_t bjh[4], bjl[4];
        {
            uint32_t bd = base + (uint32_t)((arrBj * ARR + brow * SROW + bcol) * 2);
            ldsm_x4(bjh, bd);
            ldsm_x4(bjl, bd + RNG * 2);
        }
#pragma unroll
        for (int f = 0; f < 3; f++)
#pragma unroll
            for (int n = 0; n < 2; n++) {
                mma16816h(accC2[f][n], aih + 4 * f, bjh + 2 * n);
                mma16816h(accC2[f][n], aih + 4 * f, bjl + 2 * n);
            }
        if (doC1) {
            uint32_t bih[12];  // B_i hi only
#pragma unroll
            for (int f = 0; f < 3; f++)
                ldsm_x4(bih + 4 * f,
                        base + (uint32_t)((2 * ARR + (arow + f * 16) * SROW + acol) * 2));
#pragma unroll
            for (int f = 0; f < 3; f++)
#pragma unroll
                for (int n = 0; n < 2; n++) {
                    mma16816h(accC3[f][n], bih + 4 * f, bjh + 2 * n);
                    mma16816h(accC3[f][n], bih + 4 * f, bjl + 2 * n);
                }
        }

        if (pf) {
            uint32_t nb = nxt * STG;
#pragma unroll
            for (int l = 0; l < 4; l++)
                if (l < nld) {
                    if (lslot[l] >= 0) rs[l] += va[l].x + va[l].y + va[l].z + va[l].w;
                    __half* dp = sm + nb + larr[l] * ARR + row * SROW + c4;
                    if (lneed[l]) cvt_store_h2(va[l], dp, dp + RNG);
                    else cvt_store_h1(va[l], dp);
                }
        }
        __syncthreads();
    }

    // epilogue
    int r0g = ti * 96 + wm * 48 + (lane >> 2);
    int c0g = tj * 96 + wn * 16 + (lane & 3) * 2;
#pragma unroll
    for (int f = 0; f < 3; f++)
#pragma unroll
        for (int n = 0; n < 2; n++) {
            int r = r0g + f * 16, c = c0g + n * 8;
            const float* a2 = accC2[f][n];
            atomicAdd(C2 + r * CDIM + c, a2[0]);
            atomicAdd(C2 + r * CDIM + c + 1, a2[1]);
            atomicAdd(C2 + (r + 8) * CDIM + c, a2[2]);
            atomicAdd(C2 + (r + 8) * CDIM + c + 1, a2[3]);
            if (doC1) {
                const float* a1 = accC1[f][n];
                const float* a3 = accC3[f][n];
                atomicAdd(C1 + r * CDIM + c, a1[0]);
                atomicAdd(C1 + r * CDIM + c + 1, a1[1]);
                atomicAdd(C1 + (r + 8) * CDIM + c, a1[2]);
                atomicAdd(C1 + (r + 8) * CDIM + c + 1, a1[3]);
                atomicAdd(C3 + r * CDIM + c, a3[0]);
                atomicAdd(C3 + r * CDIM + c + 1, a3[1]);
                atomicAdd(C3 + (r + 8) * CDIM + c, a3[2]);
                atomicAdd(C3 + (r + 8) * CDIM + c + 1, a3[3]);
                if (trw) {
                    atomicAdd(C1 + c * CDIM + r, a1[0]);
                    atomicAdd(C1 + (c + 1) * CDIM + r, a1[1]);
                    atomicAdd(C1 + c * CDIM + r + 8, a1[2]);
                    atomicAdd(C1 + (c + 1) * CDIM + r + 8, a1[3]);
                    atomicAdd(C3 + c * CDIM + r, a3[0]);
                    atomicAdd(C3 + (c + 1) * CDIM + r, a3[1]);
                    atomicAdd(C3 + c * CDIM + r + 8, a3[2]);
                    atomicAdd(C3 + (c + 1) * CDIM + r + 8, a3[3]);
                }
            }
        }
#pragma unroll
    for (int l = 0; l < 4; l++)
        if (l < nld && lslot[l] >= 0) atomicAdd(&g_s[b][lslot[l]][lrb[l] + row], rs[l]);
}

// -------- small NN GEMMs (192x192x192): D = W @ C --------
__global__ void smallgemm_nn(const float* __restrict__ Wq, const float* __restrict__ Wk,
                             const float* __restrict__ Wproj, int mode) {
    int z = blockIdx.z;
    const float* W; const float* C; float* D = nullptr;
    __nv_bfloat16* Dh = nullptr; __nv_bfloat16* Dl = nullptr;
    if (mode == 0) {
        int b = z / 6, g = z % 6;
        W = (g == 2 || g == 5) ? Wk : Wq;
        C = &g_C[b][g][0][0];
        D = &g_T[b][g][0][0];
    } else {
        int b = z / 2, p = z % 2;
        W = Wproj;
        C = &g_P[b][p][0][0];
        Dh = g_Mh[z];
        Dl = g_Ml[z];
    }
    int m0 = blockIdx.y * 32, j0 = blockIdx.x * 32;
    __shared__ float Ws[32][33];
    __shared__ float Cs[32][33];
    int t = threadIdx.x, tx = t % 16, ty = t / 16;
    float acc[2][2] = {{0.f, 0.f}, {0.f, 0.f}};
    for (int k0 = 0; k0 < CDIM; k0 += 32) {
        __syncthreads();
        for (int e = t; e < 1024; e += 256) {
            int r = e / 32, cc = e % 32;
            Ws[r][cc] = W[(m0 + r) * CDIM + k0 + cc];
            Cs[r][cc] = C[(k0 + r) * CDIM + j0 + cc];
        }
        __syncthreads();
#pragma unroll
        for (int kk = 0; kk < 32; kk++) {
            float w0 = Ws[ty * 2 + 0][kk], w1 = Ws[ty * 2 + 1][kk];
            float c0 = Cs[kk][tx * 2 + 0], c1 = Cs[kk][tx * 2 + 1];
            acc[0][0] = fmaf(w0, c0, acc[0][0]);
            acc[0][1] = fmaf(w0, c1, acc[0][1]);
            acc[1][0] = fmaf(w1, c0, acc[1][0]);
            acc[1][1] = fmaf(w1, c1, acc[1][1]);
        }
    }
    if (mode == 0) {
#pragma unroll
        for (int i = 0; i < 2; i++)
#pragma unroll
            for (int j = 0; j < 2; j++)
                D[(m0 + ty * 2 + i) * CDIM + (j0 + tx * 2 + j)] = acc[i][j];
    } else {
#pragma unroll
        for (int i = 0; i < 2; i++)
#pragma unroll
            for (int j = 0; j < 2; j++) {
                __nv_bfloat16 h, l;
                cvt_hl(acc[i][j], h, l);
                int idx = (m0 + ty * 2 + i) * CDIM + (j0 + tx * 2 + j);
                Dh[idx] = h;
                Dl[idx] = l;
            }
    }
}

// -------- per-batch vectors (warp per (b,c)) --------
__global__ void vec_kernel(const float* __restrict__ Wq, const float* __restrict__ Wk,
                           const float* __restrict__ bq, const float* __restrict__ bk) {
    int c = blockIdx.x, b = blockIdx.y, l = threadIdx.x;
    float a0 = 0, a1 = 0, a2 = 0, a3 = 0, d0 = 0, d2 = 0, d3 = 0, d5 = 0;
    for (int i = l; i < CDIM; i += 32) {
        float wq = Wq[c * CDIM + i], wk = Wk[c * CDIM + i];
        a0 = fmaf(wq, g_s[b][0][i], a0);
        a1 = fmaf(wk, g_s[b][1][i], a1);
        a2 = fmaf(wq, g_s[b][2][i], a2);
        a3 = fmaf(wk, g_s[b][3][i], a3);
        d0 = fmaf(g_T[b][0][c][i], wq, d0);
        d2 = fmaf(g_T[b][2][c][i], wk, d2);
        d3 = fmaf(g_T[b][3][c][i], wq, d3);
        d5 = fmaf(g_T[b][5][c][i], wk, d5);
    }
#pragma unroll
    for (int s = 16; s > 0; s >>= 1) {
        a0 += __shfl_xor_sync(0xffffffff, a0, s);
        a1 += __shfl_xor_sync(0xffffffff, a1, s);
        a2 += __shfl_xor_sync(0xffffffff, a2, s);
        a3 += __shfl_xor_sync(0xffffffff, a3, s);
        d0 += __shfl_xor_sync(0xffffffff, d0, s);
        d2 += __shfl_xor_sync(0xffffffff, d2, s);
        d3 += __shfl_xor_sync(0xffffffff, d3, s);
        d5 += __shfl_xor_sync(0xffffffff, d5, s);
    }
    if (l == 0) {
        float bqc = bq[c], bkc = bk[c];
        const float NN = (float)NTOK;
        g_vec[b][0][c] = a0;
        g_vec[b][1][c] = a1;
        g_vec[b][2][c] = a2;
        g_vec[b][3][c] = a3;
        g_vec[b][4][c] = sqrtf(fmaxf(d0 + 2.f * bqc * a0 + NN * bqc * bqc, 0.f));
        g_vec[b][5][c] = sqrtf(fmaxf(d2 + 2.f * bkc * a1 + NN * bkc * bkc, 0.f));
        g_vec[b][6][c] = sqrtf(fmaxf(d3 + 2.f * bqc * a2 + NN * bqc * bqc, 0.f));
        g_vec[b][7][c] = sqrtf(fmaxf(d5 + 2.f * bkc * a3 + NN * bkc * bkc, 0.f));
    }
}

// -------- logits + softmax --------
__global__ void attn_kernel(const float* __restrict__ Wk, const float* __restrict__ bq,
                            const float* __restrict__ bk, const float* __restrict__ scale,
                            const float* __restrict__ bv) {
    int h = blockIdx.x, pair = blockIdx.y, b = blockIdx.z;
    __shared__ float sTA[HD][CDIM];
    __shared__ float sWk[HD][CDIM];
    __shared__ float slog[HD][HD];
    const float* TA = pair ? &g_T[b][4][0][0] : &g_T[b][1][0][0];
    const float* wqs = pair ? g_vec[b][2] : g_vec[b][0];
    const float* wks = pair ? g_vec[b][3] : g_vec[b][1];
    const float* nq = pair ? g_vec[b][6] : g_vec[b][4];
    const float* nk = pair ? g_vec[b][7] : g_vec[b][5];
    int t = threadIdx.x;
    for (int e = t; e < HD * CDIM; e += 256) {
        int r = e / CDIM, cc = e % CDIM;
        sTA[r][cc] = TA[(h * HD + r) * CDIM + cc];
        sWk[r][cc] = Wk[(h * HD + r) * CDIM + cc];
    }
    __syncthreads();
    float sc = scale[h];
    const float NN = (float)NTOK;
    for (int e = t; e < HD * HD; e += 256) {
        int i = e / HD, j = e % HD;
        int c = h * HD + i, d = h * HD + j;
        float dot = 0.f;
        for (int k = 0; k < CDIM; k++) dot = fmaf(sTA[i][k], sWk[j][k], dot);
        float raw = dot + wqs[c] * bk[d] + bq[c] * wks[d] + NN * bq[c] * bk[d];
        slog[i][j] = raw / (fmaxf(nq[c], 1e-12f) * fmaxf(nk[d], 1e-12f)) * sc;
    }
    __syncthreads();
    if (t < HD) {
        int i = t;
        float m = -INFINITY;
        for (int j = 0; j < HD; j++) m = fmaxf(m, slog[i][j]);
        float ex[HD];
        float sum = 0.f;
        for (int j = 0; j < HD; j++) { ex[j] = expf(slog[i][j] - m); sum += ex[j]; }
        float inv = 1.f / sum;
        float tv = 0.f;
        for (int j = 0; j < HD; j++) {
            float a = ex[j] * inv;
            g_attn[b][pair][h][i][j] = a;
            tv = fmaf(a, bv[h * HD + j], tv);
        }
        g_tvec[b][pair][h * HD + i] = tv;
    }
}

__global__ void cvec_kernel(const float* __restrict__ Wproj) {
    int b = blockIdx.x, p = blockIdx.y, c = threadIdx.x;
    __shared__ float tv[CDIM];
    tv[c] = g_tvec[b][p][c];
    __syncthreads();
    float s = 0.f;
    for (int i = 0; i < CDIM; i++) s = fmaf(Wproj[c * CDIM + i], tv[i], s);
    g_cvec[b][p][c] = s;
}

__global__ void p_kernel(const float* __restrict__ Wv) {
    int vt = blockIdx.x, p = blockIdx.y, b = blockIdx.z;
    int v0 = vt * 32;
    __shared__ float sA[NHEADS][HD][HD];
    __shared__ float sWv[CDIM][32];
    int t = threadIdx.x;
    const float* attnflat = &g_attn[b][p][0][0][0];
    for (int e = t; e < NHEADS * HD * HD; e += 256) (&sA[0][0][0])[e] = attnflat[e];
    for (int e = t; e < CDIM * 32; e += 256) {
        int r = e / 32, vc = e % 32;
        sWv[r][vc] = Wv[r * CDIM + v0 + vc];
    }
    __syncthreads();
    for (int e = t; e < CDIM * 32; e += 256) {
        int c = e / 32, vc = e % 32;
        int h = c / HD, i = c % HD;
        float acc = 0.f;
#pragma unroll
        for (int j = 0; j < HD; j++) acc = fmaf(sA[h][i][j], sWv[h * HD + j][vc], acc);
        g_P[b][p][c][v0 + vc] = acc;
    }
}

// out = M @ X + cvec ; M resident in smem, X double-buffered (bf16 3-term).
// grid (NTOK/128, 16), 384 threads (12 warps 3x4, warp 64x32)
__global__ __launch_bounds__(384, 1) void out_mma(const float* __restrict__ x1,
                                                  const float* __restrict__ x2,
                                                  float* __restrict__ out) {
    extern __shared__ __align__(16) __nv_bfloat16 smo[];
    __nv_bfloat16* sM = smo;
    __nv_bfloat16* sX = smo + 2 * CDIM * MROW;
    float* scv = (float*)(smo + 2 * CDIM * MROW + 4 * XSTAGE);

    int z = blockIdx.y;
    int b = z >> 1, p = z & 1;
    const float* X = (p ? x1 : x2) + (size_t)b * CDIM * NTOK;
    const __nv_bfloat16* Mh = g_Mh[z];
    const __nv_bfloat16* Ml = g_Ml[z];
    float* O = out + (size_t)p * BATCH * CDIM * NTOK + (size_t)b * CDIM * NTOK;
    int n0 = blockIdx.x * 128;

    int tid = threadIdx.x, lane = tid & 31, wid = tid >> 5;
    int wm = wid >> 2, wn = wid & 3;

    if (tid < CDIM) scv[tid] = g_cvec[b][p][tid];

    for (int u = tid; u < CDIM * CDIM / 8; u += 384) {
        int row = u / 24, col = (u % 24) * 8;
        *(uint4*)(sM + row * MROW + col) = *(const uint4*)(Mh + row * CDIM + col);
        *(uint4*)(sM + CDIM * MROW + row * MROW + col) = *(const uint4*)(Ml + row * CDIM + col);
    }
    for (int u = tid; u < 1024; u += 384) {
        int r = u >> 5, c4 = (u & 31) * 4;
        float4 v = *(const float4*)(X + (size_t)r * NTOK + n0 + c4);
        cvt_store(v, sX + r * OXROW + c4, sX + XSTAGE + r * OXROW + c4);
    }
    __syncthreads();

    uint32_t sM_a = smem_u32(sM);
    uint32_t sX_a = smem_u32(sX);
    const uint32_t MLOFF = CDIM * MROW * 2;
    const uint32_t XLOFF = XSTAGE * 2;

    float acc[4][4][4];
#pragma unroll
    for (int i = 0; i < 4; i++)
#pragma unroll
        for (int j = 0; j < 4; j++)
#pragma unroll
            for (int k = 0; k < 4; k++) acc[i][j][k] = 0.f;

    float4 vx[3];
    for (int ch = 0; ch < 6; ch++) {
        int cur = ch & 1, nxt = cur ^ 1;
        bool pf = (ch < 5);
        if (pf) {
            int kb = (ch + 1) * 32;
#pragma unroll
            for (int it = 0; it < 3; it++) {
                int u = tid + it * 384;
                if (u < 1024) {
                    int r = u >> 5, c4 = (u & 31) * 4;
                    vx[it] = *(const float4*)(X + (size_t)(kb + r) * NTOK + n0 + c4);
                }
            }
        }

        uint32_t xb = sX_a + cur * (2 * XSTAGE * 2);
#pragma unroll
        for (int s = 0; s < 2; s++) {
            int kg = ch * 32 + s * 16;
            uint32_t ah[16], al[16], bx[8];
            int arow0 = wm * 64 + (lane & 15);
            int acol = kg + ((lane >> 4) << 3);
#pragma unroll
            for (int i = 0; i < 4; i++) {
                uint32_t ad = sM_a + (uint32_t)(((arow0 + i * 16) * MROW + acol) * 2);
                ldsm_x4(ah + 4 * i, ad);
                ldsm_x4(al + 4 * i, ad + MLOFF);
            }
            int krow = s * 16 + (lane & 7) + (((lane >> 3) & 1) << 3);
            int ncol0 = wn * 32 + ((lane >> 4) << 3);
#pragma unroll
            for (int jb = 0; jb < 2; jb++)
                ldsm_x4_t(bx + 4 * jb, xb + (uint32_t)((krow * OXROW + ncol0 + jb * 16) * 2));
#pragma unroll
            for (int i = 0; i < 4; i++)
#pragma unroll
                for (int jj = 0; jj < 4; jj++) {
                    const uint32_t* bp = bx + (jj >> 1) * 4 + (jj & 1) * 2;
                    mma16816(acc[i][jj], ah + 4 * i, bp);
                    mma16816(acc[i][jj], al + 4 * i, bp);
                }
#pragma unroll
            for (int jb = 0; jb < 2; jb++)
                ldsm_x4_t(bx + 4 * jb,
                          xb + XLOFF + (uint32_t)((krow * OXROW + ncol0 + jb * 16) * 2));
#pragma unroll
            for (int i = 0; i < 4; i++)
#pragma unroll
                for (int jj = 0; jj < 4; jj++)
                    mma16816(acc[i][jj], ah + 4 * i, bx + (jj >> 1) * 4 + (jj & 1) * 2);
        }

        if (pf) {
            __nv_bfloat16* nb = sX + nxt * 2 * XSTAGE;
#pragma unroll
            for (int it = 0; it < 3; it++) {
                int u = tid + it * 384;
                if (u < 1024) {
                    int r = u >> 5, c4 = (u & 31) * 4;
                    cvt_store(vx[it], nb + r * OXROW + c4, nb + XSTAGE + r * OXROW + c4);
                }
            }
        }
        __syncthreads();
    }

    int r0 = wm * 64 + (lane >> 2);
    int nb = n0 + wn * 32 + (lane & 3) * 2;
#pragma unroll
    for (int i = 0; i < 4; i++) {
        int c = r0 + i * 16;
        float b0 = scv[c], b1 = scv[c + 8];
#pragma unroll
        for (int jj = 0; jj < 4; jj++) {
            float2 v0 = {acc[i][jj][0] + b0, acc[i][jj][1] + b0};
            float2 v1 = {acc[i][jj][2] + b1, acc[i][jj][3] + b1};
            *(float2*)(O + (size_t)c * NTOK + nb + jj * 8) = v0;
            *(float2*)(O + (size_t)(c + 8) * NTOK + nb + jj * 8) = v1;
        }
    }
}

extern "C" void kernel_launch(void* const* d_in, const int* in_sizes, int n_in,
                              void* d_out, int out_size) {
    const float* x1 = (const float*)d_in[0];
    const float* x2 = (const float*)d_in[1];
    const float* q1 = (const float*)d_in[2];
    const float* q2 = (const float*)d_in[3];
    const float* Wq = (const float*)d_in[4];
    const float* bq = (const float*)d_in[5];
    const float* Wk = (const float*)d_in[6];
    const float* bk = (const float*)d_in[7];
    const float* Wv = (const float*)d_in[8];
    const float* bv = (const float*)d_in[9];
    const float* scale = (const float*)d_in[10];
    const float* Wproj = (const float*)d_in[11];
    float* out = (float*)d_out;

    static int configured = 0;
    if (!configured) {
        cudaFuncSetAttribute(gram_mma, cudaFuncAttributeMaxDynamicSharedMemorySize, GRAM_SMEM);
        cudaFuncSetAttribute(out_mma, cudaFuncAttributeMaxDynamicSharedMemorySize, OUT_SMEM);
        configured = 1;
    }

    zero_kernel<<<256, 256>>>();
    gram_mma<<<dim3(GSPLITK, 4, BATCH * 2), 384, GRAM_SMEM>>>(q1, q2, x1, x2);
    smallgemm_nn<<<dim3(6, 6, BATCH * 6), 256>>>(Wq, Wk, Wproj, 0);
    vec_kernel<<<dim3(CDIM, BATCH), 32>>>(Wq, Wk, bq, bk);
    attn_kernel<<<dim3(NHEADS, 2, BATCH), 256>>>(Wk, bq, bk, scale, bv);
    cvec_kernel<<<dim3(BATCH, 2), CDIM>>>(Wproj);
    p_kernel<<<dim3(6, 2, BATCH), 256>>>(Wv);
    smallgemm_nn<<<dim3(6, 6, BATCH * 2), 256>>>(Wq, Wk, Wproj, 1);
    out_mma<<<dim3(NTOK / 128, BATCH * 2), 384, OUT_SMEM>>>(x1, x2, out);
}

// round 8
// speedup vs baseline: 3.6315x; 1.0987x over previous
#include <cuda_runtime.h>
#include <cuda_bf16.h>
#include <cuda_fp16.h>
#include <math.h>
#include <stdint.h>

#define NTOK 16384
#define CDIM 192
#define BATCH 8
#define NHEADS 8
#define HD 24

// gram config (triple-fused, fp16 single-term)
#define GSPLITK 8
#define GSLAB (NTOK / GSPLITK)  // 2048
#define GCH 16                  // k elems per chunk
#define GNCH (GSLAB / GCH)      // 128
#define SROW 24                 // padded smem row stride (fp16 elems)
#define RNG (96 * SROW)         // elems per plane (hi only now)
#define STG (4 * RNG)           // per stage (4 planes)
#define GRAM_SMEM (2 * STG * 2) // bytes (2 stages)

// out config
#define MROW 200
#define OXROW 136
#define XSTAGE (32 * OXROW)
#define OUT_SMEM (2 * CDIM * MROW * 2 + 2 * 2 * XSTAGE * 2 + CDIM * 4)

// -------- scratch --------
__device__ float g_C[BATCH][6][CDIM][CDIM];
__device__ float g_s[BATCH][4][CDIM];  // rowsums: q1, x2, q2, x1
__device__ float g_T[BATCH][6][CDIM][CDIM];
__device__ float g_vec[BATCH][8][CDIM];
__device__ float g_attn[BATCH][2][NHEADS][HD][HD];
__device__ float g_tvec[BATCH][2][CDIM];
__device__ float g_cvec[BATCH][2][CDIM];
__device__ float g_P[BATCH][2][CDIM][CDIM];
__device__ __nv_bfloat16 g_Mh[BATCH * 2][CDIM * CDIM];
__device__ __nv_bfloat16 g_Ml[BATCH * 2][CDIM * CDIM];

// ================= mma helpers (sm_80-portable) =================
__device__ __forceinline__ uint32_t smem_u32(const void* p) {
    uint32_t a;
    asm("{ .reg .u64 t; cvta.to.shared.u64 t, %1; cvt.u32.u64 %0, t; }" : "=r"(a) : "l"(p));
    return a;
}
__device__ __forceinline__ void ldsm_x4(uint32_t* r, uint32_t addr) {
    asm volatile("ldmatrix.sync.aligned.m8n8.x4.shared.b16 {%0,%1,%2,%3}, [%4];"
                 : "=r"(r[0]), "=r"(r[1]), "=r"(r[2]), "=r"(r[3]) : "r"(addr));
}
__device__ __forceinline__ void ldsm_x4_t(uint32_t* r, uint32_t addr) {
    asm volatile("ldmatrix.sync.aligned.m8n8.x4.trans.shared.b16 {%0,%1,%2,%3}, [%4];"
                 : "=r"(r[0]), "=r"(r[1]), "=r"(r[2]), "=r"(r[3]) : "r"(addr));
}
// bf16 mma (used by out_mma)
__device__ __forceinline__ void mma16816(float* d, const uint32_t* a, const uint32_t* b) {
    asm volatile(
        "mma.sync.aligned.m16n8k16.row.col.f32.bf16.bf16.f32 "
        "{%0,%1,%2,%3}, {%4,%5,%6,%7}, {%8,%9}, {%0,%1,%2,%3};"
        : "+f"(d[0]), "+f"(d[1]), "+f"(d[2]), "+f"(d[3])
        : "r"(a[0]), "r"(a[1]), "r"(a[2]), "r"(a[3]), "r"(b[0]), "r"(b[1]));
}
// fp16 mma (used by gram)
__device__ __forceinline__ void mma16816h(float* d, const uint32_t* a, const uint32_t* b) {
    asm volatile(
        "mma.sync.aligned.m16n8k16.row.col.f32.f16.f16.f32 "
        "{%0,%1,%2,%3}, {%4,%5,%6,%7}, {%8,%9}, {%0,%1,%2,%3};"
        : "+f"(d[0]), "+f"(d[1]), "+f"(d[2]), "+f"(d[3])
        : "r"(a[0]), "r"(a[1]), "r"(a[2]), "r"(a[3]), "r"(b[0]), "r"(b[1]));
}
__device__ __forceinline__ void cvt_hl(float v, __nv_bfloat16& h, __nv_bfloat16& l) {
    h = __float2bfloat16(v);
    l = __float2bfloat16(v - __bfloat162float(h));
}
// bf16 packed store (out_mma path)
__device__ __forceinline__ void cvt_store(float4 v, __nv_bfloat16* dh, __nv_bfloat16* dl) {
    __nv_bfloat162 h01 = __floats2bfloat162_rn(v.x, v.y);
    __nv_bfloat162 h23 = __floats2bfloat162_rn(v.z, v.w);
    float2 f01 = __bfloat1622float2(h01);
    float2 f23 = __bfloat1622float2(h23);
    __nv_bfloat162 l01 = __floats2bfloat162_rn(v.x - f01.x, v.y - f01.y);
    __nv_bfloat162 l23 = __floats2bfloat162_rn(v.z - f23.x, v.w - f23.y);
    uint2 uh, ul;
    uh.x = *(uint32_t*)&h01;
    uh.y = *(uint32_t*)&h23;
    ul.x = *(uint32_t*)&l01;
    ul.y = *(uint32_t*)&l23;
    *(uint2*)dh = uh;
    *(uint2*)dl = ul;
}
// fp16 packed store, hi only (gram)
__device__ __forceinline__ void cvt_store_h1(float4 v, __half* dh) {
    __half2 h01 = __floats2half2_rn(v.x, v.y);
    __half2 h23 = __floats2half2_rn(v.z, v.w);
    uint2 uh;
    uh.x = *(uint32_t*)&h01;
    uh.y = *(uint32_t*)&h23;
    *(uint2*)dh = uh;
}

// ================= kernels =================
__global__ void zero_kernel() {
    size_t n = sizeof(g_C) / 4;
    float* c = &g_C[0][0][0][0];
    for (size_t i = (size_t)blockIdx.x * blockDim.x + threadIdx.x; i < n;
         i += (size_t)gridDim.x * blockDim.x)
        c[i] = 0.f;
    size_t ns = sizeof(g_s) / 4;
    float* s = &g_s[0][0][0];
    for (size_t i = (size_t)blockIdx.x * blockDim.x + threadIdx.x; i < ns;
         i += (size_t)gridDim.x * blockDim.x)
        s[i] = 0.f;
}

// Triple-fused tensor-core gram, fp16 single-term: C ~= Ah*Bh^T.
// triple tr: A = (q1|q2), B = (x2|x1); C1 = A@A^T, C2 = A@B^T, C3 = B@B^T
// CTA owns a 96x96 output tile (ti, tj) of each gram for one split-K slab;
// ti>tj tiles of C1/C3 reconstructed by transposed atomics from (tj,ti).
// grid (GSPLITK, 4, BATCH*2), 384 threads (12 warps 2x6, warp 48x16/gram).
__global__ __launch_bounds__(384, 1) void gram_mma(const float* __restrict__ q1,
                                                   const float* __restrict__ q2,
                                                   const float* __restrict__ x1,
                                                   const float* __restrict__ x2) {
    extern __shared__ __align__(16) __half sm[];

    int sk = blockIdx.x;
    int ti = blockIdx.y >> 1, tj = blockIdx.y & 1;
    int b = blockIdx.z >> 1, tr = blockIdx.z & 1;
    const float* A = (tr ? q2 : q1) + (size_t)b * CDIM * NTOK;
    const float* B = (tr ? x1 : x2) + (size_t)b * CDIM * NTOK;
    int slotA = tr ? 2 : 0, slotB = tr ? 3 : 1;
    float* C1 = &g_C[b][tr * 3 + 0][0][0];
    float* C2 = &g_C[b][tr * 3 + 1][0][0];
    float* C3 = &g_C[b][tr * 3 + 2][0][0];
    bool doC1 = (ti <= tj);
    bool trw = (ti < tj);
    bool aliasJ = (ti == tj);
    int arrAj = aliasJ ? 0 : 1;
    int arrBj = aliasJ ? 2 : 3;

    // load list
    const float* lsrc[4];
    int larr[4], lslot[4], lrb[4], nld = 0;
    lsrc[nld] = A + (size_t)ti * 96 * NTOK; larr[nld] = 0;
    lslot[nld] = (tj == 0) ? slotA : -1; lrb[nld] = ti * 96; nld++;
    if (doC1 && !aliasJ) {
        lsrc[nld] = A + (size_t)tj * 96 * NTOK; larr[nld] = 1;
        lslot[nld] = -1; lrb[nld] = tj * 96; nld++;
    }
    if (doC1) {
        lsrc[nld] = B + (size_t)ti * 96 * NTOK; larr[nld] = 2;
        lslot[nld] = (aliasJ && ti == 0) ? slotB : -1; lrb[nld] = ti * 96; nld++;
    }
    if (!aliasJ) {
        lsrc[nld] = B + (size_t)tj * 96 * NTOK; larr[nld] = 3;
        lslot[nld] = (ti == 0) ? slotB : -1; lrb[nld] = tj * 96; nld++;
    }

    int tid = threadIdx.x, lane = tid & 31, wid = tid >> 5;
    int wm = wid / 6, wn = wid % 6;  // 2 x 6 warps; warp tile 48 x 16 per gram
    uint32_t smb = smem_u32(sm);

    float accC1[3][2][4] = {}, accC2[3][2][4] = {}, accC3[3][2][4] = {};
    float rs[4] = {0.f, 0.f, 0.f, 0.f};

    int row = tid >> 2, c4 = (tid & 3) * 4;
    int kb0 = sk * GSLAB;

    // prologue: chunk 0 -> stage 0
#pragma unroll
    for (int l = 0; l < 4; l++)
        if (l < nld) {
            float4 v = *(const float4*)(lsrc[l] + (size_t)row * NTOK + kb0 + c4);
            if (lslot[l] >= 0) rs[l] += v.x + v.y + v.z + v.w;
            cvt_store_h1(v, sm + larr[l] * RNG + row * SROW + c4);
        }
    __syncthreads();

    float4 va[4];
    for (int ch = 0; ch < GNCH; ch++) {
        int cur = ch & 1, nxt = cur ^ 1;
        bool pf = (ch + 1 < GNCH);
        if (pf) {
            int kb = kb0 + (ch + 1) * GCH;
#pragma unroll
            for (int l = 0; l < 4; l++)
                if (l < nld)
                    va[l] = *(const float4*)(lsrc[l] + (size_t)row * NTOK + kb + c4);
        }

        uint32_t base = smb + cur * (STG * 2);
        int arow = wm * 48 + (lane & 15);
        int acol = (lane >> 4) * 8;
        int brow = wn * 16 + (lane & 7) + (((lane >> 4) & 1) << 3);
        int bcol = ((lane >> 3) & 1) * 8;

        uint32_t aih[12];
#pragma unroll
        for (int f = 0; f < 3; f++)
            ldsm_x4(aih + 4 * f, base + (uint32_t)(((arow + f * 16) * SROW + acol) * 2));
        uint32_t bjh[4];
        ldsm_x4(bjh, base + (uint32_t)((arrBj * RNG + brow * SROW + bcol) * 2));
        if (doC1) {
            uint32_t ajh[4];
            ldsm_x4(ajh, base + (uint32_t)((arrAj * RNG + brow * SROW + bcol) * 2));
#pragma unroll
            for (int f = 0; f < 3; f++)
#pragma unroll
                for (int n = 0; n < 2; n++)
                    mma16816h(accC1[f][n], aih + 4 * f, ajh + 2 * n);
        }
#pragma unroll
        for (int f = 0; f < 3; f++)
#pragma unroll
            for (int n = 0; n < 2; n++)
                mma16816h(accC2[f][n], aih + 4 * f, bjh + 2 * n);
        if (doC1) {
            uint32_t bih[12];
#pragma unroll
            for (int f = 0; f < 3; f++)
                ldsm_x4(bih + 4 * f,
                        base + (uint32_t)((2 * RNG + (arow + f * 16) * SROW + acol) * 2));
#pragma unroll
            for (int f = 0; f < 3; f++)
#pragma unroll
                for (int n = 0; n < 2; n++)
                    mma16816h(accC3[f][n], bih + 4 * f, bjh + 2 * n);
        }

        if (pf) {
            uint32_t nb = nxt * STG;
#pragma unroll
            for (int l = 0; l < 4; l++)
                if (l < nld) {
                    if (lslot[l] >= 0) rs[l] += va[l].x + va[l].y + va[l].z + va[l].w;
                    cvt_store_h1(va[l], sm + nb + larr[l] * RNG + row * SROW + c4);
                }
        }
        __syncthreads();
    }

    // epilogue
    int r0g = ti * 96 + wm * 48 + (lane >> 2);
    int c0g = tj * 96 + wn * 16 + (lane & 3) * 2;
#pragma unroll
    for (int f = 0; f < 3; f++)
#pragma unroll
        for (int n = 0; n < 2; n++) {
            int r = r0g + f * 16, c = c0g + n * 8;
            const float* a2 = accC2[f][n];
            atomicAdd(C2 + r * CDIM + c, a2[0]);
            atomicAdd(C2 + r * CDIM + c + 1, a2[1]);
            atomicAdd(C2 + (r + 8) * CDIM + c, a2[2]);
            atomicAdd(C2 + (r + 8) * CDIM + c + 1, a2[3]);
            if (doC1) {
                const float* a1 = accC1[f][n];
                const float* a3 = accC3[f][n];
                atomicAdd(C1 + r * CDIM + c, a1[0]);
                atomicAdd(C1 + r * CDIM + c + 1, a1[1]);
                atomicAdd(C1 + (r + 8) * CDIM + c, a1[2]);
                atomicAdd(C1 + (r + 8) * CDIM + c + 1, a1[3]);
                atomicAdd(C3 + r * CDIM + c, a3[0]);
                atomicAdd(C3 + r * CDIM + c + 1, a3[1]);
                atomicAdd(C3 + (r + 8) * CDIM + c, a3[2]);
                atomicAdd(C3 + (r + 8) * CDIM + c + 1, a3[3]);
                if (trw) {
                    atomicAdd(C1 + c * CDIM + r, a1[0]);
                    atomicAdd(C1 + (c + 1) * CDIM + r, a1[1]);
                    atomicAdd(C1 + c * CDIM + r + 8, a1[2]);
                    atomicAdd(C1 + (c + 1) * CDIM + r + 8, a1[3]);
                    atomicAdd(C3 + c * CDIM + r, a3[0]);
                    atomicAdd(C3 + (c + 1) * CDIM + r, a3[1]);
                    atomicAdd(C3 + c * CDIM + r + 8, a3[2]);
                    atomicAdd(C3 + (c + 1) * CDIM + r + 8, a3[3]);
                }
            }
        }
#pragma unroll
    for (int l = 0; l < 4; l++)
        if (l < nld && lslot[l] >= 0) atomicAdd(&g_s[b][lslot[l]][lrb[l] + row], rs[l]);
}

// -------- small NN GEMMs (192x192x192): D = W @ C --------
__global__ void smallgemm_nn(const float* __restrict__ Wq, const float* __restrict__ Wk,
                             const float* __restrict__ Wproj, int mode) {
    int z = blockIdx.z;
    const float* W; const float* C; float* D = nullptr;
    __nv_bfloat16* Dh = nullptr; __nv_bfloat16* Dl = nullptr;
    if (mode == 0) {
        int b = z / 6, g = z % 6;
        W = (g == 2 || g == 5) ? Wk : Wq;
        C = &g_C[b][g][0][0];
        D = &g_T[b][g][0][0];
    } else {
        int b = z / 2, p = z % 2;
        W = Wproj;
        C = &g_P[b][p][0][0];
        Dh = g_Mh[z];
        Dl = g_Ml[z];
    }
    int m0 = blockIdx.y * 32, j0 = blockIdx.x * 32;
    __shared__ float Ws[32][33];
    __shared__ float Cs[32][33];
    int t = threadIdx.x, tx = t % 16, ty = t / 16;
    float acc[2][2] = {{0.f, 0.f}, {0.f, 0.f}};
    for (int k0 = 0; k0 < CDIM; k0 += 32) {
        __syncthreads();
        for (int e = t; e < 1024; e += 256) {
            int r = e / 32, cc = e % 32;
            Ws[r][cc] = W[(m0 + r) * CDIM + k0 + cc];
            Cs[r][cc] = C[(k0 + r) * CDIM + j0 + cc];
        }
        __syncthreads();
#pragma unroll
        for (int kk = 0; kk < 32; kk++) {
            float w0 = Ws[ty * 2 + 0][kk], w1 = Ws[ty * 2 + 1][kk];
            float c0 = Cs[kk][tx * 2 + 0], c1 = Cs[kk][tx * 2 + 1];
            acc[0][0] = fmaf(w0, c0, acc[0][0]);
            acc[0][1] = fmaf(w0, c1, acc[0][1]);
            acc[1][0] = fmaf(w1, c0, acc[1][0]);
            acc[1][1] = fmaf(w1, c1, acc[1][1]);
        }
    }
    if (mode == 0) {
#pragma unroll
        for (int i = 0; i < 2; i++)
#pragma unroll
            for (int j = 0; j < 2; j++)
                D[(m0 + ty * 2 + i) * CDIM + (j0 + tx * 2 + j)] = acc[i][j];
    } else {
#pragma unroll
        for (int i = 0; i < 2; i++)
#pragma unroll
            for (int j = 0; j < 2; j++) {
                __nv_bfloat16 h, l;
                cvt_hl(acc[i][j], h, l);
                int idx = (m0 + ty * 2 + i) * CDIM + (j0 + tx * 2 + j);
                Dh[idx] = h;
                Dl[idx] = l;
            }
    }
}

// -------- per-batch vectors (warp per (b,c)) --------
__global__ void vec_kernel(const float* __restrict__ Wq, const float* __restrict__ Wk,
                           const float* __restrict__ bq, const float* __restrict__ bk) {
    int c = blockIdx.x, b = blockIdx.y, l = threadIdx.x;
    float a0 = 0, a1 = 0, a2 = 0, a3 = 0, d0 = 0, d2 = 0, d3 = 0, d5 = 0;
    for (int i = l; i < CDIM; i += 32) {
        float wq = Wq[c * CDIM + i], wk = Wk[c * CDIM + i];
        a0 = fmaf(wq, g_s[b][0][i], a0);
        a1 = fmaf(wk, g_s[b][1][i], a1);
        a2 = fmaf(wq, g_s[b][2][i], a2);
        a3 = fmaf(wk, g_s[b][3][i], a3);
        d0 = fmaf(g_T[b][0][c][i], wq, d0);
        d2 = fmaf(g_T[b][2][c][i], wk, d2);
        d3 = fmaf(g_T[b][3][c][i], wq, d3);
        d5 = fmaf(g_T[b][5][c][i], wk, d5);
    }
#pragma unroll
    for (int s = 16; s > 0; s >>= 1) {
        a0 += __shfl_xor_sync(0xffffffff, a0, s);
        a1 += __shfl_xor_sync(0xffffffff, a1, s);
        a2 += __shfl_xor_sync(0xffffffff, a2, s);
        a3 += __shfl_xor_sync(0xffffffff, a3, s);
        d0 += __shfl_xor_sync(0xffffffff, d0, s);
        d2 += __shfl_xor_sync(0xffffffff, d2, s);
        d3 += __shfl_xor_sync(0xffffffff, d3, s);
        d5 += __shfl_xor_sync(0xffffffff, d5, s);
    }
    if (l == 0) {
        float bqc = bq[c], bkc = bk[c];
        const float NN = (float)NTOK;
        g_vec[b][0][c] = a0;
        g_vec[b][1][c] = a1;
        g_vec[b][2][c] = a2;
        g_vec[b][3][c] = a3;
        g_vec[b][4][c] = sqrtf(fmaxf(d0 + 2.f * bqc * a0 + NN * bqc * bqc, 0.f));
        g_vec[b][5][c] = sqrtf(fmaxf(d2 + 2.f * bkc * a1 + NN * bkc * bkc, 0.f));
        g_vec[b][6][c] = sqrtf(fmaxf(d3 + 2.f * bqc * a2 + NN * bqc * bqc, 0.f));
        g_vec[b][7][c] = sqrtf(fmaxf(d5 + 2.f * bkc * a3 + NN * bkc * bkc, 0.f));
    }
}

// -------- logits + softmax --------
__global__ void attn_kernel(const float* __restrict__ Wk, const float* __restrict__ bq,
                            const float* __restrict__ bk, const float* __restrict__ scale,
                            const float* __restrict__ bv) {
    int h = blockIdx.x, pair = blockIdx.y, b = blockIdx.z;
    __shared__ float sTA[HD][CDIM];
    __shared__ float sWk[HD][CDIM];
    __shared__ float slog[HD][HD];
    const float* TA = pair ? &g_T[b][4][0][0] : &g_T[b][1][0][0];
    const float* wqs = pair ? g_vec[b][2] : g_vec[b][0];
    const float* wks = pair ? g_vec[b][3] : g_vec[b][1];
    const float* nq = pair ? g_vec[b][6] : g_vec[b][4];
    const float* nk = pair ? g_vec[b][7] : g_vec[b][5];
    int t = threadIdx.x;
    for (int e = t; e < HD * CDIM; e += 256) {
        int r = e / CDIM, cc = e % CDIM;
        sTA[r][cc] = TA[(h * HD + r) * CDIM + cc];
        sWk[r][cc] = Wk[(h * HD + r) * CDIM + cc];
    }
    __syncthreads();
    float sc = scale[h];
    const float NN = (float)NTOK;
    for (int e = t; e < HD * HD; e += 256) {
        int i = e / HD, j = e % HD;
        int c = h * HD + i, d = h * HD + j;
        float dot = 0.f;
        for (int k = 0; k < CDIM; k++) dot = fmaf(sTA[i][k], sWk[j][k], dot);
        float raw = dot + wqs[c] * bk[d] + bq[c] * wks[d] + NN * bq[c] * bk[d];
        slog[i][j] = raw / (fmaxf(nq[c], 1e-12f) * fmaxf(nk[d], 1e-12f)) * sc;
    }
    __syncthreads();
    if (t < HD) {
        int i = t;
        float m = -INFINITY;
        for (int j = 0; j < HD; j++) m = fmaxf(m, slog[i][j]);
        float ex[HD];
        float sum = 0.f;
        for (int j = 0; j < HD; j++) { ex[j] = expf(slog[i][j] - m); sum += ex[j]; }
        float inv = 1.f / sum;
        float tv = 0.f;
        for (int j = 0; j < HD; j++) {
            float a = ex[j] * inv;
            g_attn[b][pair][h][i][j] = a;
            tv = fmaf(a, bv[h * HD + j], tv);
        }
        g_tvec[b][pair][h * HD + i] = tv;
    }
}

__global__ void cvec_kernel(const float* __restrict__ Wproj) {
    int b = blockIdx.x, p = blockIdx.y, c = threadIdx.x;
    __shared__ float tv[CDIM];
    tv[c] = g_tvec[b][p][c];
    __syncthreads();
    float s = 0.f;
    for (int i = 0; i < CDIM; i++) s = fmaf(Wproj[c * CDIM + i], tv[i], s);
    g_cvec[b][p][c] = s;
}

__global__ void p_kernel(const float* __restrict__ Wv) {
    int vt = blockIdx.x, p = blockIdx.y, b = blockIdx.z;
    int v0 = vt * 32;
    __shared__ float sA[NHEADS][HD][HD];
    __shared__ float sWv[CDIM][32];
    int t = threadIdx.x;
    const float* attnflat = &g_attn[b][p][0][0][0];
    for (int e = t; e < NHEADS * HD * HD; e += 256) (&sA[0][0][0])[e] = attnflat[e];
    for (int e = t; e < CDIM * 32; e += 256) {
        int r = e / 32, vc = e % 32;
        sWv[r][vc] = Wv[r * CDIM + v0 + vc];
    }
    __syncthreads();
    for (int e = t; e < CDIM * 32; e += 256) {
        int c = e / 32, vc = e % 32;
        int h = c / HD, i = c % HD;
        float acc = 0.f;
#pragma unroll
        for (int j = 0; j < HD; j++) acc = fmaf(sA[h][i][j], sWv[h * HD + j][vc], acc);
        g_P[b][p][c][v0 + vc] = acc;
    }
}

// out = M @ X + cvec ; M resident in smem, X double-buffered (bf16 3-term).
// grid (NTOK/128, 16), 384 threads (12 warps 3x4, warp 64x32)
__global__ __launch_bounds__(384, 1) void out_mma(const float* __restrict__ x1,
                                                  const float* __restrict__ x2,
                                                  float* __restrict__ out) {
    extern __shared__ __align__(16) __nv_bfloat16 smo[];
    __nv_bfloat16* sM = smo;
    __nv_bfloat16* sX = smo + 2 * CDIM * MROW;
    float* scv = (float*)(smo + 2 * CDIM * MROW + 4 * XSTAGE);

    int z = blockIdx.y;
    int b = z >> 1, p = z & 1;
    const float* X = (p ? x1 : x2) + (size_t)b * CDIM * NTOK;
    const __nv_bfloat16* Mh = g_Mh[z];
    const __nv_bfloat16* Ml = g_Ml[z];
    float* O = out + (size_t)p * BATCH * CDIM * NTOK + (size_t)b * CDIM * NTOK;
    int n0 = blockIdx.x * 128;

    int tid = threadIdx.x, lane = tid & 31, wid = tid >> 5;
    int wm = wid >> 2, wn = wid & 3;

    if (tid < CDIM) scv[tid] = g_cvec[b][p][tid];

    for (int u = tid; u < CDIM * CDIM / 8; u += 384) {
        int row = u / 24, col = (u % 24) * 8;
        *(uint4*)(sM + row * MROW + col) = *(const uint4*)(Mh + row * CDIM + col);
        *(uint4*)(sM + CDIM * MROW + row * MROW + col) = *(const uint4*)(Ml + row * CDIM + col);
    }
    for (int u = tid; u < 1024; u += 384) {
        int r = u >> 5, c4 = (u & 31) * 4;
        float4 v = *(const float4*)(X + (size_t)r * NTOK + n0 + c4);
        cvt_store(v, sX + r * OXROW + c4, sX + XSTAGE + r * OXROW + c4);
    }
    __syncthreads();

    uint32_t sM_a = smem_u32(sM);
    uint32_t sX_a = smem_u32(sX);
    const uint32_t MLOFF = CDIM * MROW * 2;
    const uint32_t XLOFF = XSTAGE * 2;

    float acc[4][4][4];
#pragma unroll
    for (int i = 0; i < 4; i++)
#pragma unroll
        for (int j = 0; j < 4; j++)
#pragma unroll
            for (int k = 0; k < 4; k++) acc[i][j][k] = 0.f;

    float4 vx[3];
    for (int ch = 0; ch < 6; ch++) {
        int cur = ch & 1, nxt = cur ^ 1;
        bool pf = (ch < 5);
        if (pf) {
            int kb = (ch + 1) * 32;
#pragma unroll
            for (int it = 0; it < 3; it++) {
                int u = tid + it * 384;
                if (u < 1024) {
                    int r = u >> 5, c4 = (u & 31) * 4;
                    vx[it] = *(const float4*)(X + (size_t)(kb + r) * NTOK + n0 + c4);
                }
            }
        }

        uint32_t xb = sX_a + cur * (2 * XSTAGE * 2);
#pragma unroll
        for (int s = 0; s < 2; s++) {
            int kg = ch * 32 + s * 16;
            uint32_t ah[16], al[16], bx[8];
            int arow0 = wm * 64 + (lane & 15);
            int acol = kg + ((lane >> 4) << 3);
#pragma unroll
            for (int i = 0; i < 4; i++) {
                uint32_t ad = sM_a + (uint32_t)(((arow0 + i * 16) * MROW + acol) * 2);
                ldsm_x4(ah + 4 * i, ad);
                ldsm_x4(al + 4 * i, ad + MLOFF);
            }
            int krow = s * 16 + (lane & 7) + (((lane >> 3) & 1) << 3);
            int ncol0 = wn * 32 + ((lane >> 4) << 3);
#pragma unroll
            for (int jb = 0; jb < 2; jb++)
                ldsm_x4_t(bx + 4 * jb, xb + (uint32_t)((krow * OXROW + ncol0 + jb * 16) * 2));
#pragma unroll
            for (int i = 0; i < 4; i++)
#pragma unroll
                for (int jj = 0; jj < 4; jj++) {
                    const uint32_t* bp = bx + (jj >> 1) * 4 + (jj & 1) * 2;
                    mma16816(acc[i][jj], ah + 4 * i, bp);
                    mma16816(acc[i][jj], al + 4 * i, bp);
                }
#pragma unroll
            for (int jb = 0; jb < 2; jb++)
                ldsm_x4_t(bx + 4 * jb,
                          xb + XLOFF + (uint32_t)((krow * OXROW + ncol0 + jb * 16) * 2));
#pragma unroll
            for (int i = 0; i < 4; i++)
#pragma unroll
                for (int jj = 0; jj < 4; jj++)
                    mma16816(acc[i][jj], ah + 4 * i, bx + (jj >> 1) * 4 + (jj & 1) * 2);
        }

        if (pf) {
            __nv_bfloat16* nb = sX + nxt * 2 * XSTAGE;
#pragma unroll
            for (int it = 0; it < 3; it++) {
                int u = tid + it * 384;
                if (u < 1024) {
                    int r = u >> 5, c4 = (u & 31) * 4;
                    cvt_store(vx[it], nb + r * OXROW + c4, nb + XSTAGE + r * OXROW + c4);
                }
            }
        }
        __syncthreads();
    }

    int r0 = wm * 64 + (lane >> 2);
    int nb = n0 + wn * 32 + (lane & 3) * 2;
#pragma unroll
    for (int i = 0; i < 4; i++) {
        int c = r0 + i * 16;
        float b0 = scv[c], b1 = scv[c + 8];
#pragma unroll
        for (int jj = 0; jj < 4; jj++) {
            float2 v0 = {acc[i][jj][0] + b0, acc[i][jj][1] + b0};
            float2 v1 = {acc[i][jj][2] + b1, acc[i][jj][3] + b1};
            *(float2*)(O + (size_t)c * NTOK + nb + jj * 8) = v0;
            *(float2*)(O + (size_t)(c + 8) * NTOK + nb + jj * 8) = v1;
        }
    }
}

extern "C" void kernel_launch(void* const* d_in, const int* in_sizes, int n_in,
                              void* d_out, int out_size) {
    const float* x1 = (const float*)d_in[0];
    const float* x2 = (const float*)d_in[1];
    const float* q1 = (const float*)d_in[2];
    const float* q2 = (const float*)d_in[3];
    const float* Wq = (const float*)d_in[4];
    const float* bq = (const float*)d_in[5];
    const float* Wk = (const float*)d_in[6];
    const float* bk = (const float*)d_in[7];
    const float* Wv = (const float*)d_in[8];
    const float* bv = (const float*)d_in[9];
    const float* scale = (const float*)d_in[10];
    const float* Wproj = (const float*)d_in[11];
    float* out = (float*)d_out;

    static int configured = 0;
    if (!configured) {
        cudaFuncSetAttribute(gram_mma, cudaFuncAttributeMaxDynamicSharedMemorySize, GRAM_SMEM);
        cudaFuncSetAttribute(out_mma, cudaFuncAttributeMaxDynamicSharedMemorySize, OUT_SMEM);
        configured = 1;
    }

    zero_kernel<<<256, 256>>>();
    gram_mma<<<dim3(GSPLITK, 4, BATCH * 2), 384, GRAM_SMEM>>>(q1, q2, x1, x2);
    smallgemm_nn<<<dim3(6, 6, BATCH * 6), 256>>>(Wq, Wk, Wproj, 0);
    vec_kernel<<<dim3(CDIM, BATCH), 32>>>(Wq, Wk, bq, bk);
    attn_kernel<<<dim3(NHEADS, 2, BATCH), 256>>>(Wk, bq, bk, scale, bv);
    cvec_kernel<<<dim3(BATCH, 2), CDIM>>>(Wproj);
    p_kernel<<<dim3(6, 2, BATCH), 256>>>(Wv);
    smallgemm_nn<<<dim3(6, 6, BATCH * 2), 256>>>(Wq, Wk, Wproj, 1);
    out_mma<<<dim3(NTOK / 128, BATCH * 2), 384, OUT_SMEM>>>(x1, x2, out);
}

// round 9
// speedup vs baseline: 4.3404x; 1.1952x over previous
#include <cuda_runtime.h>
#include <cuda_bf16.h>
#include <cuda_fp16.h>
#include <math.h>
#include <stdint.h>

#define NTOK 16384
#define CDIM 192
#define BATCH 8
#define NHEADS 8
#define HD 24

// gram config (triple-fused, fp16 single-term, merged (1,0), GCH=32)
#define GSPLITK 8
#define GSLAB (NTOK / GSPLITK)  // 2048
#define GCH 32                  // k elems per chunk
#define GNCH (GSLAB / GCH)      // 64
#define SROW 40                 // padded smem row stride (fp16 elems)
#define RNG (96 * SROW)         // elems per plane
#define STG (4 * RNG)           // per stage (4 planes)
#define GRAM_SMEM (2 * STG * 2) // bytes (2 stages) = 61440

// out config
#define MROW 200
#define OXROW 136
#define XSTAGE (32 * OXROW)
#define OUT_SMEM (2 * CDIM * MROW * 2 + 2 * 2 * XSTAGE * 2 + CDIM * 4)

// -------- scratch --------
__device__ float g_C[BATCH][6][CDIM][CDIM];
__device__ float g_s[BATCH][4][CDIM];  // rowsums: q1, x2, q2, x1
__device__ float g_T[BATCH][6][CDIM][CDIM];
__device__ float g_vec[BATCH][8][CDIM];
__device__ float g_attn[BATCH][2][NHEADS][HD][HD];
__device__ float g_tvec[BATCH][2][CDIM];
__device__ float g_cvec[BATCH][2][CDIM];
__device__ float g_P[BATCH][2][CDIM][CDIM];
__device__ __nv_bfloat16 g_Mh[BATCH * 2][CDIM * CDIM];
__device__ __nv_bfloat16 g_Ml[BATCH * 2][CDIM * CDIM];

// ================= mma helpers (sm_80-portable) =================
__device__ __forceinline__ uint32_t smem_u32(const void* p) {
    uint32_t a;
    asm("{ .reg .u64 t; cvta.to.shared.u64 t, %1; cvt.u32.u64 %0, t; }" : "=r"(a) : "l"(p));
    return a;
}
__device__ __forceinline__ void ldsm_x4(uint32_t* r, uint32_t addr) {
    asm volatile("ldmatrix.sync.aligned.m8n8.x4.shared.b16 {%0,%1,%2,%3}, [%4];"
                 : "=r"(r[0]), "=r"(r[1]), "=r"(r[2]), "=r"(r[3]) : "r"(addr));
}
__device__ __forceinline__ void ldsm_x4_t(uint32_t* r, uint32_t addr) {
    asm volatile("ldmatrix.sync.aligned.m8n8.x4.trans.shared.b16 {%0,%1,%2,%3}, [%4];"
                 : "=r"(r[0]), "=r"(r[1]), "=r"(r[2]), "=r"(r[3]) : "r"(addr));
}
// bf16 mma (out_mma)
__device__ __forceinline__ void mma16816(float* d, const uint32_t* a, const uint32_t* b) {
    asm volatile(
        "mma.sync.aligned.m16n8k16.row.col.f32.bf16.bf16.f32 "
        "{%0,%1,%2,%3}, {%4,%5,%6,%7}, {%8,%9}, {%0,%1,%2,%3};"
        : "+f"(d[0]), "+f"(d[1]), "+f"(d[2]), "+f"(d[3])
        : "r"(a[0]), "r"(a[1]), "r"(a[2]), "r"(a[3]), "r"(b[0]), "r"(b[1]));
}
// fp16 mma (gram)
__device__ __forceinline__ void mma16816h(float* d, const uint32_t* a, const uint32_t* b) {
    asm volatile(
        "mma.sync.aligned.m16n8k16.row.col.f32.f16.f16.f32 "
        "{%0,%1,%2,%3}, {%4,%5,%6,%7}, {%8,%9}, {%0,%1,%2,%3};"
        : "+f"(d[0]), "+f"(d[1]), "+f"(d[2]), "+f"(d[3])
        : "r"(a[0]), "r"(a[1]), "r"(a[2]), "r"(a[3]), "r"(b[0]), "r"(b[1]));
}
__device__ __forceinline__ void cvt_hl(float v, __nv_bfloat16& h, __nv_bfloat16& l) {
    h = __float2bfloat16(v);
    l = __float2bfloat16(v - __bfloat162float(h));
}
// bf16 packed store (out_mma path)
__device__ __forceinline__ void cvt_store(float4 v, __nv_bfloat16* dh, __nv_bfloat16* dl) {
    __nv_bfloat162 h01 = __floats2bfloat162_rn(v.x, v.y);
    __nv_bfloat162 h23 = __floats2bfloat162_rn(v.z, v.w);
    float2 f01 = __bfloat1622float2(h01);
    float2 f23 = __bfloat1622float2(h23);
    __nv_bfloat162 l01 = __floats2bfloat162_rn(v.x - f01.x, v.y - f01.y);
    __nv_bfloat162 l23 = __floats2bfloat162_rn(v.z - f23.x, v.w - f23.y);
    uint2 uh, ul;
    uh.x = *(uint32_t*)&h01;
    uh.y = *(uint32_t*)&h23;
    ul.x = *(uint32_t*)&l01;
    ul.y = *(uint32_t*)&l23;
    *(uint2*)dh = uh;
    *(uint2*)dl = ul;
}
// fp16 packed store, hi only (gram)
__device__ __forceinline__ void cvt_store_h1(float4 v, __half* dh) {
    __half2 h01 = __floats2half2_rn(v.x, v.y);
    __half2 h23 = __floats2half2_rn(v.z, v.w);
    uint2 uh;
    uh.x = *(uint32_t*)&h01;
    uh.y = *(uint32_t*)&h23;
    *(uint2*)dh = uh;
}
__device__ __forceinline__ void atom4(float* C, int r, int c, const float* a) {
    atomicAdd(C + r * CDIM + c, a[0]);
    atomicAdd(C + r * CDIM + c + 1, a[1]);
    atomicAdd(C + (r + 8) * CDIM + c, a[2]);
    atomicAdd(C + (r + 8) * CDIM + c + 1, a[3]);
}
__device__ __forceinline__ void atom4t(float* C, int r, int c, const float* a) {
    atomicAdd(C + c * CDIM + r, a[0]);
    atomicAdd(C + (c + 1) * CDIM + r, a[1]);
    atomicAdd(C + c * CDIM + r + 8, a[2]);
    atomicAdd(C + (c + 1) * CDIM + r + 8, a[3]);
}

// ================= kernels =================
__global__ void zero_kernel() {
    size_t n = sizeof(g_C) / 4;
    float* c = &g_C[0][0][0][0];
    for (size_t i = (size_t)blockIdx.x * blockDim.x + threadIdx.x; i < n;
         i += (size_t)gridDim.x * blockDim.x)
        c[i] = 0.f;
    size_t ns = sizeof(g_s) / 4;
    float* s = &g_s[0][0][0];
    for (size_t i = (size_t)blockIdx.x * blockDim.x + threadIdx.x; i < ns;
         i += (size_t)gridDim.x * blockDim.x)
        s[i] = 0.f;
}

// Triple-fused fp16 single-term gram with merged off-diagonal tile.
// triple tr: A=(q1|q2), B=(x2|x1); C1=A@A^T, C2=A@B^T, C3=B@B^T
// cls 0: tile (0,0) of C1/C2/C3.  cls 2: tile (1,1).
// cls 1: tile (0,1) of C1/C2/C3 (+ transposed C1/C3) AND tile (1,0) of C2.
// grid (GSPLITK, 3, BATCH*2), 384 threads (12 warps 2x6, warp 48x16/gram).
__global__ __launch_bounds__(384, 1) void gram_mma(const float* __restrict__ q1,
                                                   const float* __restrict__ q2,
                                                   const float* __restrict__ x1,
                                                   const float* __restrict__ x2) {
    extern __shared__ __align__(16) __half sm[];

    int sk = blockIdx.x, cls = blockIdx.y;
    int b = blockIdx.z >> 1, tr = blockIdx.z & 1;
    const float* A = (tr ? q2 : q1) + (size_t)b * CDIM * NTOK;
    const float* B = (tr ? x1 : x2) + (size_t)b * CDIM * NTOK;
    int slotA = tr ? 2 : 0, slotB = tr ? 3 : 1;
    float* C1 = &g_C[b][tr * 3 + 0][0][0];
    float* C2 = &g_C[b][tr * 3 + 1][0][0];
    float* C3 = &g_C[b][tr * 3 + 2][0][0];

    const float* lsrc[4];
    int larr[4], lslot[4], lrb[4], nld;
    if (cls == 1) {
        nld = 4;
        lsrc[0] = A; larr[0] = 0; lslot[0] = -1; lrb[0] = 0;
        lsrc[1] = A + (size_t)96 * NTOK; larr[1] = 1; lslot[1] = slotA; lrb[1] = 96;
        lsrc[2] = B; larr[2] = 2; lslot[2] = -1; lrb[2] = 0;
        lsrc[3] = B + (size_t)96 * NTOK; larr[3] = 3; lslot[3] = slotB; lrb[3] = 96;
    } else {
        nld = 2;
        size_t off = (cls == 2) ? (size_t)96 * NTOK : 0;
        lsrc[0] = A + off; larr[0] = 0; lslot[0] = (cls == 0) ? slotA : -1; lrb[0] = 0;
        lsrc[1] = B + off; larr[1] = 2; lslot[1] = (cls == 0) ? slotB : -1; lrb[1] = 0;
        lsrc[2] = lsrc[0]; larr[2] = 0; lslot[2] = -1; lrb[2] = 0;
        lsrc[3] = lsrc[0]; larr[3] = 0; lslot[3] = -1; lrb[3] = 0;
    }
    int jarr1 = (cls == 1) ? 1 : 0;  // C1 j-side plane
    int jarr3 = (cls == 1) ? 3 : 2;  // C2/C3 j-side plane
    bool merged = (cls == 1);

    int tid = threadIdx.x, lane = tid & 31, wid = tid >> 5;
    int wm = wid / 6, wn = wid % 6;  // 2 x 6 warps; warp tile 48 x 16 per gram
    uint32_t smb = smem_u32(sm);

    float accC1[3][2][4] = {}, accC2[3][2][4] = {}, accC3[3][2][4] = {}, accC2b[3][2][4] = {};
    float rs[4] = {0.f, 0.f, 0.f, 0.f};

    int row = tid >> 2, c8 = (tid & 3) * 8;
    int kb0 = sk * GSLAB;

    // prologue: chunk 0 -> stage 0
#pragma unroll
    for (int l = 0; l < 4; l++)
        if (l < nld) {
            const float* sp = lsrc[l] + (size_t)row * NTOK + kb0 + c8;
            float4 v0 = *(const float4*)sp;
            float4 v1 = *(const float4*)(sp + 4);
            if (lslot[l] >= 0)
                rs[l] += v0.x + v0.y + v0.z + v0.w + v1.x + v1.y + v1.z + v1.w;
            __half* dp = sm + larr[l] * RNG + row * SROW + c8;
            cvt_store_h1(v0, dp);
            cvt_store_h1(v1, dp + 4);
        }
    __syncthreads();

    float4 va[8];
    for (int ch = 0; ch < GNCH; ch++) {
        int cur = ch & 1, nxt = cur ^ 1;
        bool pf = (ch + 1 < GNCH);
        if (pf) {
            int kb = kb0 + (ch + 1) * GCH;
#pragma unroll
            for (int l = 0; l < 4; l++)
                if (l < nld) {
                    const float* sp = lsrc[l] + (size_t)row * NTOK + kb + c8;
                    va[2 * l] = *(const float4*)sp;
                    va[2 * l + 1] = *(const float4*)(sp + 4);
                }
        }

        uint32_t base = smb + cur * (STG * 2);
        int arow = wm * 48 + (lane & 15);
        int brow = wn * 16 + (lane & 7) + (((lane >> 4) & 1) << 3);
#pragma unroll
        for (int s = 0; s < 2; s++) {
            int acol = s * 16 + ((lane >> 4) << 3);
            int bcol = s * 16 + (((lane >> 3) & 1) << 3);

            uint32_t aih[12];
#pragma unroll
            for (int f = 0; f < 3; f++)
                ldsm_x4(aih + 4 * f, base + (uint32_t)(((arow + f * 16) * SROW + acol) * 2));
            uint32_t j1[4];
            ldsm_x4(j1, base + (uint32_t)((jarr1 * RNG + brow * SROW + bcol) * 2));
#pragma unroll
            for (int f = 0; f < 3; f++)
#pragma unroll
                for (int n = 0; n < 2; n++)
                    mma16816h(accC1[f][n], aih + 4 * f, j1 + 2 * n);
            uint32_t j3[4];
            ldsm_x4(j3, base + (uint32_t)((jarr3 * RNG + brow * SROW + bcol) * 2));
#pragma unroll
            for (int f = 0; f < 3; f++)
#pragma unroll
                for (int n = 0; n < 2; n++)
                    mma16816h(accC2[f][n], aih + 4 * f, j3 + 2 * n);
            uint32_t bih[12];
#pragma unroll
            for (int f = 0; f < 3; f++)
                ldsm_x4(bih + 4 * f,
                        base + (uint32_t)((2 * RNG + (arow + f * 16) * SROW + acol) * 2));
#pragma unroll
            for (int f = 0; f < 3; f++)
#pragma unroll
                for (int n = 0; n < 2; n++)
                    mma16816h(accC3[f][n], bih + 4 * f, j3 + 2 * n);
            if (merged) {
                uint32_t ai2[12], j2[4];
#pragma unroll
                for (int f = 0; f < 3; f++)
                    ldsm_x4(ai2 + 4 * f,
                            base + (uint32_t)((RNG + (arow + f * 16) * SROW + acol) * 2));
                ldsm_x4(j2, base + (uint32_t)((2 * RNG + brow * SROW + bcol) * 2));
#pragma unroll
                for (int f = 0; f < 3; f++)
#pragma unroll
                    for (int n = 0; n < 2; n++)
                        mma16816h(accC2b[f][n], ai2 + 4 * f, j2 + 2 * n);
            }
        }

        if (pf) {
            uint32_t nb = nxt * STG;
#pragma unroll
            for (int l = 0; l < 4; l++)
                if (l < nld) {
                    float4 v0 = va[2 * l], v1 = va[2 * l + 1];
                    if (lslot[l] >= 0)
                        rs[l] += v0.x + v0.y + v0.z + v0.w + v1.x + v1.y + v1.z + v1.w;
                    __half* dp = sm + nb + larr[l] * RNG + row * SROW + c8;
                    cvt_store_h1(v0, dp);
                    cvt_store_h1(v1, dp + 4);
                }
        }
        __syncthreads();
    }

    // epilogue
    int ti = (cls == 2) ? 1 : 0;
    int tj = (cls == 0) ? 0 : 1;
    int rw = wm * 48 + (lane >> 2);
    int cw = wn * 16 + (lane & 3) * 2;
#pragma unroll
    for (int f = 0; f < 3; f++)
#pragma unroll
        for (int n = 0; n < 2; n++) {
            int r = ti * 96 + rw + f * 16, c = tj * 96 + cw + n * 8;
            atom4(C1, r, c, accC1[f][n]);
            atom4(C2, r, c, accC2[f][n]);
            atom4(C3, r, c, accC3[f][n]);
            if (merged) {
                atom4t(C1, r, c, accC1[f][n]);
                atom4t(C3, r, c, accC3[f][n]);
                atom4(C2, 96 + rw + f * 16, cw + n * 8, accC2b[f][n]);
            }
        }
#pragma unroll
    for (int l = 0; l < 4; l++)
        if (l < nld && lslot[l] >= 0) atomicAdd(&g_s[b][lslot[l]][lrb[l] + row], rs[l]);
}

// -------- small NN GEMMs (192x192x192): D = W @ C --------
__global__ void smallgemm_nn(const float* __restrict__ Wq, const float* __restrict__ Wk,
                             const float* __restrict__ Wproj, int mode) {
    int z = blockIdx.z;
    const float* W; const float* C; float* D = nullptr;
    __nv_bfloat16* Dh = nullptr; __nv_bfloat16* Dl = nullptr;
    if (mode == 0) {
        int b = z / 6, g = z % 6;
        W = (g == 2 || g == 5) ? Wk : Wq;
        C = &g_C[b][g][0][0];
        D = &g_T[b][g][0][0];
    } else {
        int b = z / 2, p = z % 2;
        W = Wproj;
        C = &g_P[b][p][0][0];
        Dh = g_Mh[z];
        Dl = g_Ml[z];
    }
    int m0 = blockIdx.y * 32, j0 = blockIdx.x * 32;
    __shared__ float Ws[32][33];
    __shared__ float Cs[32][33];
    int t = threadIdx.x, tx = t % 16, ty = t / 16;
    float acc[2][2] = {{0.f, 0.f}, {0.f, 0.f}};
    for (int k0 = 0; k0 < CDIM; k0 += 32) {
        __syncthreads();
        for (int e = t; e < 1024; e += 256) {
            int r = e / 32, cc = e % 32;
            Ws[r][cc] = W[(m0 + r) * CDIM + k0 + cc];
            Cs[r][cc] = C[(k0 + r) * CDIM + j0 + cc];
        }
        __syncthreads();
#pragma unroll
        for (int kk = 0; kk < 32; kk++) {
            float w0 = Ws[ty * 2 + 0][kk], w1 = Ws[ty * 2 + 1][kk];
            float c0 = Cs[kk][tx * 2 + 0], c1 = Cs[kk][tx * 2 + 1];
            acc[0][0] = fmaf(w0, c0, acc[0][0]);
            acc[0][1] = fmaf(w0, c1, acc[0][1]);
            acc[1][0] = fmaf(w1, c0, acc[1][0]);
            acc[1][1] = fmaf(w1, c1, acc[1][1]);
        }
    }
    if (mode == 0) {
#pragma unroll
        for (int i = 0; i < 2; i++)
#pragma unroll
            for (int j = 0; j < 2; j++)
                D[(m0 + ty * 2 + i) * CDIM + (j0 + tx * 2 + j)] = acc[i][j];
    } else {
#pragma unroll
        for (int i = 0; i < 2; i++)
#pragma unroll
            for (int j = 0; j < 2; j++) {
                __nv_bfloat16 h, l;
                cvt_hl(acc[i][j], h, l);
                int idx = (m0 + ty * 2 + i) * CDIM + (j0 + tx * 2 + j);
                Dh[idx] = h;
                Dl[idx] = l;
            }
    }
}

// -------- per-batch vectors (warp per (b,c)) --------
__global__ void vec_kernel(const float* __restrict__ Wq, const float* __restrict__ Wk,
                           const float* __restrict__ bq, const float* __restrict__ bk) {
    int c = blockIdx.x, b = blockIdx.y, l = threadIdx.x;
    float a0 = 0, a1 = 0, a2 = 0, a3 = 0, d0 = 0, d2 = 0, d3 = 0, d5 = 0;
    for (int i = l; i < CDIM; i += 32) {
        float wq = Wq[c * CDIM + i], wk = Wk[c * CDIM + i];
        a0 = fmaf(wq, g_s[b][0][i], a0);
        a1 = fmaf(wk, g_s[b][1][i], a1);
        a2 = fmaf(wq, g_s[b][2][i], a2);
        a3 = fmaf(wk, g_s[b][3][i], a3);
        d0 = fmaf(g_T[b][0][c][i], wq, d0);
        d2 = fmaf(g_T[b][2][c][i], wk, d2);
        d3 = fmaf(g_T[b][3][c][i], wq, d3);
        d5 = fmaf(g_T[b][5][c][i], wk, d5);
    }
#pragma unroll
    for (int s = 16; s > 0; s >>= 1) {
        a0 += __shfl_xor_sync(0xffffffff, a0, s);
        a1 += __shfl_xor_sync(0xffffffff, a1, s);
        a2 += __shfl_xor_sync(0xffffffff, a2, s);
        a3 += __shfl_xor_sync(0xffffffff, a3, s);
        d0 += __shfl_xor_sync(0xffffffff, d0, s);
        d2 += __shfl_xor_sync(0xffffffff, d2, s);
        d3 += __shfl_xor_sync(0xffffffff, d3, s);
        d5 += __shfl_xor_sync(0xffffffff, d5, s);
    }
    if (l == 0) {
        float bqc = bq[c], bkc = bk[c];
        const float NN = (float)NTOK;
        g_vec[b][0][c] = a0;
        g_vec[b][1][c] = a1;
        g_vec[b][2][c] = a2;
        g_vec[b][3][c] = a3;
        g_vec[b][4][c] = sqrtf(fmaxf(d0 + 2.f * bqc * a0 + NN * bqc * bqc, 0.f));
        g_vec[b][5][c] = sqrtf(fmaxf(d2 + 2.f * bkc * a1 + NN * bkc * bkc, 0.f));
        g_vec[b][6][c] = sqrtf(fmaxf(d3 + 2.f * bqc * a2 + NN * bqc * bqc, 0.f));
        g_vec[b][7][c] = sqrtf(fmaxf(d5 + 2.f * bkc * a3 + NN * bkc * bkc, 0.f));
    }
}

// -------- logits + softmax --------
__global__ void attn_kernel(const float* __restrict__ Wk, const float* __restrict__ bq,
                            const float* __restrict__ bk, const float* __restrict__ scale,
                            const float* __restrict__ bv) {
    int h = blockIdx.x, pair = blockIdx.y, b = blockIdx.z;
    __shared__ float sTA[HD][CDIM];
    __shared__ float sWk[HD][CDIM];
    __shared__ float slog[HD][HD];
    const float* TA = pair ? &g_T[b][4][0][0] : &g_T[b][1][0][0];
    const float* wqs = pair ? g_vec[b][2] : g_vec[b][0];
    const float* wks = pair ? g_vec[b][3] : g_vec[b][1];
    const float* nq = pair ? g_vec[b][6] : g_vec[b][4];
    const float* nk = pair ? g_vec[b][7] : g_vec[b][5];
    int t = threadIdx.x;
    for (int e = t; e < HD * CDIM; e += 256) {
        int r = e / CDIM, cc = e % CDIM;
        sTA[r][cc] = TA[(h * HD + r) * CDIM + cc];
        sWk[r][cc] = Wk[(h * HD + r) * CDIM + cc];
    }
    __syncthreads();
    float sc = scale[h];
    const float NN = (float)NTOK;
    for (int e = t; e < HD * HD; e += 256) {
        int i = e / HD, j = e % HD;
        int c = h * HD + i, d = h * HD + j;
        float dot = 0.f;
        for (int k = 0; k < CDIM; k++) dot = fmaf(sTA[i][k], sWk[j][k], dot);
        float raw = dot + wqs[c] * bk[d] + bq[c] * wks[d] + NN * bq[c] * bk[d];
        slog[i][j] = raw / (fmaxf(nq[c], 1e-12f) * fmaxf(nk[d], 1e-12f)) * sc;
    }
    __syncthreads();
    if (t < HD) {
        int i = t;
        float m = -INFINITY;
        for (int j = 0; j < HD; j++) m = fmaxf(m, slog[i][j]);
        float ex[HD];
        float sum = 0.f;
        for (int j = 0; j < HD; j++) { ex[j] = expf(slog[i][j] - m); sum += ex[j]; }
        float inv = 1.f / sum;
        float tv = 0.f;
        for (int j = 0; j < HD; j++) {
            float a = ex[j] * inv;
            g_attn[b][pair][h][i][j] = a;
            tv = fmaf(a, bv[h * HD + j], tv);
        }
        g_tvec[b][pair][h * HD + i] = tv;
    }
}

__global__ void cvec_kernel(const float* __restrict__ Wproj) {
    int b = blockIdx.x, p = blockIdx.y, c = threadIdx.x;
    __shared__ float tv[CDIM];
    tv[c] = g_tvec[b][p][c];
    __syncthreads();
    float s = 0.f;
    for (int i = 0; i < CDIM; i++) s = fmaf(Wproj[c * CDIM + i], tv[i], s);
    g_cvec[b][p][c] = s;
}

__global__ void p_kernel(const float* __restrict__ Wv) {
    int vt = blockIdx.x, p = blockIdx.y, b = blockIdx.z;
    int v0 = vt * 32;
    __shared__ float sA[NHEADS][HD][HD];
    __shared__ float sWv[CDIM][32];
    int t = threadIdx.x;
    const float* attnflat = &g_attn[b][p][0][0][0];
    for (int e = t; e < NHEADS * HD * HD; e += 256) (&sA[0][0][0])[e] = attnflat[e];
    for (int e = t; e < CDIM * 32; e += 256) {
        int r = e / 32, vc = e % 32;
        sWv[r][vc] = Wv[r * CDIM + v0 + vc];
    }
    __syncthreads();
    for (int e = t; e < CDIM * 32; e += 256) {
        int c = e / 32, vc = e % 32;
        int h = c / HD, i = c % HD;
        float acc = 0.f;
#pragma unroll
        for (int j = 0; j < HD; j++) acc = fmaf(sA[h][i][j], sWv[h * HD + j][vc], acc);
        g_P[b][p][c][v0 + vc] = acc;
    }
}

// out = M @ X + cvec ; M resident in smem, X double-buffered (bf16 3-term).
__global__ __launch_bounds__(384, 1) void out_mma(const float* __restrict__ x1,
                                                  const float* __restrict__ x2,
                                                  float* __restrict__ out) {
    extern __shared__ __align__(16) __nv_bfloat16 smo[];
    __nv_bfloat16* sM = smo;
    __nv_bfloat16* sX = smo + 2 * CDIM * MROW;
    float* scv = (float*)(smo + 2 * CDIM * MROW + 4 * XSTAGE);

    int z = blockIdx.y;
    int b = z >> 1, p = z & 1;
    const float* X = (p ? x1 : x2) + (size_t)b * CDIM * NTOK;
    const __nv_bfloat16* Mh = g_Mh[z];
    const __nv_bfloat16* Ml = g_Ml[z];
    float* O = out + (size_t)p * BATCH * CDIM * NTOK + (size_t)b * CDIM * NTOK;
    int n0 = blockIdx.x * 128;

    int tid = threadIdx.x, lane = tid & 31, wid = tid >> 5;
    int wm = wid >> 2, wn = wid & 3;

    if (tid < CDIM) scv[tid] = g_cvec[b][p][tid];

    for (int u = tid; u < CDIM * CDIM / 8; u += 384) {
        int row = u / 24, col = (u % 24) * 8;
        *(uint4*)(sM + row * MROW + col) = *(const uint4*)(Mh + row * CDIM + col);
        *(uint4*)(sM + CDIM * MROW + row * MROW + col) = *(const uint4*)(Ml + row * CDIM + col);
    }
    for (int u = tid; u < 1024; u += 384) {
        int r = u >> 5, c4 = (u & 31) * 4;
        float4 v = *(const float4*)(X + (size_t)r * NTOK + n0 + c4);
        cvt_store(v, sX + r * OXROW + c4, sX + XSTAGE + r * OXROW + c4);
    }
    __syncthreads();

    uint32_t sM_a = smem_u32(sM);
    uint32_t sX_a = smem_u32(sX);
    const uint32_t MLOFF = CDIM * MROW * 2;
    const uint32_t XLOFF = XSTAGE * 2;

    float acc[4][4][4];
#pragma unroll
    for (int i = 0; i < 4; i++)
#pragma unroll
        for (int j = 0; j < 4; j++)
#pragma unroll
            for (int k = 0; k < 4; k++) acc[i][j][k] = 0.f;

    float4 vx[3];
    for (int ch = 0; ch < 6; ch++) {
        int cur = ch & 1, nxt = cur ^ 1;
        bool pf = (ch < 5);
        if (pf) {
            int kb = (ch + 1) * 32;
#pragma unroll
            for (int it = 0; it < 3; it++) {
                int u = tid + it * 384;
                if (u < 1024) {
                    int r = u >> 5, c4 = (u & 31) * 4;
                    vx[it] = *(const float4*)(X + (size_t)(kb + r) * NTOK + n0 + c4);
                }
            }
        }

        uint32_t xb = sX_a + cur * (2 * XSTAGE * 2);
#pragma unroll
        for (int s = 0; s < 2; s++) {
            int kg = ch * 32 + s * 16;
            uint32_t ah[16], al[16], bx[8];
            int arow0 = wm * 64 + (lane & 15);
            int acol = kg + ((lane >> 4) << 3);
#pragma unroll
            for (int i = 0; i < 4; i++) {
                uint32_t ad = sM_a + (uint32_t)(((arow0 + i * 16) * MROW + acol) * 2);
                ldsm_x4(ah + 4 * i, ad);
                ldsm_x4(al + 4 * i, ad + MLOFF);
            }
            int krow = s * 16 + (lane & 7) + (((lane >> 3) & 1) << 3);
            int ncol0 = wn * 32 + ((lane >> 4) << 3);
#pragma unroll
            for (int jb = 0; jb < 2; jb++)
                ldsm_x4_t(bx + 4 * jb, xb + (uint32_t)((krow * OXROW + ncol0 + jb * 16) * 2));
#pragma unroll
            for (int i = 0; i < 4; i++)
#pragma unroll
                for (int jj = 0; jj < 4; jj++) {
                    const uint32_t* bp = bx + (jj >> 1) * 4 + (jj & 1) * 2;
                    mma16816(acc[i][jj], ah + 4 * i, bp);
                    mma16816(acc[i][jj], al + 4 * i, bp);
                }
#pragma unroll
            for (int jb = 0; jb < 2; jb++)
                ldsm_x4_t(bx + 4 * jb,
                          xb + XLOFF + (uint32_t)((krow * OXROW + ncol0 + jb * 16) * 2));
#pragma unroll
            for (int i = 0; i < 4; i++)
#pragma unroll
                for (int jj = 0; jj < 4; jj++)
                    mma16816(acc[i][jj], ah + 4 * i, bx + (jj >> 1) * 4 + (jj & 1) * 2);
        }

        if (pf) {
            __nv_bfloat16* nb = sX + nxt * 2 * XSTAGE;
#pragma unroll
            for (int it = 0; it < 3; it++) {
                int u = tid + it * 384;
                if (u < 1024) {
                    int r = u >> 5, c4 = (u & 31) * 4;
                    cvt_store(vx[it], nb + r * OXROW + c4, nb + XSTAGE + r * OXROW + c4);
                }
            }
        }
        __syncthreads();
    }

    int r0 = wm * 64 + (lane >> 2);
    int nb = n0 + wn * 32 + (lane & 3) * 2;
#pragma unroll
    for (int i = 0; i < 4; i++) {
        int c = r0 + i * 16;
        float b0 = scv[c], b1 = scv[c + 8];
#pragma unroll
        for (int jj = 0; jj < 4; jj++) {
            float2 v0 = {acc[i][jj][0] + b0, acc[i][jj][1] + b0};
            float2 v1 = {acc[i][jj][2] + b1, acc[i][jj][3] + b1};
            *(float2*)(O + (size_t)c * NTOK + nb + jj * 8) = v0;
            *(float2*)(O + (size_t)(c + 8) * NTOK + nb + jj * 8) = v1;
        }
    }
}

extern "C" void kernel_launch(void* const* d_in, const int* in_sizes, int n_in,
                              void* d_out, int out_size) {
    const float* x1 = (const float*)d_in[0];
    const float* x2 = (const float*)d_in[1];
    const float* q1 = (const float*)d_in[2];
    const float* q2 = (const float*)d_in[3];
    const float* Wq = (const float*)d_in[4];
    const float* bq = (const float*)d_in[5];
    const float* Wk = (const float*)d_in[6];
    const float* bk = (const float*)d_in[7];
    const float* Wv = (const float*)d_in[8];
    const float* bv = (const float*)d_in[9];
    const float* scale = (const float*)d_in[10];
    const float* Wproj = (const float*)d_in[11];
    float* out = (float*)d_out;

    static int configured = 0;
    if (!configured) {
        cudaFuncSetAttribute(gram_mma, cudaFuncAttributeMaxDynamicSharedMemorySize, GRAM_SMEM);
        cudaFuncSetAttribute(out_mma, cudaFuncAttributeMaxDynamicSharedMemorySize, OUT_SMEM);
        configured = 1;
    }

    zero_kernel<<<256, 256>>>();
    gram_mma<<<dim3(GSPLITK, 3, BATCH * 2), 384, GRAM_SMEM>>>(q1, q2, x1, x2);
    smallgemm_nn<<<dim3(6, 6, BATCH * 6), 256>>>(Wq, Wk, Wproj, 0);
    vec_kernel<<<dim3(CDIM, BATCH), 32>>>(Wq, Wk, bq, bk);
    attn_kernel<<<dim3(NHEADS, 2, BATCH), 256>>>(Wk, bq, bk, scale, bv);
    cvec_kernel<<<dim3(BATCH, 2), CDIM>>>(Wproj);
    p_kernel<<<dim3(6, 2, BATCH), 256>>>(Wv);
    smallgemm_nn<<<dim3(6, 6, BATCH * 2), 256>>>(Wq, Wk, Wproj, 1);
    out_mma<<<dim3(NTOK / 128, BATCH * 2), 384, OUT_SMEM>>>(x1, x2, out);
}

// round 11
// speedup vs baseline: 4.7126x; 1.0858x over previous
#include <cuda_runtime.h>
#include <cuda_bf16.h>
#include <cuda_fp16.h>
#include <math.h>
#include <stdint.h>

#define NTOK 16384
#define CDIM 192
#define BATCH 8
#define NHEADS 8
#define HD 24

// gram config (triple-fused, fp16 single-term, merged (1,0), GCH=32)
#define GSPLITK 8
#define GSLAB (NTOK / GSPLITK)  // 2048
#define GCH 32                  // k elems per chunk
#define GNCH (GSLAB / GCH)      // 64
#define SROW 40                 // padded smem row stride (fp16 elems)
#define RNG (96 * SROW)         // elems per plane
#define STG (4 * RNG)           // per stage (4 planes)
#define GRAM_SMEM (2 * STG * 2) // bytes (2 stages) = 61440

// out config (fp16: M single plane, X hi/lo)
#define MROW 200
#define OXROW 136
#define XSTAGE (32 * OXROW)
#define OUT_SMEM (CDIM * MROW * 2 + 2 * 2 * XSTAGE * 2 + CDIM * 4)

// -------- scratch --------
__device__ float g_C[BATCH][6][CDIM][CDIM];
__device__ float g_s[BATCH][4][CDIM];  // rowsums: q1, x2, q2, x1
__device__ float g_T[BATCH][6][CDIM][CDIM];
__device__ float g_vec[BATCH][8][CDIM];
__device__ float g_attn[BATCH][2][NHEADS][HD][HD];
__device__ float g_tvec[BATCH][2][CDIM];
__device__ float g_cvec[BATCH][2][CDIM];
__device__ float g_P[BATCH][2][CDIM][CDIM];
__device__ __half g_Mh[BATCH * 2][CDIM * CDIM];

// ================= mma helpers (sm_80-portable) =================
__device__ __forceinline__ uint32_t smem_u32(const void* p) {
    uint32_t a;
    asm("{ .reg .u64 t; cvta.to.shared.u64 t, %1; cvt.u32.u64 %0, t; }" : "=r"(a) : "l"(p));
    return a;
}
__device__ __forceinline__ void ldsm_x4(uint32_t* r, uint32_t addr) {
    asm volatile("ldmatrix.sync.aligned.m8n8.x4.shared.b16 {%0,%1,%2,%3}, [%4];"
                 : "=r"(r[0]), "=r"(r[1]), "=r"(r[2]), "=r"(r[3]) : "r"(addr));
}
__device__ __forceinline__ void ldsm_x4_t(uint32_t* r, uint32_t addr) {
    asm volatile("ldmatrix.sync.aligned.m8n8.x4.trans.shared.b16 {%0,%1,%2,%3}, [%4];"
                 : "=r"(r[0]), "=r"(r[1]), "=r"(r[2]), "=r"(r[3]) : "r"(addr));
}
// fp16 mma
__device__ __forceinline__ void mma16816h(float* d, const uint32_t* a, const uint32_t* b) {
    asm volatile(
        "mma.sync.aligned.m16n8k16.row.col.f32.f16.f16.f32 "
        "{%0,%1,%2,%3}, {%4,%5,%6,%7}, {%8,%9}, {%0,%1,%2,%3};"
        : "+f"(d[0]), "+f"(d[1]), "+f"(d[2]), "+f"(d[3])
        : "r"(a[0]), "r"(a[1]), "r"(a[2]), "r"(a[3]), "r"(b[0]), "r"(b[1]));
}
// fp16 packed store, hi only (gram)
__device__ __forceinline__ void cvt_store_h1(float4 v, __half* dh) {
    __half2 h01 = __floats2half2_rn(v.x, v.y);
    __half2 h23 = __floats2half2_rn(v.z, v.w);
    uint2 uh;
    uh.x = *(uint32_t*)&h01;
    uh.y = *(uint32_t*)&h23;
    *(uint2*)dh = uh;
}
// fp16 packed store, hi+lo (out_mma X path)
__device__ __forceinline__ void cvt_store_h2(float4 v, __half* dh, __half* dl) {
    __half2 h01 = __floats2half2_rn(v.x, v.y);
    __half2 h23 = __floats2half2_rn(v.z, v.w);
    float2 f01 = __half22float2(h01);
    float2 f23 = __half22float2(h23);
    __half2 l01 = __floats2half2_rn(v.x - f01.x, v.y - f01.y);
    __half2 l23 = __floats2half2_rn(v.z - f23.x, v.w - f23.y);
    uint2 uh, ul;
    uh.x = *(uint32_t*)&h01;
    uh.y = *(uint32_t*)&h23;
    ul.x = *(uint32_t*)&l01;
    ul.y = *(uint32_t*)&l23;
    *(uint2*)dh = uh;
    *(uint2*)dl = ul;
}
__device__ __forceinline__ void atom4(float* C, int r, int c, const float* a) {
    atomicAdd(C + r * CDIM + c, a[0]);
    atomicAdd(C + r * CDIM + c + 1, a[1]);
    atomicAdd(C + (r + 8) * CDIM + c, a[2]);
    atomicAdd(C + (r + 8) * CDIM + c + 1, a[3]);
}
__device__ __forceinline__ void atom4t(float* C, int r, int c, const float* a) {
    atomicAdd(C + c * CDIM + r, a[0]);
    atomicAdd(C + (c + 1) * CDIM + r, a[1]);
    atomicAdd(C + c * CDIM + r + 8, a[2]);
    atomicAdd(C + (c + 1) * CDIM + r + 8, a[3]);
}

// ================= kernels =================
__global__ void zero_kernel() {
    size_t n = sizeof(g_C) / 4;
    float* c = &g_C[0][0][0][0];
    for (size_t i = (size_t)blockIdx.x * blockDim.x + threadIdx.x; i < n;
         i += (size_t)gridDim.x * blockDim.x)
        c[i] = 0.f;
    size_t ns = sizeof(g_s) / 4;
    float* s = &g_s[0][0][0];
    for (size_t i = (size_t)blockIdx.x * blockDim.x + threadIdx.x; i < ns;
         i += (size_t)gridDim.x * blockDim.x)
        s[i] = 0.f;
}

// Triple-fused fp16 single-term gram with merged off-diagonal tile (unchanged from R9).
__global__ __launch_bounds__(384, 1) void gram_mma(const float* __restrict__ q1,
                                                   const float* __restrict__ q2,
                                                   const float* __restrict__ x1,
                                                   const float* __restrict__ x2) {
    extern __shared__ __align__(16) __half sm[];

    int sk = blockIdx.x, cls = blockIdx.y;
    int b = blockIdx.z >> 1, tr = blockIdx.z & 1;
    const float* A = (tr ? q2 : q1) + (size_t)b * CDIM * NTOK;
    const float* B = (tr ? x1 : x2) + (size_t)b * CDIM * NTOK;
    int slotA = tr ? 2 : 0, slotB = tr ? 3 : 1;
    float* C1 = &g_C[b][tr * 3 + 0][0][0];
    float* C2 = &g_C[b][tr * 3 + 1][0][0];
    float* C3 = &g_C[b][tr * 3 + 2][0][0];

    const float* lsrc[4];
    int larr[4], lslot[4], lrb[4], nld;
    if (cls == 1) {
        nld = 4;
        lsrc[0] = A; larr[0] = 0; lslot[0] = -1; lrb[0] = 0;
        lsrc[1] = A + (size_t)96 * NTOK; larr[1] = 1; lslot[1] = slotA; lrb[1] = 96;
        lsrc[2] = B; larr[2] = 2; lslot[2] = -1; lrb[2] = 0;
        lsrc[3] = B + (size_t)96 * NTOK; larr[3] = 3; lslot[3] = slotB; lrb[3] = 96;
    } else {
        nld = 2;
        size_t off = (cls == 2) ? (size_t)96 * NTOK : 0;
        lsrc[0] = A + off; larr[0] = 0; lslot[0] = (cls == 0) ? slotA : -1; lrb[0] = 0;
        lsrc[1] = B + off; larr[1] = 2; lslot[1] = (cls == 0) ? slotB : -1; lrb[1] = 0;
        lsrc[2] = lsrc[0]; larr[2] = 0; lslot[2] = -1; lrb[2] = 0;
        lsrc[3] = lsrc[0]; larr[3] = 0; lslot[3] = -1; lrb[3] = 0;
    }
    int jarr1 = (cls == 1) ? 1 : 0;
    int jarr3 = (cls == 1) ? 3 : 2;
    bool merged = (cls == 1);

    int tid = threadIdx.x, lane = tid & 31, wid = tid >> 5;
    int wm = wid / 6, wn = wid % 6;
    uint32_t smb = smem_u32(sm);

    float accC1[3][2][4] = {}, accC2[3][2][4] = {}, accC3[3][2][4] = {}, accC2b[3][2][4] = {};
    float rs[4] = {0.f, 0.f, 0.f, 0.f};

    int row = tid >> 2, c8 = (tid & 3) * 8;
    int kb0 = sk * GSLAB;

#pragma unroll
    for (int l = 0; l < 4; l++)
        if (l < nld) {
            const float* sp = lsrc[l] + (size_t)row * NTOK + kb0 + c8;
            float4 v0 = *(const float4*)sp;
            float4 v1 = *(const float4*)(sp + 4);
            if (lslot[l] >= 0)
                rs[l] += v0.x + v0.y + v0.z + v0.w + v1.x + v1.y + v1.z + v1.w;
            __half* dp = sm + larr[l] * RNG + row * SROW + c8;
            cvt_store_h1(v0, dp);
            cvt_store_h1(v1, dp + 4);
        }
    __syncthreads();

    float4 va[8];
    for (int ch = 0; ch < GNCH; ch++) {
        int cur = ch & 1, nxt = cur ^ 1;
        bool pf = (ch + 1 < GNCH);
        if (pf) {
            int kb = kb0 + (ch + 1) * GCH;
#pragma unroll
            for (int l = 0; l < 4; l++)
                if (l < nld) {
                    const float* sp = lsrc[l] + (size_t)row * NTOK + kb + c8;
                    va[2 * l] = *(const float4*)sp;
                    va[2 * l + 1] = *(const float4*)(sp + 4);
                }
        }

        uint32_t base = smb + cur * (STG * 2);
        int arow = wm * 48 + (lane & 15);
        int brow = wn * 16 + (lane & 7) + (((lane >> 4) & 1) << 3);
#pragma unroll
        for (int s = 0; s < 2; s++) {
            int acol = s * 16 + ((lane >> 4) << 3);
            int bcol = s * 16 + (((lane >> 3) & 1) << 3);

            uint32_t aih[12];
#pragma unroll
            for (int f = 0; f < 3; f++)
                ldsm_x4(aih + 4 * f, base + (uint32_t)(((arow + f * 16) * SROW + acol) * 2));
            uint32_t j1[4];
            ldsm_x4(j1, base + (uint32_t)((jarr1 * RNG + brow * SROW + bcol) * 2));
#pragma unroll
            for (int f = 0; f < 3; f++)
#pragma unroll
                for (int n = 0; n < 2; n++)
                    mma16816h(accC1[f][n], aih + 4 * f, j1 + 2 * n);
            uint32_t j3[4];
            ldsm_x4(j3, base + (uint32_t)((jarr3 * RNG + brow * SROW + bcol) * 2));
#pragma unroll
            for (int f = 0; f < 3; f++)
#pragma unroll
                for (int n = 0; n < 2; n++)
                    mma16816h(accC2[f][n], aih + 4 * f, j3 + 2 * n);
            uint32_t bih[12];
#pragma unroll
            for (int f = 0; f < 3; f++)
                ldsm_x4(bih + 4 * f,
                        base + (uint32_t)((2 * RNG + (arow + f * 16) * SROW + acol) * 2));
#pragma unroll
            for (int f = 0; f < 3; f++)
#pragma unroll
                for (int n = 0; n < 2; n++)
                    mma16816h(accC3[f][n], bih + 4 * f, j3 + 2 * n);
            if (merged) {
                uint32_t ai2[12], j2[4];
#pragma unroll
                for (int f = 0; f < 3; f++)
                    ldsm_x4(ai2 + 4 * f,
                            base + (uint32_t)((RNG + (arow + f * 16) * SROW + acol) * 2));
                ldsm_x4(j2, base + (uint32_t)((2 * RNG + brow * SROW + bcol) * 2));
#pragma unroll
                for (int f = 0; f < 3; f++)
#pragma unroll
                    for (int n = 0; n < 2; n++)
                        mma16816h(accC2b[f][n], ai2 + 4 * f, j2 + 2 * n);
            }
        }

        if (pf) {
            uint32_t nb = nxt * STG;
#pragma unroll
            for (int l = 0; l < 4; l++)
                if (l < nld) {
                    float4 v0 = va[2 * l], v1 = va[2 * l + 1];
                    if (lslot[l] >= 0)
                        rs[l] += v0.x + v0.y + v0.z + v0.w + v1.x + v1.y + v1.z + v1.w;
                    __half* dp = sm + nb + larr[l] * RNG + row * SROW + c8;
                    cvt_store_h1(v0, dp);
                    cvt_store_h1(v1, dp + 4);
                }
        }
        __syncthreads();
    }

    int ti = (cls == 2) ? 1 : 0;
    int tj = (cls == 0) ? 0 : 1;
    int rw = wm * 48 + (lane >> 2);
    int cw = wn * 16 + (lane & 3) * 2;
#pragma unroll
    for (int f = 0; f < 3; f++)
#pragma unroll
        for (int n = 0; n < 2; n++) {
            int r = ti * 96 + rw + f * 16, c = tj * 96 + cw + n * 8;
            atom4(C1, r, c, accC1[f][n]);
            atom4(C2, r, c, accC2[f][n]);
            atom4(C3, r, c, accC3[f][n]);
            if (merged) {
                atom4t(C1, r, c, accC1[f][n]);
                atom4t(C3, r, c, accC3[f][n]);
                atom4(C2, 96 + rw + f * 16, cw + n * 8, accC2b[f][n]);
            }
        }
#pragma unroll
    for (int l = 0; l < 4; l++)
        if (l < nld && lslot[l] >= 0) atomicAdd(&g_s[b][lslot[l]][lrb[l] + row], rs[l]);
}

// -------- small NN GEMMs (192x192x192): D = W @ C ; 64x64 tiles, 4x4/thread --------
// mode 0: T = W(g) @ C (fp32). mode 1: M = Wproj @ P -> fp16 g_Mh.
// NOTE: smem row pads are 68 floats (272 B, 16B-multiple) so float4 loads stay aligned.
__global__ void smallgemm_nn(const float* __restrict__ Wq, const float* __restrict__ Wk,
                             const float* __restrict__ Wproj, int mode) {
    int z = blockIdx.z;
    const float* W; const float* C; float* D = nullptr;
    __half* Dh = nullptr;
    if (mode == 0) {
        int b = z / 6, g = z % 6;
        W = (g == 2 || g == 5) ? Wk : Wq;
        C = &g_C[b][g][0][0];
        D = &g_T[b][g][0][0];
    } else {
        int b = z / 2, p = z % 2;
        W = Wproj;
        C = &g_P[b][p][0][0];
        Dh = g_Mh[z];
        (void)b;
    }
    int m0 = blockIdx.y * 64, j0 = blockIdx.x * 64;
    __shared__ float Ws[32][68];  // [k][m], 272B row stride (16B aligned)
    __shared__ float Cs[32][68];  // [k][n]
    int t = threadIdx.x, tx = t % 16, ty = t / 16;
    float acc[4][4] = {};
    for (int k0 = 0; k0 < CDIM; k0 += 32) {
        __syncthreads();
        for (int e = t; e < 2048; e += 256) {
            int r = e >> 5, c = e & 31;           // r = m-row, c = k
            Ws[c][r] = W[(m0 + r) * CDIM + k0 + c];
        }
        for (int e = t; e < 2048; e += 256) {
            int r = e >> 6, n = e & 63;           // r = k, n = col
            Cs[r][n] = C[(k0 + r) * CDIM + j0 + n];
        }
        __syncthreads();
#pragma unroll
        for (int kk = 0; kk < 32; kk++) {
            float4 a4 = *(float4*)&Ws[kk][ty * 4];
            float4 b4 = *(float4*)&Cs[kk][tx * 4];
            float a[4] = {a4.x, a4.y, a4.z, a4.w};
            float bb[4] = {b4.x, b4.y, b4.z, b4.w};
#pragma unroll
            for (int i = 0; i < 4; i++)
#pragma unroll
                for (int j = 0; j < 4; j++) acc[i][j] = fmaf(a[i], bb[j], acc[i][j]);
        }
    }
    if (mode == 0) {
#pragma unroll
        for (int i = 0; i < 4; i++)
#pragma unroll
            for (int j = 0; j < 4; j++)
                D[(m0 + ty * 4 + i) * CDIM + (j0 + tx * 4 + j)] = acc[i][j];
    } else {
#pragma unroll
        for (int i = 0; i < 4; i++)
#pragma unroll
            for (int j = 0; j < 4; j++)
                Dh[(m0 + ty * 4 + i) * CDIM + (j0 + tx * 4 + j)] = __float2half(acc[i][j]);
    }
}

// -------- per-batch vectors (warp per (b,c)) --------
__global__ void vec_kernel(const float* __restrict__ Wq, const float* __restrict__ Wk,
                           const float* __restrict__ bq, const float* __restrict__ bk) {
    int c = blockIdx.x, b = blockIdx.y, l = threadIdx.x;
    float a0 = 0, a1 = 0, a2 = 0, a3 = 0, d0 = 0, d2 = 0, d3 = 0, d5 = 0;
    for (int i = l; i < CDIM; i += 32) {
        float wq = Wq[c * CDIM + i], wk = Wk[c * CDIM + i];
        a0 = fmaf(wq, g_s[b][0][i], a0);
        a1 = fmaf(wk, g_s[b][1][i], a1);
        a2 = fmaf(wq, g_s[b][2][i], a2);
        a3 = fmaf(wk, g_s[b][3][i], a3);
        d0 = fmaf(g_T[b][0][c][i], wq, d0);
        d2 = fmaf(g_T[b][2][c][i], wk, d2);
        d3 = fmaf(g_T[b][3][c][i], wq, d3);
        d5 = fmaf(g_T[b][5][c][i], wk, d5);
    }
#pragma unroll
    for (int s = 16; s > 0; s >>= 1) {
        a0 += __shfl_xor_sync(0xffffffff, a0, s);
        a1 += __shfl_xor_sync(0xffffffff, a1, s);
        a2 += __shfl_xor_sync(0xffffffff, a2, s);
        a3 += __shfl_xor_sync(0xffffffff, a3, s);
        d0 += __shfl_xor_sync(0xffffffff, d0, s);
        d2 += __shfl_xor_sync(0xffffffff, d2, s);
        d3 += __shfl_xor_sync(0xffffffff, d3, s);
        d5 += __shfl_xor_sync(0xffffffff, d5, s);
    }
    if (l == 0) {
        float bqc = bq[c], bkc = bk[c];
        const float NN = (float)NTOK;
        g_vec[b][0][c] = a0;
        g_vec[b][1][c] = a1;
        g_vec[b][2][c] = a2;
        g_vec[b][3][c] = a3;
        g_vec[b][4][c] = sqrtf(fmaxf(d0 + 2.f * bqc * a0 + NN * bqc * bqc, 0.f));
        g_vec[b][5][c] = sqrtf(fmaxf(d2 + 2.f * bkc * a1 + NN * bkc * bkc, 0.f));
        g_vec[b][6][c] = sqrtf(fmaxf(d3 + 2.f * bqc * a2 + NN * bqc * bqc, 0.f));
        g_vec[b][7][c] = sqrtf(fmaxf(d5 + 2.f * bkc * a3 + NN * bkc * bkc, 0.f));
    }
}

// -------- logits + softmax --------
__global__ void attn_kernel(const float* __restrict__ Wk, const float* __restrict__ bq,
                            const float* __restrict__ bk, const float* __restrict__ scale,
                            const float* __restrict__ bv) {
    int h = blockIdx.x, pair = blockIdx.y, b = blockIdx.z;
    __shared__ float sTA[HD][CDIM];
    __shared__ float sWk[HD][CDIM];
    __shared__ float slog[HD][HD];
    const float* TA = pair ? &g_T[b][4][0][0] : &g_T[b][1][0][0];
    const float* wqs = pair ? g_vec[b][2] : g_vec[b][0];
    const float* wks = pair ? g_vec[b][3] : g_vec[b][1];
    const float* nq = pair ? g_vec[b][6] : g_vec[b][4];
    const float* nk = pair ? g_vec[b][7] : g_vec[b][5];
    int t = threadIdx.x;
    for (int e = t; e < HD * CDIM; e += 256) {
        int r = e / CDIM, cc = e % CDIM;
        sTA[r][cc] = TA[(h * HD + r) * CDIM + cc];
        sWk[r][cc] = Wk[(h * HD + r) * CDIM + cc];
    }
    __syncthreads();
    float sc = scale[h];
    const float NN = (float)NTOK;
    for (int e = t; e < HD * HD; e += 256) {
        int i = e / HD, j = e % HD;
        int c = h * HD + i, d = h * HD + j;
        float dot = 0.f;
        for (int k = 0; k < CDIM; k++) dot = fmaf(sTA[i][k], sWk[j][k], dot);
        float raw = dot + wqs[c] * bk[d] + bq[c] * wks[d] + NN * bq[c] * bk[d];
        slog[i][j] = raw / (fmaxf(nq[c], 1e-12f) * fmaxf(nk[d], 1e-12f)) * sc;
    }
    __syncthreads();
    if (t < HD) {
        int i = t;
        float m = -INFINITY;
        for (int j = 0; j < HD; j++) m = fmaxf(m, slog[i][j]);
        float ex[HD];
        float sum = 0.f;
        for (int j = 0; j < HD; j++) { ex[j] = expf(slog[i][j] - m); sum += ex[j]; }
        float inv = 1.f / sum;
        float tv = 0.f;
        for (int j = 0; j < HD; j++) {
            float a = ex[j] * inv;
            g_attn[b][pair][h][i][j] = a;
            tv = fmaf(a, bv[h * HD + j], tv);
        }
        g_tvec[b][pair][h * HD + i] = tv;
    }
}

__global__ void cvec_kernel(const float* __restrict__ Wproj) {
    int b = blockIdx.x, p = blockIdx.y, c = threadIdx.x;
    __shared__ float tv[CDIM];
    tv[c] = g_tvec[b][p][c];
    __syncthreads();
    float s = 0.f;
    for (int i = 0; i < CDIM; i++) s = fmaf(Wproj[c * CDIM + i], tv[i], s);
    g_cvec[b][p][c] = s;
}

__global__ void p_kernel(const float* __restrict__ Wv) {
    int vt = blockIdx.x, p = blockIdx.y, b = blockIdx.z;
    int v0 = vt * 32;
    __shared__ float sA[NHEADS][HD][HD];
    __shared__ float sWv[CDIM][32];
    int t = threadIdx.x;
    const float* attnflat = &g_attn[b][p][0][0][0];
    for (int e = t; e < NHEADS * HD * HD; e += 256) (&sA[0][0][0])[e] = attnflat[e];
    for (int e = t; e < CDIM * 32; e += 256) {
        int r = e / 32, vc = e % 32;
        sWv[r][vc] = Wv[r * CDIM + v0 + vc];
    }
    __syncthreads();
    for (int e = t; e < CDIM * 32; e += 256) {
        int c = e / 32, vc = e % 32;
        int h = c / HD, i = c % HD;
        float acc = 0.f;
#pragma unroll
        for (int j = 0; j < HD; j++) acc = fmaf(sA[h][i][j], sWv[h * HD + j][vc], acc);
        g_P[b][p][c][v0 + vc] = acc;
    }
}

// out = M @ X + cvec ; fp16 2-term: Mh(single) x (Xh + Xl).
// M resident in smem, X double-buffered. grid (NTOK/128, 16), 384 threads.
__global__ __launch_bounds__(384, 1) void out_mma(const float* __restrict__ x1,
                                                  const float* __restrict__ x2,
                                                  float* __restrict__ out) {
    extern __shared__ __align__(16) __half smo[];
    __half* sM = smo;                       // [CDIM * MROW]
    __half* sX = smo + CDIM * MROW;         // stage s: hi at s*2*XSTAGE, lo +XSTAGE
    float* scv = (float*)(smo + CDIM * MROW + 4 * XSTAGE);

    int z = blockIdx.y;
    int b = z >> 1, p = z & 1;
    const float* X = (p ? x1 : x2) + (size_t)b * CDIM * NTOK;
    const __half* Mh = g_Mh[z];
    float* O = out + (size_t)p * BATCH * CDIM * NTOK + (size_t)b * CDIM * NTOK;
    int n0 = blockIdx.x * 128;

    int tid = threadIdx.x, lane = tid & 31, wid = tid >> 5;
    int wm = wid >> 2, wn = wid & 3;

    if (tid < CDIM) scv[tid] = g_cvec[b][p][tid];

    // resident M load, padded stride MROW
    for (int u = tid; u < CDIM * CDIM / 8; u += 384) {
        int row = u / 24, col = (u % 24) * 8;
        *(uint4*)(sM + row * MROW + col) = *(const uint4*)(Mh + row * CDIM + col);
    }
    // X chunk 0 -> stage 0
    for (int u = tid; u < 1024; u += 384) {
        int r = u >> 5, c4 = (u & 31) * 4;
        float4 v = *(const float4*)(X + (size_t)r * NTOK + n0 + c4);
        cvt_store_h2(v, sX + r * OXROW + c4, sX + XSTAGE + r * OXROW + c4);
    }
    __syncthreads();

    uint32_t sM_a = smem_u32(sM);
    uint32_t sX_a = smem_u32(sX);
    const uint32_t XLOFF = XSTAGE * 2;

    float acc[4][4][4];
#pragma unroll
    for (int i = 0; i < 4; i++)
#pragma unroll
        for (int j = 0; j < 4; j++)
#pragma unroll
            for (int k = 0; k < 4; k++) acc[i][j][k] = 0.f;

    float4 vx[3];
    for (int ch = 0; ch < 6; ch++) {
        int cur = ch & 1, nxt = cur ^ 1;
        bool pf = (ch < 5);
        if (pf) {
            int kb = (ch + 1) * 32;
#pragma unroll
            for (int it = 0; it < 3; it++) {
                int u = tid + it * 384;
                if (u < 1024) {
                    int r = u >> 5, c4 = (u & 31) * 4;
                    vx[it] = *(const float4*)(X + (size_t)(kb + r) * NTOK + n0 + c4);
                }
            }
        }

        uint32_t xb = sX_a + cur * (2 * XSTAGE * 2);
#pragma unroll
        for (int s = 0; s < 2; s++) {
            int kg = ch * 32 + s * 16;
            uint32_t ah[16], bx[8];
            int arow0 = wm * 64 + (lane & 15);
            int acol = kg + ((lane >> 4) << 3);
#pragma unroll
            for (int i = 0; i < 4; i++)
                ldsm_x4(ah + 4 * i, sM_a + (uint32_t)(((arow0 + i * 16) * MROW + acol) * 2));
            int krow = s * 16 + (lane & 7) + (((lane >> 3) & 1) << 3);
            int ncol0 = wn * 32 + ((lane >> 4) << 3);
#pragma unroll
            for (int jb = 0; jb < 2; jb++)
                ldsm_x4_t(bx + 4 * jb, xb + (uint32_t)((krow * OXROW + ncol0 + jb * 16) * 2));
#pragma unroll
            for (int i = 0; i < 4; i++)
#pragma unroll
                for (int jj = 0; jj < 4; jj++)
                    mma16816h(acc[i][jj], ah + 4 * i, bx + (jj >> 1) * 4 + (jj & 1) * 2);
#pragma unroll
            for (int jb = 0; jb < 2; jb++)
                ldsm_x4_t(bx + 4 * jb,
                          xb + XLOFF + (uint32_t)((krow * OXROW + ncol0 + jb * 16) * 2));
#pragma unroll
            for (int i = 0; i < 4; i++)
#pragma unroll
                for (int jj = 0; jj < 4; jj++)
                    mma16816h(acc[i][jj], ah + 4 * i, bx + (jj >> 1) * 4 + (jj & 1) * 2);
        }

        if (pf) {
            __half* nb = sX + nxt * 2 * XSTAGE;
#pragma unroll
            for (int it = 0; it < 3; it++) {
                int u = tid + it * 384;
                if (u < 1024) {
                    int r = u >> 5, c4 = (u & 31) * 4;
                    cvt_store_h2(vx[it], nb + r * OXROW + c4, nb + XSTAGE + r * OXROW + c4);
                }
            }
        }
        __syncthreads();
    }

    int r0 = wm * 64 + (lane >> 2);
    int nb = n0 + wn * 32 + (lane & 3) * 2;
#pragma unroll
    for (int i = 0; i < 4; i++) {
        int c = r0 + i * 16;
        float b0 = scv[c], b1 = scv[c + 8];
#pragma unroll
        for (int jj = 0; jj < 4; jj++) {
            float2 v0 = {acc[i][jj][0] + b0, acc[i][jj][1] + b0};
            float2 v1 = {acc[i][jj][2] + b1, acc[i][jj][3] + b1};
            *(float2*)(O + (size_t)c * NTOK + nb + jj * 8) = v0;
            *(float2*)(O + (size_t)(c + 8) * NTOK + nb + jj * 8) = v1;
        }
    }
}

extern "C" void kernel_launch(void* const* d_in, const int* in_sizes, int n_in,
                              void* d_out, int out_size) {
    const float* x1 = (const float*)d_in[0];
    const float* x2 = (const float*)d_in[1];
    const float* q1 = (const float*)d_in[2];
    const float* q2 = (const float*)d_in[3];
    const float* Wq = (const float*)d_in[4];
    const float* bq = (const float*)d_in[5];
    const float* Wk = (const float*)d_in[6];
    const float* bk = (const float*)d_in[7];
    const float* Wv = (const float*)d_in[8];
    const float* bv = (const float*)d_in[9];
    const float* scale = (const float*)d_in[10];
    const float* Wproj = (const float*)d_in[11];
    float* out = (float*)d_out;

    static int configured = 0;
    if (!configured) {
        cudaFuncSetAttribute(gram_mma, cudaFuncAttributeMaxDynamicSharedMemorySize, GRAM_SMEM);
        cudaFuncSetAttribute(out_mma, cudaFuncAttributeMaxDynamicSharedMemorySize, OUT_SMEM);
        configured = 1;
    }

    zero_kernel<<<256, 256>>>();
    gram_mma<<<dim3(GSPLITK, 3, BATCH * 2), 384, GRAM_SMEM>>>(q1, q2, x1, x2);
    smallgemm_nn<<<dim3(3, 3, BATCH * 6), 256>>>(Wq, Wk, Wproj, 0);
    vec_kernel<<<dim3(CDIM, BATCH), 32>>>(Wq, Wk, bq, bk);
    attn_kernel<<<dim3(NHEADS, 2, BATCH), 256>>>(Wk, bq, bk, scale, bv);
    cvec_kernel<<<dim3(BATCH, 2), CDIM>>>(Wproj);
    p_kernel<<<dim3(6, 2, BATCH), 256>>>(Wv);
    smallgemm_nn<<<dim3(3, 3, BATCH * 2), 256>>>(Wq, Wk, Wproj, 1);
    out_mma<<<dim3(NTOK / 128, BATCH * 2), 384, OUT_SMEM>>>(x1, x2, out);
}

// round 12
// speedup vs baseline: 5.0004x; 1.0611x over previous
#include <cuda_runtime.h>
#include <cuda_bf16.h>
#include <cuda_fp16.h>
#include <math.h>
#include <stdint.h>

#define NTOK 16384
#define CDIM 192
#define BATCH 8
#define NHEADS 8
#define HD 24

// gram config (triple-fused, fp16 single-term, merged (1,0), GCH=32)
#define GSPLITK 8
#define GSLAB (NTOK / GSPLITK)  // 2048
#define GCH 32                  // k elems per chunk
#define GNCH (GSLAB / GCH)      // 64
#define SROW 40                 // padded smem row stride (fp16 elems)
#define RNG (96 * SROW)         // elems per plane
#define STG (4 * RNG)           // per stage (4 planes)
#define GRAM_SMEM (2 * STG * 2) // bytes (2 stages) = 61440

// out config (fp16 single-term: M and X single planes)
#define MROW 200
#define OXROW 136
#define XSTAGE (32 * OXROW)
#define OUT_SMEM (CDIM * MROW * 2 + 2 * XSTAGE * 2 + CDIM * 4)

// -------- scratch --------
__device__ float g_C[BATCH][6][CDIM][CDIM];
__device__ float g_s[BATCH][4][CDIM];  // rowsums: q1, x2, q2, x1
__device__ float g_T[BATCH][6][CDIM][CDIM];
__device__ float g_vec[BATCH][8][CDIM];
__device__ float g_attn[BATCH][2][NHEADS][HD][HD];
__device__ float g_tvec[BATCH][2][CDIM];
__device__ float g_cvec[BATCH][2][CDIM];
__device__ float g_P[BATCH][2][CDIM][CDIM];
__device__ __half g_Mh[BATCH * 2][CDIM * CDIM];

// ================= mma helpers (sm_80-portable) =================
__device__ __forceinline__ uint32_t smem_u32(const void* p) {
    uint32_t a;
    asm("{ .reg .u64 t; cvta.to.shared.u64 t, %1; cvt.u32.u64 %0, t; }" : "=r"(a) : "l"(p));
    return a;
}
__device__ __forceinline__ void ldsm_x4(uint32_t* r, uint32_t addr) {
    asm volatile("ldmatrix.sync.aligned.m8n8.x4.shared.b16 {%0,%1,%2,%3}, [%4];"
                 : "=r"(r[0]), "=r"(r[1]), "=r"(r[2]), "=r"(r[3]) : "r"(addr));
}
__device__ __forceinline__ void ldsm_x4_t(uint32_t* r, uint32_t addr) {
    asm volatile("ldmatrix.sync.aligned.m8n8.x4.trans.shared.b16 {%0,%1,%2,%3}, [%4];"
                 : "=r"(r[0]), "=r"(r[1]), "=r"(r[2]), "=r"(r[3]) : "r"(addr));
}
// fp16 mma
__device__ __forceinline__ void mma16816h(float* d, const uint32_t* a, const uint32_t* b) {
    asm volatile(
        "mma.sync.aligned.m16n8k16.row.col.f32.f16.f16.f32 "
        "{%0,%1,%2,%3}, {%4,%5,%6,%7}, {%8,%9}, {%0,%1,%2,%3};"
        : "+f"(d[0]), "+f"(d[1]), "+f"(d[2]), "+f"(d[3])
        : "r"(a[0]), "r"(a[1]), "r"(a[2]), "r"(a[3]), "r"(b[0]), "r"(b[1]));
}
// fp16 packed store, hi only
__device__ __forceinline__ void cvt_store_h1(float4 v, __half* dh) {
    __half2 h01 = __floats2half2_rn(v.x, v.y);
    __half2 h23 = __floats2half2_rn(v.z, v.w);
    uint2 uh;
    uh.x = *(uint32_t*)&h01;
    uh.y = *(uint32_t*)&h23;
    *(uint2*)dh = uh;
}
__device__ __forceinline__ void atom4(float* C, int r, int c, const float* a) {
    atomicAdd(C + r * CDIM + c, a[0]);
    atomicAdd(C + r * CDIM + c + 1, a[1]);
    atomicAdd(C + (r + 8) * CDIM + c, a[2]);
    atomicAdd(C + (r + 8) * CDIM + c + 1, a[3]);
}
__device__ __forceinline__ void atom4t(float* C, int r, int c, const float* a) {
    atomicAdd(C + c * CDIM + r, a[0]);
    atomicAdd(C + (c + 1) * CDIM + r, a[1]);
    atomicAdd(C + c * CDIM + r + 8, a[2]);
    atomicAdd(C + (c + 1) * CDIM + r + 8, a[3]);
}

// ================= kernels =================
__global__ void zero_kernel() {
    size_t n = sizeof(g_C) / 4;
    float* c = &g_C[0][0][0][0];
    for (size_t i = (size_t)blockIdx.x * blockDim.x + threadIdx.x; i < n;
         i += (size_t)gridDim.x * blockDim.x)
        c[i] = 0.f;
    size_t ns = sizeof(g_s) / 4;
    float* s = &g_s[0][0][0];
    for (size_t i = (size_t)blockIdx.x * blockDim.x + threadIdx.x; i < ns;
         i += (size_t)gridDim.x * blockDim.x)
        s[i] = 0.f;
}

// Triple-fused fp16 single-term gram with merged off-diagonal tile (unchanged from R9).
__global__ __launch_bounds__(384, 1) void gram_mma(const float* __restrict__ q1,
                                                   const float* __restrict__ q2,
                                                   const float* __restrict__ x1,
                                                   const float* __restrict__ x2) {
    extern __shared__ __align__(16) __half sm[];

    int sk = blockIdx.x, cls = blockIdx.y;
    int b = blockIdx.z >> 1, tr = blockIdx.z & 1;
    const float* A = (tr ? q2 : q1) + (size_t)b * CDIM * NTOK;
    const float* B = (tr ? x1 : x2) + (size_t)b * CDIM * NTOK;
    int slotA = tr ? 2 : 0, slotB = tr ? 3 : 1;
    float* C1 = &g_C[b][tr * 3 + 0][0][0];
    float* C2 = &g_C[b][tr * 3 + 1][0][0];
    float* C3 = &g_C[b][tr * 3 + 2][0][0];

    const float* lsrc[4];
    int larr[4], lslot[4], lrb[4], nld;
    if (cls == 1) {
        nld = 4;
        lsrc[0] = A; larr[0] = 0; lslot[0] = -1; lrb[0] = 0;
        lsrc[1] = A + (size_t)96 * NTOK; larr[1] = 1; lslot[1] = slotA; lrb[1] = 96;
        lsrc[2] = B; larr[2] = 2; lslot[2] = -1; lrb[2] = 0;
        lsrc[3] = B + (size_t)96 * NTOK; larr[3] = 3; lslot[3] = slotB; lrb[3] = 96;
    } else {
        nld = 2;
        size_t off = (cls == 2) ? (size_t)96 * NTOK : 0;
        lsrc[0] = A + off; larr[0] = 0; lslot[0] = (cls == 0) ? slotA : -1; lrb[0] = 0;
        lsrc[1] = B + off; larr[1] = 2; lslot[1] = (cls == 0) ? slotB : -1; lrb[1] = 0;
        lsrc[2] = lsrc[0]; larr[2] = 0; lslot[2] = -1; lrb[2] = 0;
        lsrc[3] = lsrc[0]; larr[3] = 0; lslot[3] = -1; lrb[3] = 0;
    }
    int jarr1 = (cls == 1) ? 1 : 0;
    int jarr3 = (cls == 1) ? 3 : 2;
    bool merged = (cls == 1);

    int tid = threadIdx.x, lane = tid & 31, wid = tid >> 5;
    int wm = wid / 6, wn = wid % 6;
    uint32_t smb = smem_u32(sm);

    float accC1[3][2][4] = {}, accC2[3][2][4] = {}, accC3[3][2][4] = {}, accC2b[3][2][4] = {};
    float rs[4] = {0.f, 0.f, 0.f, 0.f};

    int row = tid >> 2, c8 = (tid & 3) * 8;
    int kb0 = sk * GSLAB;

#pragma unroll
    for (int l = 0; l < 4; l++)
        if (l < nld) {
            const float* sp = lsrc[l] + (size_t)row * NTOK + kb0 + c8;
            float4 v0 = *(const float4*)sp;
            float4 v1 = *(const float4*)(sp + 4);
            if (lslot[l] >= 0)
                rs[l] += v0.x + v0.y + v0.z + v0.w + v1.x + v1.y + v1.z + v1.w;
            __half* dp = sm + larr[l] * RNG + row * SROW + c8;
            cvt_store_h1(v0, dp);
            cvt_store_h1(v1, dp + 4);
        }
    __syncthreads();

    float4 va[8];
    for (int ch = 0; ch < GNCH; ch++) {
        int cur = ch & 1, nxt = cur ^ 1;
        bool pf = (ch + 1 < GNCH);
        if (pf) {
            int kb = kb0 + (ch + 1) * GCH;
#pragma unroll
            for (int l = 0; l < 4; l++)
                if (l < nld) {
                    const float* sp = lsrc[l] + (size_t)row * NTOK + kb + c8;
                    va[2 * l] = *(const float4*)sp;
                    va[2 * l + 1] = *(const float4*)(sp + 4);
                }
        }

        uint32_t base = smb + cur * (STG * 2);
        int arow = wm * 48 + (lane & 15);
        int brow = wn * 16 + (lane & 7) + (((lane >> 4) & 1) << 3);
#pragma unroll
        for (int s = 0; s < 2; s++) {
            int acol = s * 16 + ((lane >> 4) << 3);
            int bcol = s * 16 + (((lane >> 3) & 1) << 3);

            uint32_t aih[12];
#pragma unroll
            for (int f = 0; f < 3; f++)
                ldsm_x4(aih + 4 * f, base + (uint32_t)(((arow + f * 16) * SROW + acol) * 2));
            uint32_t j1[4];
            ldsm_x4(j1, base + (uint32_t)((jarr1 * RNG + brow * SROW + bcol) * 2));
#pragma unroll
            for (int f = 0; f < 3; f++)
#pragma unroll
                for (int n = 0; n < 2; n++)
                    mma16816h(accC1[f][n], aih + 4 * f, j1 + 2 * n);
            uint32_t j3[4];
            ldsm_x4(j3, base + (uint32_t)((jarr3 * RNG + brow * SROW + bcol) * 2));
#pragma unroll
            for (int f = 0; f < 3; f++)
#pragma unroll
                for (int n = 0; n < 2; n++)
                    mma16816h(accC2[f][n], aih + 4 * f, j3 + 2 * n);
            uint32_t bih[12];
#pragma unroll
            for (int f = 0; f < 3; f++)
                ldsm_x4(bih + 4 * f,
                        base + (uint32_t)((2 * RNG + (arow + f * 16) * SROW + acol) * 2));
#pragma unroll
            for (int f = 0; f < 3; f++)
#pragma unroll
                for (int n = 0; n < 2; n++)
                    mma16816h(accC3[f][n], bih + 4 * f, j3 + 2 * n);
            if (merged) {
                uint32_t ai2[12], j2[4];
#pragma unroll
                for (int f = 0; f < 3; f++)
                    ldsm_x4(ai2 + 4 * f,
                            base + (uint32_t)((RNG + (arow + f * 16) * SROW + acol) * 2));
                ldsm_x4(j2, base + (uint32_t)((2 * RNG + brow * SROW + bcol) * 2));
#pragma unroll
                for (int f = 0; f < 3; f++)
#pragma unroll
                    for (int n = 0; n < 2; n++)
                        mma16816h(accC2b[f][n], ai2 + 4 * f, j2 + 2 * n);
            }
        }

        if (pf) {
            uint32_t nb = nxt * STG;
#pragma unroll
            for (int l = 0; l < 4; l++)
                if (l < nld) {
                    float4 v0 = va[2 * l], v1 = va[2 * l + 1];
                    if (lslot[l] >= 0)
                        rs[l] += v0.x + v0.y + v0.z + v0.w + v1.x + v1.y + v1.z + v1.w;
                    __half* dp = sm + nb + larr[l] * RNG + row * SROW + c8;
                    cvt_store_h1(v0, dp);
                    cvt_store_h1(v1, dp + 4);
                }
        }
        __syncthreads();
    }

    int ti = (cls == 2) ? 1 : 0;
    int tj = (cls == 0) ? 0 : 1;
    int rw = wm * 48 + (lane >> 2);
    int cw = wn * 16 + (lane & 3) * 2;
#pragma unroll
    for (int f = 0; f < 3; f++)
#pragma unroll
        for (int n = 0; n < 2; n++) {
            int r = ti * 96 + rw + f * 16, c = tj * 96 + cw + n * 8;
            atom4(C1, r, c, accC1[f][n]);
            atom4(C2, r, c, accC2[f][n]);
            atom4(C3, r, c, accC3[f][n]);
            if (merged) {
                atom4t(C1, r, c, accC1[f][n]);
                atom4t(C3, r, c, accC3[f][n]);
                atom4(C2, 96 + rw + f * 16, cw + n * 8, accC2b[f][n]);
            }
        }
#pragma unroll
    for (int l = 0; l < 4; l++)
        if (l < nld && lslot[l] >= 0) atomicAdd(&g_s[b][lslot[l]][lrb[l] + row], rs[l]);
}

// -------- small NN GEMMs (192x192x192): D = W @ C ; 64x64 tiles, 4x4/thread --------
__global__ void smallgemm_nn(const float* __restrict__ Wq, const float* __restrict__ Wk,
                             const float* __restrict__ Wproj, int mode) {
    int z = blockIdx.z;
    const float* W; const float* C; float* D = nullptr;
    __half* Dh = nullptr;
    if (mode == 0) {
        int b = z / 6, g = z % 6;
        W = (g == 2 || g == 5) ? Wk : Wq;
        C = &g_C[b][g][0][0];
        D = &g_T[b][g][0][0];
    } else {
        int b = z / 2, p = z % 2;
        W = Wproj;
        C = &g_P[b][p][0][0];
        Dh = g_Mh[z];
        (void)b;
    }
    int m0 = blockIdx.y * 64, j0 = blockIdx.x * 64;
    __shared__ float Ws[32][68];  // 272B row stride (16B aligned)
    __shared__ float Cs[32][68];
    int t = threadIdx.x, tx = t % 16, ty = t / 16;
    float acc[4][4] = {};
    for (int k0 = 0; k0 < CDIM; k0 += 32) {
        __syncthreads();
        for (int e = t; e < 2048; e += 256) {
            int r = e >> 5, c = e & 31;
            Ws[c][r] = W[(m0 + r) * CDIM + k0 + c];
        }
        for (int e = t; e < 2048; e += 256) {
            int r = e >> 6, n = e & 63;
            Cs[r][n] = C[(k0 + r) * CDIM + j0 + n];
        }
        __syncthreads();
#pragma unroll
        for (int kk = 0; kk < 32; kk++) {
            float4 a4 = *(float4*)&Ws[kk][ty * 4];
            float4 b4 = *(float4*)&Cs[kk][tx * 4];
            float a[4] = {a4.x, a4.y, a4.z, a4.w};
            float bb[4] = {b4.x, b4.y, b4.z, b4.w};
#pragma unroll
            for (int i = 0; i < 4; i++)
#pragma unroll
                for (int j = 0; j < 4; j++) acc[i][j] = fmaf(a[i], bb[j], acc[i][j]);
        }
    }
    if (mode == 0) {
#pragma unroll
        for (int i = 0; i < 4; i++)
#pragma unroll
            for (int j = 0; j < 4; j++)
                D[(m0 + ty * 4 + i) * CDIM + (j0 + tx * 4 + j)] = acc[i][j];
    } else {
#pragma unroll
        for (int i = 0; i < 4; i++)
#pragma unroll
            for (int j = 0; j < 4; j++)
                Dh[(m0 + ty * 4 + i) * CDIM + (j0 + tx * 4 + j)] = __float2half(acc[i][j]);
    }
}

// -------- per-batch vectors (warp per (b,c)) --------
__global__ void vec_kernel(const float* __restrict__ Wq, const float* __restrict__ Wk,
                           const float* __restrict__ bq, const float* __restrict__ bk) {
    int c = blockIdx.x, b = blockIdx.y, l = threadIdx.x;
    float a0 = 0, a1 = 0, a2 = 0, a3 = 0, d0 = 0, d2 = 0, d3 = 0, d5 = 0;
    for (int i = l; i < CDIM; i += 32) {
        float wq = Wq[c * CDIM + i], wk = Wk[c * CDIM + i];
        a0 = fmaf(wq, g_s[b][0][i], a0);
        a1 = fmaf(wk, g_s[b][1][i], a1);
        a2 = fmaf(wq, g_s[b][2][i], a2);
        a3 = fmaf(wk, g_s[b][3][i], a3);
        d0 = fmaf(g_T[b][0][c][i], wq, d0);
        d2 = fmaf(g_T[b][2][c][i], wk, d2);
        d3 = fmaf(g_T[b][3][c][i], wq, d3);
        d5 = fmaf(g_T[b][5][c][i], wk, d5);
    }
#pragma unroll
    for (int s = 16; s > 0; s >>= 1) {
        a0 += __shfl_xor_sync(0xffffffff, a0, s);
        a1 += __shfl_xor_sync(0xffffffff, a1, s);
        a2 += __shfl_xor_sync(0xffffffff, a2, s);
        a3 += __shfl_xor_sync(0xffffffff, a3, s);
        d0 += __shfl_xor_sync(0xffffffff, d0, s);
        d2 += __shfl_xor_sync(0xffffffff, d2, s);
        d3 += __shfl_xor_sync(0xffffffff, d3, s);
        d5 += __shfl_xor_sync(0xffffffff, d5, s);
    }
    if (l == 0) {
        float bqc = bq[c], bkc = bk[c];
        const float NN = (float)NTOK;
        g_vec[b][0][c] = a0;
        g_vec[b][1][c] = a1;
        g_vec[b][2][c] = a2;
        g_vec[b][3][c] = a3;
        g_vec[b][4][c] = sqrtf(fmaxf(d0 + 2.f * bqc * a0 + NN * bqc * bqc, 0.f));
        g_vec[b][5][c] = sqrtf(fmaxf(d2 + 2.f * bkc * a1 + NN * bkc * bkc, 0.f));
        g_vec[b][6][c] = sqrtf(fmaxf(d3 + 2.f * bqc * a2 + NN * bqc * bqc, 0.f));
        g_vec[b][7][c] = sqrtf(fmaxf(d5 + 2.f * bkc * a3 + NN * bkc * bkc, 0.f));
    }
}

// -------- logits + softmax --------
__global__ void attn_kernel(const float* __restrict__ Wk, const float* __restrict__ bq,
                            const float* __restrict__ bk, const float* __restrict__ scale,
                            const float* __restrict__ bv) {
    int h = blockIdx.x, pair = blockIdx.y, b = blockIdx.z;
    __shared__ float sTA[HD][CDIM];
    __shared__ float sWk[HD][CDIM];
    __shared__ float slog[HD][HD];
    const float* TA = pair ? &g_T[b][4][0][0] : &g_T[b][1][0][0];
    const float* wqs = pair ? g_vec[b][2] : g_vec[b][0];
    const float* wks = pair ? g_vec[b][3] : g_vec[b][1];
    const float* nq = pair ? g_vec[b][6] : g_vec[b][4];
    const float* nk = pair ? g_vec[b][7] : g_vec[b][5];
    int t = threadIdx.x;
    for (int e = t; e < HD * CDIM; e += 256) {
        int r = e / CDIM, cc = e % CDIM;
        sTA[r][cc] = TA[(h * HD + r) * CDIM + cc];
        sWk[r][cc] = Wk[(h * HD + r) * CDIM + cc];
    }
    __syncthreads();
    float sc = scale[h];
    const float NN = (float)NTOK;
    for (int e = t; e < HD * HD; e += 256) {
        int i = e / HD, j = e % HD;
        int c = h * HD + i, d = h * HD + j;
        float dot = 0.f;
        for (int k = 0; k < CDIM; k++) dot = fmaf(sTA[i][k], sWk[j][k], dot);
        float raw = dot + wqs[c] * bk[d] + bq[c] * wks[d] + NN * bq[c] * bk[d];
        slog[i][j] = raw / (fmaxf(nq[c], 1e-12f) * fmaxf(nk[d], 1e-12f)) * sc;
    }
    __syncthreads();
    if (t < HD) {
        int i = t;
        float m = -INFINITY;
        for (int j = 0; j < HD; j++) m = fmaxf(m, slog[i][j]);
        float ex[HD];
        float sum = 0.f;
        for (int j = 0; j < HD; j++) { ex[j] = expf(slog[i][j] - m); sum += ex[j]; }
        float inv = 1.f / sum;
        float tv = 0.f;
        for (int j = 0; j < HD; j++) {
            float a = ex[j] * inv;
            g_attn[b][pair][h][i][j] = a;
            tv = fmaf(a, bv[h * HD + j], tv);
        }
        g_tvec[b][pair][h * HD + i] = tv;
    }
}

__global__ void cvec_kernel(const float* __restrict__ Wproj) {
    int b = blockIdx.x, p = blockIdx.y, c = threadIdx.x;
    __shared__ float tv[CDIM];
    tv[c] = g_tvec[b][p][c];
    __syncthreads();
    float s = 0.f;
    for (int i = 0; i < CDIM; i++) s = fmaf(Wproj[c * CDIM + i], tv[i], s);
    g_cvec[b][p][c] = s;
}

__global__ void p_kernel(const float* __restrict__ Wv) {
    int vt = blockIdx.x, p = blockIdx.y, b = blockIdx.z;
    int v0 = vt * 32;
    __shared__ float sA[NHEADS][HD][HD];
    __shared__ float sWv[CDIM][32];
    int t = threadIdx.x;
    const float* attnflat = &g_attn[b][p][0][0][0];
    for (int e = t; e < NHEADS * HD * HD; e += 256) (&sA[0][0][0])[e] = attnflat[e];
    for (int e = t; e < CDIM * 32; e += 256) {
        int r = e / 32, vc = e % 32;
        sWv[r][vc] = Wv[r * CDIM + v0 + vc];
    }
    __syncthreads();
    for (int e = t; e < CDIM * 32; e += 256) {
        int c = e / 32, vc = e % 32;
        int h = c / HD, i = c % HD;
        float acc = 0.f;
#pragma unroll
        for (int j = 0; j < HD; j++) acc = fmaf(sA[h][i][j], sWv[h * HD + j][vc], acc);
        g_P[b][p][c][v0 + vc] = acc;
    }
}

// out = M @ X + cvec ; fp16 single-term: Mh x Xh.
// M resident in smem, X double-buffered (single plane). grid (NTOK/128, 16), 384 threads.
__global__ __launch_bounds__(384, 1) void out_mma(const float* __restrict__ x1,
                                                  const float* __restrict__ x2,
                                                  float* __restrict__ out) {
    extern __shared__ __align__(16) __half smo[];
    __half* sM = smo;                       // [CDIM * MROW]
    __half* sX = smo + CDIM * MROW;         // stage s at s*XSTAGE
    float* scv = (float*)(smo + CDIM * MROW + 2 * XSTAGE);

    int z = blockIdx.y;
    int b = z >> 1, p = z & 1;
    const float* X = (p ? x1 : x2) + (size_t)b * CDIM * NTOK;
    const __half* Mh = g_Mh[z];
    float* O = out + (size_t)p * BATCH * CDIM * NTOK + (size_t)b * CDIM * NTOK;
    int n0 = blockIdx.x * 128;

    int tid = threadIdx.x, lane = tid & 31, wid = tid >> 5;
    int wm = wid >> 2, wn = wid & 3;

    if (tid < CDIM) scv[tid] = g_cvec[b][p][tid];

    // resident M load, padded stride MROW
    for (int u = tid; u < CDIM * CDIM / 8; u += 384) {
        int row = u / 24, col = (u % 24) * 8;
        *(uint4*)(sM + row * MROW + col) = *(const uint4*)(Mh + row * CDIM + col);
    }
    // X chunk 0 -> stage 0
    for (int u = tid; u < 1024; u += 384) {
        int r = u >> 5, c4 = (u & 31) * 4;
        float4 v = *(const float4*)(X + (size_t)r * NTOK + n0 + c4);
        cvt_store_h1(v, sX + r * OXROW + c4);
    }
    __syncthreads();

    uint32_t sM_a = smem_u32(sM);
    uint32_t sX_a = smem_u32(sX);

    float acc[4][4][4];
#pragma unroll
    for (int i = 0; i < 4; i++)
#pragma unroll
        for (int j = 0; j < 4; j++)
#pragma unroll
            for (int k = 0; k < 4; k++) acc[i][j][k] = 0.f;

    float4 vx[3];
    for (int ch = 0; ch < 6; ch++) {
        int cur = ch & 1, nxt = cur ^ 1;
        bool pf = (ch < 5);
        if (pf) {
            int kb = (ch + 1) * 32;
#pragma unroll
            for (int it = 0; it < 3; it++) {
                int u = tid + it * 384;
                if (u < 1024) {
                    int r = u >> 5, c4 = (u & 31) * 4;
                    vx[it] = *(const float4*)(X + (size_t)(kb + r) * NTOK + n0 + c4);
                }
            }
        }

        uint32_t xb = sX_a + cur * (XSTAGE * 2);
#pragma unroll
        for (int s = 0; s < 2; s++) {
            int kg = ch * 32 + s * 16;
            uint32_t ah[16], bx[8];
            int arow0 = wm * 64 + (lane & 15);
            int acol = kg + ((lane >> 4) << 3);
#pragma unroll
            for (int i = 0; i < 4; i++)
                ldsm_x4(ah + 4 * i, sM_a + (uint32_t)(((arow0 + i * 16) * MROW + acol) * 2));
            int krow = s * 16 + (lane & 7) + (((lane >> 3) & 1) << 3);
            int ncol0 = wn * 32 + ((lane >> 4) << 3);
#pragma unroll
            for (int jb = 0; jb < 2; jb++)
                ldsm_x4_t(bx + 4 * jb, xb + (uint32_t)((krow * OXROW + ncol0 + jb * 16) * 2));
#pragma unroll
            for (int i = 0; i < 4; i++)
#pragma unroll
                for (int jj = 0; jj < 4; jj++)
                    mma16816h(acc[i][jj], ah + 4 * i, bx + (jj >> 1) * 4 + (jj & 1) * 2);
        }

        if (pf) {
            __half* nb = sX + nxt * XSTAGE;
#pragma unroll
            for (int it = 0; it < 3; it++) {
                int u = tid + it * 384;
                if (u < 1024) {
                    int r = u >> 5, c4 = (u & 31) * 4;
                    cvt_store_h1(vx[it], nb + r * OXROW + c4);
                }
            }
        }
        __syncthreads();
    }

    int r0 = wm * 64 + (lane >> 2);
    int nb = n0 + wn * 32 + (lane & 3) * 2;
#pragma unroll
    for (int i = 0; i < 4; i++) {
        int c = r0 + i * 16;
        float b0 = scv[c], b1 = scv[c + 8];
#pragma unroll
        for (int jj = 0; jj < 4; jj++) {
            float2 v0 = {acc[i][jj][0] + b0, acc[i][jj][1] + b0};
            float2 v1 = {acc[i][jj][2] + b1, acc[i][jj][3] + b1};
            *(float2*)(O + (size_t)c * NTOK + nb + jj * 8) = v0;
            *(float2*)(O + (size_t)(c + 8) * NTOK + nb + jj * 8) = v1;
        }
    }
}

extern "C" void kernel_launch(void* const* d_in, const int* in_sizes, int n_in,
                              void* d_out, int out_size) {
    const float* x1 = (const float*)d_in[0];
    const float* x2 = (const float*)d_in[1];
    const float* q1 = (const float*)d_in[2];
    const float* q2 = (const float*)d_in[3];
    const float* Wq = (const float*)d_in[4];
    const float* bq = (const float*)d_in[5];
    const float* Wk = (const float*)d_in[6];
    const float* bk = (const float*)d_in[7];
    const float* Wv = (const float*)d_in[8];
    const float* bv = (const float*)d_in[9];
    const float* scale = (const float*)d_in[10];
    const float* Wproj = (const float*)d_in[11];
    float* out = (float*)d_out;

    static int configured = 0;
    if (!configured) {
        cudaFuncSetAttribute(gram_mma, cudaFuncAttributeMaxDynamicSharedMemorySize, GRAM_SMEM);
        cudaFuncSetAttribute(out_mma, cudaFuncAttributeMaxDynamicSharedMemorySize, OUT_SMEM);
        configured = 1;
    }

    zero_kernel<<<256, 256>>>();
    gram_mma<<<dim3(GSPLITK, 3, BATCH * 2), 384, GRAM_SMEM>>>(q1, q2, x1, x2);
    smallgemm_nn<<<dim3(3, 3, BATCH * 6), 256>>>(Wq, Wk, Wproj, 0);
    vec_kernel<<<dim3(CDIM, BATCH), 32>>>(Wq, Wk, bq, bk);
    attn_kernel<<<dim3(NHEADS, 2, BATCH), 256>>>(Wk, bq, bk, scale, bv);
    cvec_kernel<<<dim3(BATCH, 2), CDIM>>>(Wproj);
    p_kernel<<<dim3(6, 2, BATCH), 256>>>(Wv);
    smallgemm_nn<<<dim3(3, 3, BATCH * 2), 256>>>(Wq, Wk, Wproj, 1);
    out_mma<<<dim3(NTOK / 128, BATCH * 2), 384, OUT_SMEM>>>(x1, x2, out);
}